// round 6
// baseline (speedup 1.0000x reference)
#include <cuda_runtime.h>
#include <cuda_bf16.h>
#include <math.h>
#include <stdint.h>

#define BB   16
#define HH   256
#define LL   4096
#define DIN  100
#define DMID 512
#define DOUTP 100
#define NST  32
#define CH   64
#define NC   64
#define MTOK (BB * LL)

// ---------------- fp32 intermediates ----------------
__device__ float g_u[BB * HH * LL];       // encoder output, (B,H,L)
__device__ float g_E[BB * HH * LL];       // chunk end-states (stageA -> scan)
__device__ float g_hres[BB * HH * LL];    // post-gelu residual, (B,H,L)
__device__ float g_wS[HH * NST * 2];      // w^64 per (h,n)

// ---------------- bf16 hi/lo split planes ----------------
__device__ uint16_t g_xSh[MTOK * 128],  g_xSl[MTOK * 128];     // x padded K 100->128
__device__ uint16_t g_wencSh[HH * 128], g_wencSl[HH * 128];    // enc_w padded
__device__ uint16_t g_w1Sh[DMID * HH],  g_w1Sl[DMID * HH];
__device__ uint16_t g_w2Sh[128 * DMID], g_w2Sl[128 * DMID];    // dec2_w padded rows 100->128
__device__ uint16_t g_uSh[BB * HH * LL], g_uSl[BB * HH * LL];  // split of u (B,H,L)
__device__ uint16_t g_tlnSh[BB * LL * HH], g_tlnSl[BB * LL * HH];
__device__ uint16_t g_zSh[MTOK * DMID], g_zSl[MTOK * DMID];
__device__ uint16_t g_PSh[BB * HH * LL], g_PSl[BB * HH * LL];  // scan output P, split
__device__ uint16_t g_VSh[HH * 64 * 64], g_VSl[HH * 64 * 64];  // [h][s][t]
__device__ uint16_t g_CMSh[HH * 64 * 128], g_CMSl[HH * 64 * 128]; // [h][t][k]

__device__ __forceinline__ float gelu_f(float x) {
    return 0.5f * x * (1.0f + erff(x * 0.70710678118654752f));
}
__device__ __forceinline__ void splitf(float v, uint16_t& h, uint16_t& l) {
    __nv_bfloat16 bh = __float2bfloat16_rn(v);
    float hf = __bfloat162float(bh);
    __nv_bfloat16 bl = __float2bfloat16_rn(v - hf);
    h = *(uint16_t*)&bh; l = *(uint16_t*)&bl;
}
__device__ __forceinline__ void mma16816(float* c, const uint32_t* a, uint32_t b0, uint32_t b1) {
    asm volatile(
        "mma.sync.aligned.m16n8k16.row.col.f32.bf16.bf16.f32 "
        "{%0,%1,%2,%3}, {%4,%5,%6,%7}, {%8,%9}, {%0,%1,%2,%3};"
        : "+f"(c[0]), "+f"(c[1]), "+f"(c[2]), "+f"(c[3])
        : "r"(a[0]), "r"(a[1]), "r"(a[2]), "r"(a[3]), "r"(b0), "r"(b1));
}
__device__ __forceinline__ uint32_t smem_u32(const void* p) {
    uint32_t a;
    asm("{ .reg .u64 t; cvta.to.shared.u64 t, %1; cvt.u32.u64 %0, t; }" : "=r"(a) : "l"(p));
    return a;
}
#define CP16(dst, src) asm volatile("cp.async.cg.shared.global [%0], [%1], 16;" :: "r"(dst), "l"(src))
#define CPCOMMIT() asm volatile("cp.async.commit_group;" ::: "memory")
#define CPWAIT1() asm volatile("cp.async.wait_group 1;" ::: "memory")
#define CPWAIT0() asm volatile("cp.async.wait_group 0;" ::: "memory")

// ---------------- split+pad elementwise kernel ----------------
__global__ void split_pad(const float* __restrict__ src, uint16_t* __restrict__ dh,
                          uint16_t* __restrict__ dl, int M, int K, int Kp, int total)
{
    int i = blockIdx.x * 256 + threadIdx.x;
    if (i >= total) return;
    int r = i / Kp, c = i - r * Kp;
    float v = (r < M && c < K) ? src[(long)r * K + c] : 0.0f;
    uint16_t h, l; splitf(v, h, l);
    dh[i] = h; dl[i] = l;
}

// ============ pre-split tensor-core GEMM: C[M,N] = A[M,K]*B[N,K]^T + bias ============
// tile 128x128, BK=32, double-buffered cp.async. 3-MMA bf16 hi/lo split.
// OM: 0 = fp32 out w/ Nvalid guard (dec2); 1 = split-plane out + gelu (dec1);
//     2 = transposed fp32 + split planes out (encoder -> (B,H,L))
#define SAST 40
#define PLANE_BYTES (128 * SAST * 2)   // 10240
#define BUF_BYTES (4 * PLANE_BYTES)    // 40960
#define GP_SMEM (2 * BUF_BYTES)        // 81920

template <bool GELU, int OM>
__global__ void __launch_bounds__(256)
gemm_ps(const uint16_t* __restrict__ Ah, const uint16_t* __restrict__ Al,
        const uint16_t* __restrict__ Bh, const uint16_t* __restrict__ Bl,
        const float* __restrict__ bias, float* __restrict__ Cf,
        uint16_t* __restrict__ Coh, uint16_t* __restrict__ Col,
        int K, int Nvalid, int ldc)
{
    extern __shared__ char smem[];
    uint32_t sb = smem_u32(smem);
    int tid = threadIdx.x;
    int warp = tid >> 5, lane = tid & 31;
    int warp_m = warp >> 1, warp_n = warp & 1;
    int g = lane >> 2, tg = lane & 3;
    int m0 = blockIdx.y * 128, n0 = blockIdx.x * 128;

    auto load_chunk = [&](int buf, int k0) {
        uint32_t base = sb + (uint32_t)buf * BUF_BYTES;
#pragma unroll
        for (int p = 0; p < 2; p++) {
            int idx = tid + p * 256;
            int row = idx >> 2, seg = idx & 3;
            uint32_t doff = (uint32_t)(row * SAST + seg * 8) * 2;
            long ao = (long)(m0 + row) * K + k0 + seg * 8;
            long bo = (long)(n0 + row) * K + k0 + seg * 8;
            CP16(base + doff, Ah + ao);
            CP16(base + PLANE_BYTES + doff, Al + ao);
            CP16(base + 2 * PLANE_BYTES + doff, Bh + bo);
            CP16(base + 3 * PLANE_BYTES + doff, Bl + bo);
        }
    };

    float acc[2][8][4];
#pragma unroll
    for (int mt = 0; mt < 2; mt++)
#pragma unroll
        for (int nt = 0; nt < 8; nt++)
#pragma unroll
            for (int q = 0; q < 4; q++) acc[mt][nt][q] = 0.0f;

    int nch = K >> 5;
    load_chunk(0, 0);
    CPCOMMIT();
    for (int c = 0; c < nch; c++) {
        if (c + 1 < nch) { load_chunk((c + 1) & 1, (c + 1) << 5); CPCOMMIT(); CPWAIT1(); }
        else CPWAIT0();
        __syncthreads();
        const uint16_t* sAh = (const uint16_t*)smem + (c & 1) * (BUF_BYTES / 2);
        const uint16_t* sAl = sAh + 128 * SAST;
        const uint16_t* sBh = sAl + 128 * SAST;
        const uint16_t* sBl = sBh + 128 * SAST;
#pragma unroll
        for (int ks = 0; ks < 2; ks++) {
            int kb = ks * 16;
            uint32_t ah[2][4], al[2][4];
#pragma unroll
            for (int mt = 0; mt < 2; mt++) {
                int ra = warp_m * 32 + mt * 16;
                ah[mt][0] = *(const uint32_t*)&sAh[(ra + g) * SAST + kb + tg * 2];
                ah[mt][1] = *(const uint32_t*)&sAh[(ra + g + 8) * SAST + kb + tg * 2];
                ah[mt][2] = *(const uint32_t*)&sAh[(ra + g) * SAST + kb + tg * 2 + 8];
                ah[mt][3] = *(const uint32_t*)&sAh[(ra + g + 8) * SAST + kb + tg * 2 + 8];
                al[mt][0] = *(const uint32_t*)&sAl[(ra + g) * SAST + kb + tg * 2];
                al[mt][1] = *(const uint32_t*)&sAl[(ra + g + 8) * SAST + kb + tg * 2];
                al[mt][2] = *(const uint32_t*)&sAl[(ra + g) * SAST + kb + tg * 2 + 8];
                al[mt][3] = *(const uint32_t*)&sAl[(ra + g + 8) * SAST + kb + tg * 2 + 8];
            }
#pragma unroll
            for (int nt = 0; nt < 8; nt++) {
                int nb = warp_n * 64 + nt * 8 + g;
                uint32_t bh0 = *(const uint32_t*)&sBh[nb * SAST + kb + tg * 2];
                uint32_t bh1 = *(const uint32_t*)&sBh[nb * SAST + kb + tg * 2 + 8];
                uint32_t bl0 = *(const uint32_t*)&sBl[nb * SAST + kb + tg * 2];
                uint32_t bl1 = *(const uint32_t*)&sBl[nb * SAST + kb + tg * 2 + 8];
#pragma unroll
                for (int mt = 0; mt < 2; mt++) {
                    mma16816(acc[mt][nt], ah[mt], bh0, bh1);
                    mma16816(acc[mt][nt], ah[mt], bl0, bl1);
                    mma16816(acc[mt][nt], al[mt], bh0, bh1);
                }
            }
        }
        __syncthreads();
    }

    // -------- epilogue via smem stage --------
    float* stage = (float*)smem;
    for (int nh = 0; nh < 2; nh++) {
        if (warp_n == nh) {
#pragma unroll
            for (int mt = 0; mt < 2; mt++) {
#pragma unroll
                for (int nt = 0; nt < 8; nt++) {
                    int nl = nt * 8 + tg * 2;
                    int ng = n0 + nh * 64 + nl;
                    int r0 = warp_m * 32 + mt * 16 + g;
                    float b0v = (OM == 0) ? ((ng < Nvalid) ? bias[ng] : 0.0f) : bias[ng];
                    float b1v = (OM == 0) ? ((ng + 1 < Nvalid) ? bias[ng + 1] : 0.0f) : bias[ng + 1];
                    float v0 = acc[mt][nt][0] + b0v;
                    float v1 = acc[mt][nt][1] + b1v;
                    float v2 = acc[mt][nt][2] + b0v;
                    float v3 = acc[mt][nt][3] + b1v;
                    if (GELU) { v0 = gelu_f(v0); v1 = gelu_f(v1); v2 = gelu_f(v2); v3 = gelu_f(v3); }
                    if (OM == 2) {
                        stage[nl * 132 + r0] = v0;
                        stage[(nl + 1) * 132 + r0] = v1;
                        stage[nl * 132 + r0 + 8] = v2;
                        stage[(nl + 1) * 132 + r0 + 8] = v3;
                    } else {
                        stage[r0 * 68 + nl] = v0;
                        stage[r0 * 68 + nl + 1] = v1;
                        stage[(r0 + 8) * 68 + nl] = v2;
                        stage[(r0 + 8) * 68 + nl + 1] = v3;
                    }
                }
            }
        }
        __syncthreads();
        if (OM == 2) {
            int bidx = m0 >> 12;
            int l0 = m0 & 4095;
#pragma unroll
            for (int p = 0; p < 8; p++) {
                int nl = p * 8 + warp;
                int m4 = lane * 4;
                float4 v = *(float4*)&stage[nl * 132 + m4];
                int ng = n0 + nh * 64 + nl;
                long base = ((long)((bidx << 8) + ng)) * 4096 + l0 + m4;
                *(float4*)&Cf[base] = v;
                uint16_t h0, h1, h2, h3, q0, q1, q2, q3;
                splitf(v.x, h0, q0); splitf(v.y, h1, q1);
                splitf(v.z, h2, q2); splitf(v.w, h3, q3);
                uint64_t ph = (uint64_t)h0 | ((uint64_t)h1 << 16) | ((uint64_t)h2 << 32) | ((uint64_t)h3 << 48);
                uint64_t pq = (uint64_t)q0 | ((uint64_t)q1 << 16) | ((uint64_t)q2 << 32) | ((uint64_t)q3 << 48);
                *(uint64_t*)&Coh[base] = ph;
                *(uint64_t*)&Col[base] = pq;
            }
        } else if (OM == 1) {
#pragma unroll
            for (int p = 0; p < 8; p++) {
                int idx = tid + p * 256;
                int r = idx >> 4;
                int c4 = (idx & 15) * 4;
                int n = n0 + nh * 64 + c4;
                float4 v = *(float4*)&stage[r * 68 + c4];
                long base = (long)(m0 + r) * ldc + n;
                uint16_t h0, h1, h2, h3, q0, q1, q2, q3;
                splitf(v.x, h0, q0); splitf(v.y, h1, q1);
                splitf(v.z, h2, q2); splitf(v.w, h3, q3);
                uint64_t ph = (uint64_t)h0 | ((uint64_t)h1 << 16) | ((uint64_t)h2 << 32) | ((uint64_t)h3 << 48);
                uint64_t pq = (uint64_t)q0 | ((uint64_t)q1 << 16) | ((uint64_t)q2 << 32) | ((uint64_t)q3 << 48);
                *(uint64_t*)&Coh[base] = ph;
                *(uint64_t*)&Col[base] = pq;
            }
        } else {
#pragma unroll
            for (int p = 0; p < 8; p++) {
                int idx = tid + p * 256;
                int r = idx >> 4;
                int c4 = (idx & 15) * 4;
                int n = n0 + nh * 64 + c4;
                if (n < Nvalid) {
                    float4 v = *(float4*)&stage[r * 68 + c4];
                    *(float4*)&Cf[(long)(m0 + r) * ldc + n] = v;
                }
            }
        }
        __syncthreads();
    }
}

// ---------------- precompute per-head matrices (split output) ----------------
__global__ void precompute_kernel(const float* __restrict__ log_dt,
                                  const float* __restrict__ log_A_real,
                                  const float* __restrict__ A_imag,
                                  const float* __restrict__ B_re,
                                  const float* __restrict__ B_im,
                                  const float* __restrict__ C_re,
                                  const float* __restrict__ C_im)
{
    int h = blockIdx.x;
    int t = threadIdx.x;   // 0..63
    __shared__ float s_dtr[NST], s_dti[NST], s_c2r[NST], s_c2i[NST];
    __shared__ float s_k[CH];

    float dt = expf(log_dt[h]);
    if (t < NST) {
        int n = t;
        float Ar = -expf(log_A_real[h * NST + n]);
        float Ai = A_imag[h * NST + n];
        float dtr = dt * Ar, dti = dt * Ai;
        float er = expf(dtr);
        float Er = er * cosf(dti) - 1.0f;
        float Ei = er * sinf(dti);
        float br = B_re[h * NST + n], bi = B_im[h * NST + n];
        float cr = C_re[h * NST + n], ci = C_im[h * NST + n];
        float BCr = br * cr - bi * ci;
        float BCi = br * ci + bi * cr;
        float numr = BCr * Er - BCi * Ei;
        float numi = BCr * Ei + BCi * Er;
        float den = Ar * Ar + Ai * Ai;
        float cpr = (numr * Ar + numi * Ai) / den;
        float cpi = (numi * Ar - numr * Ai) / den;
        s_c2r[n] = 2.0f * cpr;
        s_c2i[n] = 2.0f * cpi;
        s_dtr[n] = dtr;
        s_dti[n] = dti;
        float e64 = expf(64.0f * dtr);
        g_wS[(h * NST + n) * 2 + 0] = e64 * cosf(64.0f * dti);
        g_wS[(h * NST + n) * 2 + 1] = e64 * sinf(64.0f * dti);
    }
    __syncthreads();

    float kt = 0.0f;
    for (int n = 0; n < NST; n++) {
        float dtr = s_dtr[n], dti = s_dti[n];
        float c2r = s_c2r[n], c2i = s_c2i[n];
        // V^T planes: VS[h][s][t] = w_n^{63-t} (re for s=2n, im for s=2n+1)
        float p = (float)(63 - t);
        float ep = expf(p * dtr);
        float vr = ep * cosf(p * dti), vi = ep * sinf(p * dti);
        uint16_t hh, ll;
        splitf(vr, hh, ll);
        g_VSh[h * 4096 + (2 * n) * 64 + t] = hh; g_VSl[h * 4096 + (2 * n) * 64 + t] = ll;
        splitf(vi, hh, ll);
        g_VSh[h * 4096 + (2 * n + 1) * 64 + t] = hh; g_VSl[h * 4096 + (2 * n + 1) * 64 + t] = ll;
        // k[t]
        float pt = (float)t;
        float et = expf(pt * dtr);
        float wr = et * cosf(pt * dti), wi = et * sinf(pt * dti);
        kt += c2r * wr - c2i * wi;
        // G coefficients at CMS[h][t][64+2n], [64+2n+1]
        float p1 = (float)(t + 1);
        float e1 = expf(p1 * dtr);
        float w1r = e1 * cosf(p1 * dti), w1i = e1 * sinf(p1 * dti);
        float gr = c2r * w1r - c2i * w1i;
        float gi = -(c2r * w1i + c2i * w1r);
        splitf(gr, hh, ll);
        g_CMSh[h * 8192 + t * 128 + 64 + 2 * n] = hh; g_CMSl[h * 8192 + t * 128 + 64 + 2 * n] = ll;
        splitf(gi, hh, ll);
        g_CMSh[h * 8192 + t * 128 + 64 + 2 * n + 1] = hh; g_CMSl[h * 8192 + t * 128 + 64 + 2 * n + 1] = ll;
    }
    s_k[t] = kt;
    __syncthreads();
    for (int j = 0; j < CH; j++) {
        float val = (j <= t) ? s_k[t - j] : 0.0f;
        uint16_t hh, ll; splitf(val, hh, ll);
        g_CMSh[h * 8192 + t * 128 + j] = hh;
        g_CMSl[h * 8192 + t * 128 + j] = ll;
    }
}

// ---------------- stage A (mma): E[c][s] = sum_t U[c][t] V^T[s][t] ----------------
__global__ void __launch_bounds__(128) stageA_mma()
{
    __shared__ __align__(16) uint16_t sUh[64 * 72], sUl[64 * 72], sVh[64 * 72], sVl[64 * 72];
    int bh = blockIdx.x, h = bh & (HH - 1);
    int tid = threadIdx.x, warp = tid >> 5, lane = tid & 31;
    int g = lane >> 2, tg = lane & 3;
    const uint16_t* uh = g_uSh + (long)bh * LL;
    const uint16_t* ul = g_uSl + (long)bh * LL;
    const uint16_t* vh = g_VSh + h * 4096;
    const uint16_t* vl = g_VSl + h * 4096;
#pragma unroll
    for (int p = 0; p < 4; p++) {
        int idx = tid + p * 128;
        int row = idx >> 3, seg = idx & 7;
        int so = row * 72 + seg * 8, go = row * 64 + seg * 8;
        *(uint4*)&sUh[so] = *(const uint4*)&uh[go];
        *(uint4*)&sUl[so] = *(const uint4*)&ul[go];
        *(uint4*)&sVh[so] = *(const uint4*)&vh[go];
        *(uint4*)&sVl[so] = *(const uint4*)&vl[go];
    }
    __syncthreads();

    float acc[8][4];
#pragma unroll
    for (int nt = 0; nt < 8; nt++)
#pragma unroll
        for (int q = 0; q < 4; q++) acc[nt][q] = 0.0f;
    int ra = warp * 16;
#pragma unroll
    for (int ks = 0; ks < 4; ks++) {
        int kb = ks * 16;
        uint32_t ah[4], al[4];
        ah[0] = *(const uint32_t*)&sUh[(ra + g) * 72 + kb + tg * 2];
        ah[1] = *(const uint32_t*)&sUh[(ra + g + 8) * 72 + kb + tg * 2];
        ah[2] = *(const uint32_t*)&sUh[(ra + g) * 72 + kb + tg * 2 + 8];
        ah[3] = *(const uint32_t*)&sUh[(ra + g + 8) * 72 + kb + tg * 2 + 8];
        al[0] = *(const uint32_t*)&sUl[(ra + g) * 72 + kb + tg * 2];
        al[1] = *(const uint32_t*)&sUl[(ra + g + 8) * 72 + kb + tg * 2];
        al[2] = *(const uint32_t*)&sUl[(ra + g) * 72 + kb + tg * 2 + 8];
        al[3] = *(const uint32_t*)&sUl[(ra + g + 8) * 72 + kb + tg * 2 + 8];
#pragma unroll
        for (int nt = 0; nt < 8; nt++) {
            int nb = nt * 8 + g;
            uint32_t bh0 = *(const uint32_t*)&sVh[nb * 72 + kb + tg * 2];
            uint32_t bh1 = *(const uint32_t*)&sVh[nb * 72 + kb + tg * 2 + 8];
            uint32_t bl0 = *(const uint32_t*)&sVl[nb * 72 + kb + tg * 2];
            uint32_t bl1 = *(const uint32_t*)&sVl[nb * 72 + kb + tg * 2 + 8];
            mma16816(acc[nt], ah, bh0, bh1);
            mma16816(acc[nt], ah, bl0, bl1);
            mma16816(acc[nt], al, bh0, bh1);
        }
    }
    float* ep = g_E + (long)bh * LL;
#pragma unroll
    for (int nt = 0; nt < 8; nt++) {
        int s = nt * 8 + tg * 2;
        *(float2*)&ep[(ra + g) * 64 + s] = make_float2(acc[nt][0], acc[nt][1]);
        *(float2*)&ep[(ra + g + 8) * 64 + s] = make_float2(acc[nt][2], acc[nt][3]);
    }
}

// ---------------- stage B: cross-chunk scan, writes split P planes ----------------
__global__ void scan_kernel()
{
    int gid = blockIdx.x * blockDim.x + threadIdx.x;
    int bh = gid >> 5;
    int n = gid & 31;
    int h = bh & (HH - 1);
    const float2* E2 = (const float2*)g_E + (long)bh * (LL / 2);
    uint32_t* p32h = (uint32_t*)g_PSh + (long)bh * (LL / 2);
    uint32_t* p32l = (uint32_t*)g_PSl + (long)bh * (LL / 2);
    float wr = g_wS[(h * NST + n) * 2 + 0];
    float wi = g_wS[(h * NST + n) * 2 + 1];
    float sr = 0.0f, si = 0.0f;
    for (int c = 0; c < NC; c++) {
        float2 e = E2[c * 32 + n];
        uint16_t hr, lr, hi2, li2;
        splitf(sr, hr, lr);
        splitf(si, hi2, li2);
        p32h[c * 32 + n] = (uint32_t)hr | ((uint32_t)hi2 << 16);
        p32l[c * 32 + n] = (uint32_t)lr | ((uint32_t)li2 << 16);
        float nsr = wr * sr - wi * si + e.x;
        si = wr * si + wi * sr + e.y;
        sr = nsr;
    }
}

// ---------------- stage C (mma): Y = [u|P] * CM^T, + Dskip*u, gelu, +u ----------------
#define CST 136
#define SC_SMEM (4 * 64 * CST * 2)   // 69632
__global__ void __launch_bounds__(128) stageC_mma(const float* __restrict__ Dskip)
{
    extern __shared__ char smemc[];
    uint16_t* sIh = (uint16_t*)smemc;
    uint16_t* sIl = sIh + 64 * CST;
    uint16_t* sCh = sIl + 64 * CST;
    uint16_t* sCl = sCh + 64 * CST;
    int bh = blockIdx.x, h = bh & (HH - 1);
    int tid = threadIdx.x, warp = tid >> 5, lane = tid & 31;
    int g = lane >> 2, tg = lane & 3;
    const uint16_t* uh = g_uSh + (long)bh * LL;
    const uint16_t* ul = g_uSl + (long)bh * LL;
    const uint16_t* ph = g_PSh + (long)bh * LL;
    const uint16_t* pl = g_PSl + (long)bh * LL;
    const uint16_t* ch = g_CMSh + h * 8192;
    const uint16_t* cl = g_CMSl + h * 8192;
#pragma unroll
    for (int p = 0; p < 8; p++) {
        int idx = tid + p * 128;
        int row = idx >> 4, seg = idx & 15;
        int so = row * CST + seg * 8;
        if (seg < 8) {
            int go = row * 64 + seg * 8;
            *(uint4*)&sIh[so] = *(const uint4*)&uh[go];
            *(uint4*)&sIl[so] = *(const uint4*)&ul[go];
        } else {
            int go = row * 64 + (seg - 8) * 8;
            *(uint4*)&sIh[so] = *(const uint4*)&ph[go];
            *(uint4*)&sIl[so] = *(const uint4*)&pl[go];
        }
        int gc = row * 128 + seg * 8;
        *(uint4*)&sCh[so] = *(const uint4*)&ch[gc];
        *(uint4*)&sCl[so] = *(const uint4*)&cl[gc];
    }
    __syncthreads();

    float acc[8][4];
#pragma unroll
    for (int nt = 0; nt < 8; nt++)
#pragma unroll
        for (int q = 0; q < 4; q++) acc[nt][q] = 0.0f;
    int ra = warp * 16;
#pragma unroll
    for (int ks = 0; ks < 8; ks++) {
        int kb = ks * 16;
        uint32_t ah[4], al[4];
        ah[0] = *(const uint32_t*)&sIh[(ra + g) * CST + kb + tg * 2];
        ah[1] = *(const uint32_t*)&sIh[(ra + g + 8) * CST + kb + tg * 2];
        ah[2] = *(const uint32_t*)&sIh[(ra + g) * CST + kb + tg * 2 + 8];
        ah[3] = *(const uint32_t*)&sIh[(ra + g + 8) * CST + kb + tg * 2 + 8];
        al[0] = *(const uint32_t*)&sIl[(ra + g) * CST + kb + tg * 2];
        al[1] = *(const uint32_t*)&sIl[(ra + g + 8) * CST + kb + tg * 2];
        al[2] = *(const uint32_t*)&sIl[(ra + g) * CST + kb + tg * 2 + 8];
        al[3] = *(const uint32_t*)&sIl[(ra + g + 8) * CST + kb + tg * 2 + 8];
#pragma unroll
        for (int nt = 0; nt < 8; nt++) {
            int nb = nt * 8 + g;
            uint32_t bh0 = *(const uint32_t*)&sCh[nb * CST + kb + tg * 2];
            uint32_t bh1 = *(const uint32_t*)&sCh[nb * CST + kb + tg * 2 + 8];
            uint32_t bl0 = *(const uint32_t*)&sCl[nb * CST + kb + tg * 2];
            uint32_t bl1 = *(const uint32_t*)&sCl[nb * CST + kb + tg * 2 + 8];
            mma16816(acc[nt], ah, bh0, bh1);
            mma16816(acc[nt], ah, bl0, bl1);
            mma16816(acc[nt], al, bh0, bh1);
        }
    }

    float dsk = Dskip[h];
    const float* up = g_u + (long)bh * LL;
    float* hp = g_hres + (long)bh * LL;
#pragma unroll
    for (int nt = 0; nt < 8; nt++) {
        int t = nt * 8 + tg * 2;
        float2 u0 = *(const float2*)&up[(ra + g) * 64 + t];
        float2 u1 = *(const float2*)&up[(ra + g + 8) * 64 + t];
        float y0 = gelu_f(acc[nt][0] + dsk * u0.x) + u0.x;
        float y1 = gelu_f(acc[nt][1] + dsk * u0.y) + u0.y;
        float y2 = gelu_f(acc[nt][2] + dsk * u1.x) + u1.x;
        float y3 = gelu_f(acc[nt][3] + dsk * u1.y) + u1.y;
        *(float2*)&hp[(ra + g) * 64 + t] = make_float2(y0, y1);
        *(float2*)&hp[(ra + g + 8) * 64 + t] = make_float2(y2, y3);
    }
}

// ---------------- layernorm + transpose (B,H,L) -> (B,L,H), split output ----------------
__global__ void __launch_bounds__(256, 1) layernorm_kernel(const float* __restrict__ ln_g,
                                                           const float* __restrict__ ln_b)
{
    int b = blockIdx.y;
    int l0 = blockIdx.x * 32;
    __shared__ float tile[256][33];
    int tid = threadIdx.x;
    int w = tid >> 5, lane = tid & 31;
    const float* hp = g_hres + (long)b * HH * LL;
    for (int hh = w; hh < 256; hh += 8) {
        tile[hh][lane] = hp[(long)hh * LL + l0 + lane];
    }
    __syncthreads();
    uint16_t* oph = g_tlnSh + ((long)b * LL + l0) * HH;
    uint16_t* opl = g_tlnSl + ((long)b * LL + l0) * HH;
#pragma unroll
    for (int q = 0; q < 4; q++) {
        int tok = w * 4 + q;
        float s = 0.0f, sq = 0.0f;
#pragma unroll
        for (int j = 0; j < 8; j++) {
            float v = tile[lane + 32 * j][tok];
            s += v;
            sq += v * v;
        }
#pragma unroll
        for (int o = 16; o > 0; o >>= 1) {
            s += __shfl_xor_sync(0xffffffffu, s, o);
            sq += __shfl_xor_sync(0xffffffffu, sq, o);
        }
        float mean = s * (1.0f / 256.0f);
        float var = sq * (1.0f / 256.0f) - mean * mean;
        float rstd = rsqrtf(var + 1e-5f);
#pragma unroll
        for (int j = 0; j < 8; j++) {
            int hh = lane + 32 * j;
            float v = (tile[hh][tok] - mean) * rstd * ln_g[hh] + ln_b[hh];
            uint16_t vh, vl;
            splitf(v, vh, vl);
            oph[(long)tok * HH + hh] = vh;
            opl[(long)tok * HH + hh] = vl;
        }
    }
}

// ---------------- launcher ----------------
extern "C" void kernel_launch(void* const* d_in, const int* in_sizes, int n_in,
                              void* d_out, int out_size)
{
    const float* x          = (const float*)d_in[0];
    const float* enc_w      = (const float*)d_in[1];
    const float* enc_b      = (const float*)d_in[2];
    const float* log_dt     = (const float*)d_in[3];
    const float* log_A_real = (const float*)d_in[4];
    const float* A_imag     = (const float*)d_in[5];
    const float* B_re       = (const float*)d_in[6];
    const float* B_im       = (const float*)d_in[7];
    const float* C_re       = (const float*)d_in[8];
    const float* C_im       = (const float*)d_in[9];
    const float* Dskip      = (const float*)d_in[10];
    const float* ln_g       = (const float*)d_in[11];
    const float* ln_b       = (const float*)d_in[12];
    const float* dec1_w     = (const float*)d_in[13];
    const float* dec1_b     = (const float*)d_in[14];
    const float* dec2_w     = (const float*)d_in[15];
    const float* dec2_b     = (const float*)d_in[16];
    float* out = (float*)d_out;

    void *pu = 0;
    void *pxh = 0, *pxl = 0, *pweh = 0, *pwel = 0, *pw1h = 0, *pw1l = 0, *pw2h = 0, *pw2l = 0;
    void *puh = 0, *pul = 0, *ptlh = 0, *ptll = 0, *pzh = 0, *pzl = 0;
    cudaGetSymbolAddress(&pu, g_u);
    cudaGetSymbolAddress(&pxh, g_xSh);   cudaGetSymbolAddress(&pxl, g_xSl);
    cudaGetSymbolAddress(&pweh, g_wencSh); cudaGetSymbolAddress(&pwel, g_wencSl);
    cudaGetSymbolAddress(&pw1h, g_w1Sh); cudaGetSymbolAddress(&pw1l, g_w1Sl);
    cudaGetSymbolAddress(&pw2h, g_w2Sh); cudaGetSymbolAddress(&pw2l, g_w2Sl);
    cudaGetSymbolAddress(&puh, g_uSh);   cudaGetSymbolAddress(&pul, g_uSl);
    cudaGetSymbolAddress(&ptlh, g_tlnSh); cudaGetSymbolAddress(&ptll, g_tlnSl);
    cudaGetSymbolAddress(&pzh, g_zSh);   cudaGetSymbolAddress(&pzl, g_zSl);

    cudaFuncSetAttribute(gemm_ps<false, 2>, cudaFuncAttributeMaxDynamicSharedMemorySize, GP_SMEM);
    cudaFuncSetAttribute(gemm_ps<true, 1>,  cudaFuncAttributeMaxDynamicSharedMemorySize, GP_SMEM);
    cudaFuncSetAttribute(gemm_ps<false, 0>, cudaFuncAttributeMaxDynamicSharedMemorySize, GP_SMEM);
    cudaFuncSetAttribute(stageC_mma, cudaFuncAttributeMaxDynamicSharedMemorySize, SC_SMEM);

    // 0. split+pad inputs/weights
    split_pad<<<(MTOK * 128 + 255) / 256, 256>>>(x, (uint16_t*)pxh, (uint16_t*)pxl,
                                                 MTOK, DIN, 128, MTOK * 128);
    split_pad<<<(HH * 128 + 255) / 256, 256>>>(enc_w, (uint16_t*)pweh, (uint16_t*)pwel,
                                               HH, DIN, 128, HH * 128);
    split_pad<<<(DMID * HH + 255) / 256, 256>>>(dec1_w, (uint16_t*)pw1h, (uint16_t*)pw1l,
                                                DMID, HH, HH, DMID * HH);
    split_pad<<<(128 * DMID + 255) / 256, 256>>>(dec2_w, (uint16_t*)pw2h, (uint16_t*)pw2l,
                                                 DOUTP, DMID, DMID, 128 * DMID);

    // 1. per-head S4 matrices (split)
    precompute_kernel<<<HH, 64>>>(log_dt, log_A_real, A_imag, B_re, B_im, C_re, C_im);

    // 2. encoder GEMM -> g_u fp32 (B,H,L) + split planes
    gemm_ps<false, 2><<<dim3(2, 512), 256, GP_SMEM>>>(
        (const uint16_t*)pxh, (const uint16_t*)pxl,
        (const uint16_t*)pweh, (const uint16_t*)pwel,
        enc_b, (float*)pu, (uint16_t*)puh, (uint16_t*)pul,
        128, HH, 0);

    // 3. chunk states (mma)
    stageA_mma<<<BB * HH, 128>>>();

    // 4. cross-chunk scan -> split P planes
    scan_kernel<<<(BB * HH * NST) / 256, 256>>>();

    // 5. output stage (mma) + Dskip + gelu + residual
    stageC_mma<<<BB * HH, 128, SC_SMEM>>>(Dskip);

    // 6. layernorm + transpose -> split planes
    layernorm_kernel<<<dim3(LL / 32, BB), 256>>>(ln_g, ln_b);

    // 7. decoder MLP
    gemm_ps<true, 1><<<dim3(4, 512), 256, GP_SMEM>>>(
        (const uint16_t*)ptlh, (const uint16_t*)ptll,
        (const uint16_t*)pw1h, (const uint16_t*)pw1l,
        dec1_b, nullptr, (uint16_t*)pzh, (uint16_t*)pzl,
        HH, DMID, DMID);

    gemm_ps<false, 0><<<dim3(1, 512), 256, GP_SMEM>>>(
        (const uint16_t*)pzh, (const uint16_t*)pzl,
        (const uint16_t*)pw2h, (const uint16_t*)pw2l,
        dec2_b, out, nullptr, nullptr,
        DMID, DOUTP, DOUTP);
}

// round 7
// speedup vs baseline: 1.0538x; 1.0538x over previous
#include <cuda_runtime.h>
#include <cuda_bf16.h>
#include <math.h>
#include <stdint.h>

#define BB   16
#define HH   256
#define LL   4096
#define DIN  100
#define DMID 512
#define DOUTP 100
#define NST  32
#define CH   64
#define NC   64
#define MTOK (BB * LL)

// ---------------- fp32 intermediates ----------------
__device__ float g_u[BB * HH * LL];       // encoder output, (B,H,L)
__device__ float g_hres[BB * HH * LL];    // post-gelu residual, (B,H,L)
__device__ float g_wS[HH * NST * 2];      // w^64 per (h,n)

// ---------------- bf16 hi/lo split planes ----------------
__device__ uint16_t g_xSh[MTOK * 128],  g_xSl[MTOK * 128];     // x padded K 100->128
__device__ uint16_t g_wencSh[HH * 128], g_wencSl[HH * 128];    // enc_w padded
__device__ uint16_t g_w1Sh[DMID * HH],  g_w1Sl[DMID * HH];
__device__ uint16_t g_w2Sh[128 * DMID], g_w2Sl[128 * DMID];    // dec2_w padded rows 100->128
__device__ uint16_t g_tlnSh[BB * LL * HH], g_tlnSl[BB * LL * HH];
__device__ uint16_t g_zSh[MTOK * DMID], g_zSl[MTOK * DMID];
__device__ uint16_t g_PSh[BB * HH * LL], g_PSl[BB * HH * LL];  // scan output P, split
__device__ uint16_t g_VSh[HH * 64 * 64], g_VSl[HH * 64 * 64];  // [h][s][t]
__device__ uint16_t g_CMSh[HH * 64 * 128], g_CMSl[HH * 64 * 128]; // [h][t][k]

__device__ __forceinline__ float gelu_f(float x) {
    return 0.5f * x * (1.0f + erff(x * 0.70710678118654752f));
}
__device__ __forceinline__ void splitf(float v, uint16_t& h, uint16_t& l) {
    __nv_bfloat16 bh = __float2bfloat16_rn(v);
    float hf = __bfloat162float(bh);
    __nv_bfloat16 bl = __float2bfloat16_rn(v - hf);
    h = *(uint16_t*)&bh; l = *(uint16_t*)&bl;
}
__device__ __forceinline__ void mma16816(float* c, const uint32_t* a, uint32_t b0, uint32_t b1) {
    asm volatile(
        "mma.sync.aligned.m16n8k16.row.col.f32.bf16.bf16.f32 "
        "{%0,%1,%2,%3}, {%4,%5,%6,%7}, {%8,%9}, {%0,%1,%2,%3};"
        : "+f"(c[0]), "+f"(c[1]), "+f"(c[2]), "+f"(c[3])
        : "r"(a[0]), "r"(a[1]), "r"(a[2]), "r"(a[3]), "r"(b0), "r"(b1));
}
__device__ __forceinline__ uint32_t smem_u32(const void* p) {
    uint32_t a;
    asm("{ .reg .u64 t; cvta.to.shared.u64 t, %1; cvt.u32.u64 %0, t; }" : "=r"(a) : "l"(p));
    return a;
}
#define CP16(dst, src) asm volatile("cp.async.cg.shared.global [%0], [%1], 16;" :: "r"(dst), "l"(src))
#define CPCOMMIT() asm volatile("cp.async.commit_group;" ::: "memory")
#define CPWAIT1() asm volatile("cp.async.wait_group 1;" ::: "memory")
#define CPWAIT0() asm volatile("cp.async.wait_group 0;" ::: "memory")

// ---------------- split+pad elementwise kernel ----------------
__global__ void split_pad(const float* __restrict__ src, uint16_t* __restrict__ dh,
                          uint16_t* __restrict__ dl, int M, int K, int Kp, int total)
{
    int i = blockIdx.x * 256 + threadIdx.x;
    if (i >= total) return;
    int r = i / Kp, c = i - r * Kp;
    float v = (r < M && c < K) ? src[(long)r * K + c] : 0.0f;
    uint16_t h, l; splitf(v, h, l);
    dh[i] = h; dl[i] = l;
}

// ============ pre-split tensor-core GEMM: C[M,N] = A[M,K]*B[N,K]^T + bias ============
// tile 128x128, BK=32, double-buffered cp.async. 3-MMA bf16 hi/lo split.
// OM: 0 = fp32 out w/ Nvalid guard (dec2); 1 = split-plane out + gelu (dec1);
//     2 = transposed fp32 out (encoder -> (B,H,L))
#define SAST 40
#define PLANE_BYTES (128 * SAST * 2)   // 10240
#define BUF_BYTES (4 * PLANE_BYTES)    // 40960
#define GP_SMEM (2 * BUF_BYTES)        // 81920

template <bool GELU, int OM>
__global__ void __launch_bounds__(256)
gemm_ps(const uint16_t* __restrict__ Ah, const uint16_t* __restrict__ Al,
        const uint16_t* __restrict__ Bh, const uint16_t* __restrict__ Bl,
        const float* __restrict__ bias, float* __restrict__ Cf,
        uint16_t* __restrict__ Coh, uint16_t* __restrict__ Col,
        int K, int Nvalid, int ldc)
{
    extern __shared__ char smem[];
    uint32_t sb = smem_u32(smem);
    int tid = threadIdx.x;
    int warp = tid >> 5, lane = tid & 31;
    int warp_m = warp >> 1, warp_n = warp & 1;
    int g = lane >> 2, tg = lane & 3;
    int m0 = blockIdx.y * 128, n0 = blockIdx.x * 128;

    auto load_chunk = [&](int buf, int k0) {
        uint32_t base = sb + (uint32_t)buf * BUF_BYTES;
#pragma unroll
        for (int p = 0; p < 2; p++) {
            int idx = tid + p * 256;
            int row = idx >> 2, seg = idx & 3;
            uint32_t doff = (uint32_t)(row * SAST + seg * 8) * 2;
            long ao = (long)(m0 + row) * K + k0 + seg * 8;
            long bo = (long)(n0 + row) * K + k0 + seg * 8;
            CP16(base + doff, Ah + ao);
            CP16(base + PLANE_BYTES + doff, Al + ao);
            CP16(base + 2 * PLANE_BYTES + doff, Bh + bo);
            CP16(base + 3 * PLANE_BYTES + doff, Bl + bo);
        }
    };

    float acc[2][8][4];
#pragma unroll
    for (int mt = 0; mt < 2; mt++)
#pragma unroll
        for (int nt = 0; nt < 8; nt++)
#pragma unroll
            for (int q = 0; q < 4; q++) acc[mt][nt][q] = 0.0f;

    int nch = K >> 5;
    load_chunk(0, 0);
    CPCOMMIT();
    for (int c = 0; c < nch; c++) {
        if (c + 1 < nch) { load_chunk((c + 1) & 1, (c + 1) << 5); CPCOMMIT(); CPWAIT1(); }
        else CPWAIT0();
        __syncthreads();
        const uint16_t* sAh = (const uint16_t*)smem + (c & 1) * (BUF_BYTES / 2);
        const uint16_t* sAl = sAh + 128 * SAST;
        const uint16_t* sBh = sAl + 128 * SAST;
        const uint16_t* sBl = sBh + 128 * SAST;
#pragma unroll
        for (int ks = 0; ks < 2; ks++) {
            int kb = ks * 16;
            uint32_t ah[2][4], al[2][4];
#pragma unroll
            for (int mt = 0; mt < 2; mt++) {
                int ra = warp_m * 32 + mt * 16;
                ah[mt][0] = *(const uint32_t*)&sAh[(ra + g) * SAST + kb + tg * 2];
                ah[mt][1] = *(const uint32_t*)&sAh[(ra + g + 8) * SAST + kb + tg * 2];
                ah[mt][2] = *(const uint32_t*)&sAh[(ra + g) * SAST + kb + tg * 2 + 8];
                ah[mt][3] = *(const uint32_t*)&sAh[(ra + g + 8) * SAST + kb + tg * 2 + 8];
                al[mt][0] = *(const uint32_t*)&sAl[(ra + g) * SAST + kb + tg * 2];
                al[mt][1] = *(const uint32_t*)&sAl[(ra + g + 8) * SAST + kb + tg * 2];
                al[mt][2] = *(const uint32_t*)&sAl[(ra + g) * SAST + kb + tg * 2 + 8];
                al[mt][3] = *(const uint32_t*)&sAl[(ra + g + 8) * SAST + kb + tg * 2 + 8];
            }
#pragma unroll
            for (int nt = 0; nt < 8; nt++) {
                int nb = warp_n * 64 + nt * 8 + g;
                uint32_t bh0 = *(const uint32_t*)&sBh[nb * SAST + kb + tg * 2];
                uint32_t bh1 = *(const uint32_t*)&sBh[nb * SAST + kb + tg * 2 + 8];
                uint32_t bl0 = *(const uint32_t*)&sBl[nb * SAST + kb + tg * 2];
                uint32_t bl1 = *(const uint32_t*)&sBl[nb * SAST + kb + tg * 2 + 8];
#pragma unroll
                for (int mt = 0; mt < 2; mt++) {
                    mma16816(acc[mt][nt], ah[mt], bh0, bh1);
                    mma16816(acc[mt][nt], ah[mt], bl0, bl1);
                    mma16816(acc[mt][nt], al[mt], bh0, bh1);
                }
            }
        }
        __syncthreads();
    }

    // -------- epilogue via smem stage --------
    float* stage = (float*)smem;
    for (int nh = 0; nh < 2; nh++) {
        if (warp_n == nh) {
#pragma unroll
            for (int mt = 0; mt < 2; mt++) {
#pragma unroll
                for (int nt = 0; nt < 8; nt++) {
                    int nl = nt * 8 + tg * 2;
                    int ng = n0 + nh * 64 + nl;
                    int r0 = warp_m * 32 + mt * 16 + g;
                    float b0v = (OM == 0) ? ((ng < Nvalid) ? bias[ng] : 0.0f) : bias[ng];
                    float b1v = (OM == 0) ? ((ng + 1 < Nvalid) ? bias[ng + 1] : 0.0f) : bias[ng + 1];
                    float v0 = acc[mt][nt][0] + b0v;
                    float v1 = acc[mt][nt][1] + b1v;
                    float v2 = acc[mt][nt][2] + b0v;
                    float v3 = acc[mt][nt][3] + b1v;
                    if (GELU) { v0 = gelu_f(v0); v1 = gelu_f(v1); v2 = gelu_f(v2); v3 = gelu_f(v3); }
                    if (OM == 2) {
                        stage[nl * 132 + r0] = v0;
                        stage[(nl + 1) * 132 + r0] = v1;
                        stage[nl * 132 + r0 + 8] = v2;
                        stage[(nl + 1) * 132 + r0 + 8] = v3;
                    } else {
                        stage[r0 * 68 + nl] = v0;
                        stage[r0 * 68 + nl + 1] = v1;
                        stage[(r0 + 8) * 68 + nl] = v2;
                        stage[(r0 + 8) * 68 + nl + 1] = v3;
                    }
                }
            }
        }
        __syncthreads();
        if (OM == 2) {
            int bidx = m0 >> 12;
            int l0 = m0 & 4095;
#pragma unroll
            for (int p = 0; p < 8; p++) {
                int nl = p * 8 + warp;
                int m4 = lane * 4;
                float4 v = *(float4*)&stage[nl * 132 + m4];
                int ng = n0 + nh * 64 + nl;
                long base = ((long)((bidx << 8) + ng)) * 4096 + l0 + m4;
                *(float4*)&Cf[base] = v;
            }
        } else if (OM == 1) {
#pragma unroll
            for (int p = 0; p < 8; p++) {
                int idx = tid + p * 256;
                int r = idx >> 4;
                int c4 = (idx & 15) * 4;
                int n = n0 + nh * 64 + c4;
                float4 v = *(float4*)&stage[r * 68 + c4];
                long base = (long)(m0 + r) * ldc + n;
                uint16_t h0, h1, h2, h3, q0, q1, q2, q3;
                splitf(v.x, h0, q0); splitf(v.y, h1, q1);
                splitf(v.z, h2, q2); splitf(v.w, h3, q3);
                uint64_t ph = (uint64_t)h0 | ((uint64_t)h1 << 16) | ((uint64_t)h2 << 32) | ((uint64_t)h3 << 48);
                uint64_t pq = (uint64_t)q0 | ((uint64_t)q1 << 16) | ((uint64_t)q2 << 32) | ((uint64_t)q3 << 48);
                *(uint64_t*)&Coh[base] = ph;
                *(uint64_t*)&Col[base] = pq;
            }
        } else {
#pragma unroll
            for (int p = 0; p < 8; p++) {
                int idx = tid + p * 256;
                int r = idx >> 4;
                int c4 = (idx & 15) * 4;
                int n = n0 + nh * 64 + c4;
                if (n < Nvalid) {
                    float4 v = *(float4*)&stage[r * 68 + c4];
                    *(float4*)&Cf[(long)(m0 + r) * ldc + n] = v;
                }
            }
        }
        __syncthreads();
    }
}

// ---------------- precompute per-head matrices (split output) ----------------
__global__ void precompute_kernel(const float* __restrict__ log_dt,
                                  const float* __restrict__ log_A_real,
                                  const float* __restrict__ A_imag,
                                  const float* __restrict__ B_re,
                                  const float* __restrict__ B_im,
                                  const float* __restrict__ C_re,
                                  const float* __restrict__ C_im)
{
    int h = blockIdx.x;
    int t = threadIdx.x;   // 0..63
    __shared__ float s_dtr[NST], s_dti[NST], s_c2r[NST], s_c2i[NST];
    __shared__ float s_k[CH];

    float dt = expf(log_dt[h]);
    if (t < NST) {
        int n = t;
        float Ar = -expf(log_A_real[h * NST + n]);
        float Ai = A_imag[h * NST + n];
        float dtr = dt * Ar, dti = dt * Ai;
        float er = expf(dtr);
        float Er = er * cosf(dti) - 1.0f;
        float Ei = er * sinf(dti);
        float br = B_re[h * NST + n], bi = B_im[h * NST + n];
        float cr = C_re[h * NST + n], ci = C_im[h * NST + n];
        float BCr = br * cr - bi * ci;
        float BCi = br * ci + bi * cr;
        float numr = BCr * Er - BCi * Ei;
        float numi = BCr * Ei + BCi * Er;
        float den = Ar * Ar + Ai * Ai;
        float cpr = (numr * Ar + numi * Ai) / den;
        float cpi = (numi * Ar - numr * Ai) / den;
        s_c2r[n] = 2.0f * cpr;
        s_c2i[n] = 2.0f * cpi;
        s_dtr[n] = dtr;
        s_dti[n] = dti;
        float e64 = expf(64.0f * dtr);
        g_wS[(h * NST + n) * 2 + 0] = e64 * cosf(64.0f * dti);
        g_wS[(h * NST + n) * 2 + 1] = e64 * sinf(64.0f * dti);
    }
    __syncthreads();

    float kt = 0.0f;
    for (int n = 0; n < NST; n++) {
        float dtr = s_dtr[n], dti = s_dti[n];
        float c2r = s_c2r[n], c2i = s_c2i[n];
        float p = (float)(63 - t);
        float ep = expf(p * dtr);
        float vr = ep * cosf(p * dti), vi = ep * sinf(p * dti);
        uint16_t hh, ll;
        splitf(vr, hh, ll);
        g_VSh[h * 4096 + (2 * n) * 64 + t] = hh; g_VSl[h * 4096 + (2 * n) * 64 + t] = ll;
        splitf(vi, hh, ll);
        g_VSh[h * 4096 + (2 * n + 1) * 64 + t] = hh; g_VSl[h * 4096 + (2 * n + 1) * 64 + t] = ll;
        float pt = (float)t;
        float et = expf(pt * dtr);
        float wr = et * cosf(pt * dti), wi = et * sinf(pt * dti);
        kt += c2r * wr - c2i * wi;
        float p1 = (float)(t + 1);
        float e1 = expf(p1 * dtr);
        float w1r = e1 * cosf(p1 * dti), w1i = e1 * sinf(p1 * dti);
        float gr = c2r * w1r - c2i * w1i;
        float gi = -(c2r * w1i + c2i * w1r);
        splitf(gr, hh, ll);
        g_CMSh[h * 8192 + t * 128 + 64 + 2 * n] = hh; g_CMSl[h * 8192 + t * 128 + 64 + 2 * n] = ll;
        splitf(gi, hh, ll);
        g_CMSh[h * 8192 + t * 128 + 64 + 2 * n + 1] = hh; g_CMSl[h * 8192 + t * 128 + 64 + 2 * n + 1] = ll;
    }
    s_k[t] = kt;
    __syncthreads();
    for (int j = 0; j < CH; j++) {
        float val = (j <= t) ? s_k[t - j] : 0.0f;
        uint16_t hh, ll; splitf(val, hh, ll);
        g_CMSh[h * 8192 + t * 128 + j] = hh;
        g_CMSl[h * 8192 + t * 128 + j] = ll;
    }
}

// ---------------- stage A + scan fused: E = U V^T (mma), then in-block scan -> P planes ----
#define SA_SMEM (4 * 64 * 72 * 2 + 64 * 66 * 4)   // 36864 + 16896 = 53760
__global__ void __launch_bounds__(128) stageA_scan()
{
    extern __shared__ char sma[];
    uint16_t* sUh = (uint16_t*)sma;
    uint16_t* sUl = sUh + 64 * 72;
    uint16_t* sVh = sUl + 64 * 72;
    uint16_t* sVl = sVh + 64 * 72;
    float* sE = (float*)(sma + 4 * 64 * 72 * 2);
    int bh = blockIdx.x, h = bh & (HH - 1);
    int tid = threadIdx.x, warp = tid >> 5, lane = tid & 31;
    int g = lane >> 2, tg = lane & 3;
    const float* up = g_u + (long)bh * LL;
    const uint16_t* vh = g_VSh + h * 4096;
    const uint16_t* vl = g_VSl + h * 4096;

    // load u fp32, split into smem planes ([row=c][t], stride 72)
#pragma unroll
    for (int p = 0; p < 8; p++) {
        int i = tid + p * 128;
        int e = i * 4, row = e >> 6, col = e & 63;
        float4 v = *(const float4*)(up + e);
        uint16_t h0, l0, h1, l1, h2, l2, h3, l3;
        splitf(v.x, h0, l0); splitf(v.y, h1, l1);
        splitf(v.z, h2, l2); splitf(v.w, h3, l3);
        *(uint2*)&sUh[row * 72 + col] = make_uint2((uint32_t)h0 | ((uint32_t)h1 << 16),
                                                   (uint32_t)h2 | ((uint32_t)h3 << 16));
        *(uint2*)&sUl[row * 72 + col] = make_uint2((uint32_t)l0 | ((uint32_t)l1 << 16),
                                                   (uint32_t)l2 | ((uint32_t)l3 << 16));
    }
#pragma unroll
    for (int p = 0; p < 4; p++) {
        int i = tid + p * 128;
        int row = i >> 3, seg = i & 7;
        *(uint4*)&sVh[row * 72 + seg * 8] = *(const uint4*)&vh[row * 64 + seg * 8];
        *(uint4*)&sVl[row * 72 + seg * 8] = *(const uint4*)&vl[row * 64 + seg * 8];
    }
    __syncthreads();

    float acc[8][4];
#pragma unroll
    for (int nt = 0; nt < 8; nt++)
#pragma unroll
        for (int q = 0; q < 4; q++) acc[nt][q] = 0.0f;
    int ra = warp * 16;
#pragma unroll
    for (int ks = 0; ks < 4; ks++) {
        int kb = ks * 16;
        uint32_t ah[4], al[4];
        ah[0] = *(const uint32_t*)&sUh[(ra + g) * 72 + kb + tg * 2];
        ah[1] = *(const uint32_t*)&sUh[(ra + g + 8) * 72 + kb + tg * 2];
        ah[2] = *(const uint32_t*)&sUh[(ra + g) * 72 + kb + tg * 2 + 8];
        ah[3] = *(const uint32_t*)&sUh[(ra + g + 8) * 72 + kb + tg * 2 + 8];
        al[0] = *(const uint32_t*)&sUl[(ra + g) * 72 + kb + tg * 2];
        al[1] = *(const uint32_t*)&sUl[(ra + g + 8) * 72 + kb + tg * 2];
        al[2] = *(const uint32_t*)&sUl[(ra + g) * 72 + kb + tg * 2 + 8];
        al[3] = *(const uint32_t*)&sUl[(ra + g + 8) * 72 + kb + tg * 2 + 8];
#pragma unroll
        for (int nt = 0; nt < 8; nt++) {
            int nb = nt * 8 + g;
            uint32_t bh0 = *(const uint32_t*)&sVh[nb * 72 + kb + tg * 2];
            uint32_t bh1 = *(const uint32_t*)&sVh[nb * 72 + kb + tg * 2 + 8];
            uint32_t bl0 = *(const uint32_t*)&sVl[nb * 72 + kb + tg * 2];
            uint32_t bl1 = *(const uint32_t*)&sVl[nb * 72 + kb + tg * 2 + 8];
            mma16816(acc[nt], ah, bh0, bh1);
            mma16816(acc[nt], ah, bl0, bl1);
            mma16816(acc[nt], al, bh0, bh1);
        }
    }

    // E -> smem
#pragma unroll
    for (int nt = 0; nt < 8; nt++) {
        int s = nt * 8 + tg * 2;
        sE[(ra + g) * 66 + s] = acc[nt][0];
        sE[(ra + g) * 66 + s + 1] = acc[nt][1];
        sE[(ra + g + 8) * 66 + s] = acc[nt][2];
        sE[(ra + g + 8) * 66 + s + 1] = acc[nt][3];
    }
    __syncthreads();

    // in-block scan over chunks (32 threads; n = complex state index)
    if (tid < 32) {
        int n = tid;
        float wr = g_wS[(h * NST + n) * 2 + 0];
        float wi = g_wS[(h * NST + n) * 2 + 1];
        uint32_t* ph = (uint32_t*)g_PSh + (long)bh * (LL / 2);
        uint32_t* pl = (uint32_t*)g_PSl + (long)bh * (LL / 2);
        float sr = 0.0f, si = 0.0f;
        for (int c = 0; c < NC; c++) {
            uint16_t hr, lr, hi2, li2;
            splitf(sr, hr, lr);
            splitf(si, hi2, li2);
            ph[c * 32 + n] = (uint32_t)hr | ((uint32_t)hi2 << 16);
            pl[c * 32 + n] = (uint32_t)lr | ((uint32_t)li2 << 16);
            float er = sE[c * 66 + 2 * n];
            float ei = sE[c * 66 + 2 * n + 1];
            float nsr = wr * sr - wi * si + er;
            si = wr * si + wi * sr + ei;
            sr = nsr;
        }
    }
}

// ---------------- stage C (mma): Y = [u|P] * CM^T, + Dskip*u, gelu, +u ----------------
#define CST 136
#define SC_SMEM (4 * 64 * CST * 2 + 64 * 68 * 4)   // 69632 + 17408 = 87040
__global__ void __launch_bounds__(128) stageC_mma(const float* __restrict__ Dskip)
{
    extern __shared__ char smemc[];
    uint16_t* sIh = (uint16_t*)smemc;
    uint16_t* sIl = sIh + 64 * CST;
    uint16_t* sCh = sIl + 64 * CST;
    uint16_t* sCl = sCh + 64 * CST;
    float* sUf = (float*)(smemc + 4 * 64 * CST * 2);
    int bh = blockIdx.x, h = bh & (HH - 1);
    int tid = threadIdx.x, warp = tid >> 5, lane = tid & 31;
    int g = lane >> 2, tg = lane & 3;
    const float* up = g_u + (long)bh * LL;
    const uint16_t* ph = g_PSh + (long)bh * LL;
    const uint16_t* pl = g_PSl + (long)bh * LL;
    const uint16_t* ch = g_CMSh + h * 8192;
    const uint16_t* cl = g_CMSl + h * 8192;

    // u fp32 -> sUf + split planes (seg 0..7 of sI)
#pragma unroll
    for (int p = 0; p < 8; p++) {
        int i = tid + p * 128;
        int e = i * 4, row = e >> 6, col = e & 63;
        float4 v = *(const float4*)(up + e);
        *(float4*)&sUf[row * 68 + col] = v;
        uint16_t h0, l0, h1, l1, h2, l2, h3, l3;
        splitf(v.x, h0, l0); splitf(v.y, h1, l1);
        splitf(v.z, h2, l2); splitf(v.w, h3, l3);
        *(uint2*)&sIh[row * CST + col] = make_uint2((uint32_t)h0 | ((uint32_t)h1 << 16),
                                                    (uint32_t)h2 | ((uint32_t)h3 << 16));
        *(uint2*)&sIl[row * CST + col] = make_uint2((uint32_t)l0 | ((uint32_t)l1 << 16),
                                                    (uint32_t)l2 | ((uint32_t)l3 << 16));
    }
    // P planes (seg 8..15 of sI)
#pragma unroll
    for (int p = 0; p < 4; p++) {
        int i = tid + p * 128;
        int row = i >> 3, seg = i & 7;
        *(uint4*)&sIh[row * CST + 64 + seg * 8] = *(const uint4*)&ph[row * 64 + seg * 8];
        *(uint4*)&sIl[row * CST + 64 + seg * 8] = *(const uint4*)&pl[row * 64 + seg * 8];
    }
    // CM planes
#pragma unroll
    for (int p = 0; p < 8; p++) {
        int i = tid + p * 128;
        int row = i >> 4, seg = i & 15;
        *(uint4*)&sCh[row * CST + seg * 8] = *(const uint4*)&ch[row * 128 + seg * 8];
        *(uint4*)&sCl[row * CST + seg * 8] = *(const uint4*)&cl[row * 128 + seg * 8];
    }
    __syncthreads();

    float acc[8][4];
#pragma unroll
    for (int nt = 0; nt < 8; nt++)
#pragma unroll
        for (int q = 0; q < 4; q++) acc[nt][q] = 0.0f;
    int ra = warp * 16;
#pragma unroll
    for (int ks = 0; ks < 8; ks++) {
        int kb = ks * 16;
        uint32_t ah[4], al[4];
        ah[0] = *(const uint32_t*)&sIh[(ra + g) * CST + kb + tg * 2];
        ah[1] = *(const uint32_t*)&sIh[(ra + g + 8) * CST + kb + tg * 2];
        ah[2] = *(const uint32_t*)&sIh[(ra + g) * CST + kb + tg * 2 + 8];
        ah[3] = *(const uint32_t*)&sIh[(ra + g + 8) * CST + kb + tg * 2 + 8];
        al[0] = *(const uint32_t*)&sIl[(ra + g) * CST + kb + tg * 2];
        al[1] = *(const uint32_t*)&sIl[(ra + g + 8) * CST + kb + tg * 2];
        al[2] = *(const uint32_t*)&sIl[(ra + g) * CST + kb + tg * 2 + 8];
        al[3] = *(const uint32_t*)&sIl[(ra + g + 8) * CST + kb + tg * 2 + 8];
#pragma unroll
        for (int nt = 0; nt < 8; nt++) {
            int nb = nt * 8 + g;
            uint32_t bh0 = *(const uint32_t*)&sCh[nb * CST + kb + tg * 2];
            uint32_t bh1 = *(const uint32_t*)&sCh[nb * CST + kb + tg * 2 + 8];
            uint32_t bl0 = *(const uint32_t*)&sCl[nb * CST + kb + tg * 2];
            uint32_t bl1 = *(const uint32_t*)&sCl[nb * CST + kb + tg * 2 + 8];
            mma16816(acc[nt], ah, bh0, bh1);
            mma16816(acc[nt], ah, bl0, bl1);
            mma16816(acc[nt], al, bh0, bh1);
        }
    }

    float dsk = Dskip[h];
    float* hp = g_hres + (long)bh * LL;
#pragma unroll
    for (int nt = 0; nt < 8; nt++) {
        int t = nt * 8 + tg * 2;
        float u00 = sUf[(ra + g) * 68 + t],     u01 = sUf[(ra + g) * 68 + t + 1];
        float u10 = sUf[(ra + g + 8) * 68 + t], u11 = sUf[(ra + g + 8) * 68 + t + 1];
        float y0 = gelu_f(acc[nt][0] + dsk * u00) + u00;
        float y1 = gelu_f(acc[nt][1] + dsk * u01) + u01;
        float y2 = gelu_f(acc[nt][2] + dsk * u10) + u10;
        float y3 = gelu_f(acc[nt][3] + dsk * u11) + u11;
        *(float2*)&hp[(ra + g) * 64 + t] = make_float2(y0, y1);
        *(float2*)&hp[(ra + g + 8) * 64 + t] = make_float2(y2, y3);
    }
}

// ---------------- layernorm + transpose (B,H,L) -> (B,L,H), split output ----------------
__global__ void __launch_bounds__(256, 1) layernorm_kernel(const float* __restrict__ ln_g,
                                                           const float* __restrict__ ln_b)
{
    int b = blockIdx.y;
    int l0 = blockIdx.x * 32;
    __shared__ float tile[256][33];
    int tid = threadIdx.x;
    int w = tid >> 5, lane = tid & 31;
    const float* hp = g_hres + (long)b * HH * LL;
    for (int hh = w; hh < 256; hh += 8) {
        tile[hh][lane] = hp[(long)hh * LL + l0 + lane];
    }
    __syncthreads();
    uint16_t* oph = g_tlnSh + ((long)b * LL + l0) * HH;
    uint16_t* opl = g_tlnSl + ((long)b * LL + l0) * HH;
#pragma unroll
    for (int q = 0; q < 4; q++) {
        int tok = w * 4 + q;
        float s = 0.0f, sq = 0.0f;
#pragma unroll
        for (int j = 0; j < 8; j++) {
            float v = tile[lane + 32 * j][tok];
            s += v;
            sq += v * v;
        }
#pragma unroll
        for (int o = 16; o > 0; o >>= 1) {
            s += __shfl_xor_sync(0xffffffffu, s, o);
            sq += __shfl_xor_sync(0xffffffffu, sq, o);
        }
        float mean = s * (1.0f / 256.0f);
        float var = sq * (1.0f / 256.0f) - mean * mean;
        float rstd = rsqrtf(var + 1e-5f);
#pragma unroll
        for (int j = 0; j < 8; j++) {
            int hh = lane + 32 * j;
            float v = (tile[hh][tok] - mean) * rstd * ln_g[hh] + ln_b[hh];
            uint16_t vh, vl;
            splitf(v, vh, vl);
            oph[(long)tok * HH + hh] = vh;
            opl[(long)tok * HH + hh] = vl;
        }
    }
}

// ---------------- launcher ----------------
extern "C" void kernel_launch(void* const* d_in, const int* in_sizes, int n_in,
                              void* d_out, int out_size)
{
    const float* x          = (const float*)d_in[0];
    const float* enc_w      = (const float*)d_in[1];
    const float* enc_b      = (const float*)d_in[2];
    const float* log_dt     = (const float*)d_in[3];
    const float* log_A_real = (const float*)d_in[4];
    const float* A_imag     = (const float*)d_in[5];
    const float* B_re       = (const float*)d_in[6];
    const float* B_im       = (const float*)d_in[7];
    const float* C_re       = (const float*)d_in[8];
    const float* C_im       = (const float*)d_in[9];
    const float* Dskip      = (const float*)d_in[10];
    const float* ln_g       = (const float*)d_in[11];
    const float* ln_b       = (const float*)d_in[12];
    const float* dec1_w     = (const float*)d_in[13];
    const float* dec1_b     = (const float*)d_in[14];
    const float* dec2_w     = (const float*)d_in[15];
    const float* dec2_b     = (const float*)d_in[16];
    float* out = (float*)d_out;

    void *pu = 0;
    void *pxh = 0, *pxl = 0, *pweh = 0, *pwel = 0, *pw1h = 0, *pw1l = 0, *pw2h = 0, *pw2l = 0;
    void *ptlh = 0, *ptll = 0, *pzh = 0, *pzl = 0;
    cudaGetSymbolAddress(&pu, g_u);
    cudaGetSymbolAddress(&pxh, g_xSh);   cudaGetSymbolAddress(&pxl, g_xSl);
    cudaGetSymbolAddress(&pweh, g_wencSh); cudaGetSymbolAddress(&pwel, g_wencSl);
    cudaGetSymbolAddress(&pw1h, g_w1Sh); cudaGetSymbolAddress(&pw1l, g_w1Sl);
    cudaGetSymbolAddress(&pw2h, g_w2Sh); cudaGetSymbolAddress(&pw2l, g_w2Sl);
    cudaGetSymbolAddress(&ptlh, g_tlnSh); cudaGetSymbolAddress(&ptll, g_tlnSl);
    cudaGetSymbolAddress(&pzh, g_zSh);   cudaGetSymbolAddress(&pzl, g_zSl);

    cudaFuncSetAttribute(gemm_ps<false, 2>, cudaFuncAttributeMaxDynamicSharedMemorySize, GP_SMEM);
    cudaFuncSetAttribute(gemm_ps<true, 1>,  cudaFuncAttributeMaxDynamicSharedMemorySize, GP_SMEM);
    cudaFuncSetAttribute(gemm_ps<false, 0>, cudaFuncAttributeMaxDynamicSharedMemorySize, GP_SMEM);
    cudaFuncSetAttribute(stageA_scan, cudaFuncAttributeMaxDynamicSharedMemorySize, SA_SMEM);
    cudaFuncSetAttribute(stageC_mma,  cudaFuncAttributeMaxDynamicSharedMemorySize, SC_SMEM);

    // #1..#3: splits needed by enc + dec1 weight split (order chosen so enc is launch #4 -> ncu capture)
    split_pad<<<(MTOK * 128 + 255) / 256, 256>>>(x, (uint16_t*)pxh, (uint16_t*)pxl,
                                                 MTOK, DIN, 128, MTOK * 128);
    split_pad<<<(HH * 128 + 255) / 256, 256>>>(enc_w, (uint16_t*)pweh, (uint16_t*)pwel,
                                               HH, DIN, 128, HH * 128);
    split_pad<<<(DMID * HH + 255) / 256, 256>>>(dec1_w, (uint16_t*)pw1h, (uint16_t*)pw1l,
                                                DMID, HH, HH, DMID * HH);

    // #4: encoder GEMM -> g_u fp32 (B,H,L)   [ncu capture target]
    gemm_ps<false, 2><<<dim3(2, 512), 256, GP_SMEM>>>(
        (const uint16_t*)pxh, (const uint16_t*)pxl,
        (const uint16_t*)pweh, (const uint16_t*)pwel,
        enc_b, (float*)pu, nullptr, nullptr,
        128, HH, 0);

    // #5, #6
    precompute_kernel<<<HH, 64>>>(log_dt, log_A_real, A_imag, B_re, B_im, C_re, C_im);
    split_pad<<<(128 * DMID + 255) / 256, 256>>>(dec2_w, (uint16_t*)pw2h, (uint16_t*)pw2l,
                                                 DOUTP, DMID, DMID, 128 * DMID);

    // #7: chunk states + fused cross-chunk scan -> P split planes
    stageA_scan<<<BB * HH, 128, SA_SMEM>>>();

    // #8: output stage (mma) + Dskip + gelu + residual
    stageC_mma<<<BB * HH, 128, SC_SMEM>>>(Dskip);

    // #9: layernorm + transpose -> split planes
    layernorm_kernel<<<dim3(LL / 32, BB), 256>>>(ln_g, ln_b);

    // #10, #11: decoder MLP
    gemm_ps<true, 1><<<dim3(4, 512), 256, GP_SMEM>>>(
        (const uint16_t*)ptlh, (const uint16_t*)ptll,
        (const uint16_t*)pw1h, (const uint16_t*)pw1l,
        dec1_b, nullptr, (uint16_t*)pzh, (uint16_t*)pzl,
        HH, DMID, DMID);

    gemm_ps<false, 0><<<dim3(1, 512), 256, GP_SMEM>>>(
        (const uint16_t*)pzh, (const uint16_t*)pzl,
        (const uint16_t*)pw2h, (const uint16_t*)pw2l,
        dec2_b, out, nullptr, nullptr,
        DMID, DOUTP, DOUTP);
}

// round 8
// speedup vs baseline: 1.2223x; 1.1599x over previous
#include <cuda_runtime.h>
#include <cuda_bf16.h>
#include <math.h>
#include <stdint.h>

#define BB   16
#define HH   256
#define LL   4096
#define DIN  100
#define DMID 512
#define DOUTP 100
#define NST  32
#define CH   64
#define NC   64
#define MTOK (BB * LL)

// ---------------- fp32 intermediates ----------------
__device__ float g_u[BB * HH * LL];       // encoder output, (B,H,L)
__device__ float g_hres[BB * HH * LL];    // post-gelu residual, (B,H,L)
__device__ float g_wS[HH * NST * 2];      // w^64 per (h,n)

// ---------------- bf16 hi/lo split planes ----------------
__device__ uint16_t g_xSh[MTOK * 128],  g_xSl[MTOK * 128];     // x padded K 100->128
__device__ uint16_t g_wencSh[HH * 128], g_wencSl[HH * 128];    // enc_w padded
__device__ uint16_t g_w1Sh[DMID * HH],  g_w1Sl[DMID * HH];
__device__ uint16_t g_w2Sh[128 * DMID], g_w2Sl[128 * DMID];    // dec2_w padded rows 100->128
__device__ uint16_t g_tlnSh[BB * LL * HH], g_tlnSl[BB * LL * HH];
__device__ uint16_t g_zSh[MTOK * DMID], g_zSl[MTOK * DMID];
__device__ uint16_t g_PSh[BB * HH * LL], g_PSl[BB * HH * LL];  // scan output P, split
__device__ uint16_t g_VSh[HH * 64 * 64], g_VSl[HH * 64 * 64];  // [h][s][t]
__device__ uint16_t g_CMSh[HH * 64 * 128], g_CMSl[HH * 64 * 128]; // [h][t][k]

__device__ __forceinline__ float gelu_f(float x) {
    return 0.5f * x * (1.0f + erff(x * 0.70710678118654752f));
}
__device__ __forceinline__ void splitf(float v, uint16_t& h, uint16_t& l) {
    __nv_bfloat16 bh = __float2bfloat16_rn(v);
    float hf = __bfloat162float(bh);
    __nv_bfloat16 bl = __float2bfloat16_rn(v - hf);
    h = *(uint16_t*)&bh; l = *(uint16_t*)&bl;
}
__device__ __forceinline__ void mma16816(float* c, const uint32_t* a, uint32_t b0, uint32_t b1) {
    asm volatile(
        "mma.sync.aligned.m16n8k16.row.col.f32.bf16.bf16.f32 "
        "{%0,%1,%2,%3}, {%4,%5,%6,%7}, {%8,%9}, {%0,%1,%2,%3};"
        : "+f"(c[0]), "+f"(c[1]), "+f"(c[2]), "+f"(c[3])
        : "r"(a[0]), "r"(a[1]), "r"(a[2]), "r"(a[3]), "r"(b0), "r"(b1));
}
__device__ __forceinline__ uint32_t smem_u32(const void* p) {
    uint32_t a;
    asm("{ .reg .u64 t; cvta.to.shared.u64 t, %1; cvt.u32.u64 %0, t; }" : "=r"(a) : "l"(p));
    return a;
}
#define CP16(dst, src) asm volatile("cp.async.cg.shared.global [%0], [%1], 16;" :: "r"(dst), "l"(src))
#define CPCOMMIT() asm volatile("cp.async.commit_group;" ::: "memory")
#define CPWAIT1() asm volatile("cp.async.wait_group 1;" ::: "memory")
#define CPWAIT0() asm volatile("cp.async.wait_group 0;" ::: "memory")

// ---------------- split+pad elementwise kernel ----------------
__global__ void split_pad(const float* __restrict__ src, uint16_t* __restrict__ dh,
                          uint16_t* __restrict__ dl, int M, int K, int Kp, int total)
{
    int i = blockIdx.x * 256 + threadIdx.x;
    if (i >= total) return;
    int r = i / Kp, c = i - r * Kp;
    float v = (r < M && c < K) ? src[(long)r * K + c] : 0.0f;
    uint16_t h, l; splitf(v, h, l);
    dh[i] = h; dl[i] = l;
}

// ============ pre-split tensor-core GEMM: C[M,N] = A[M,K]*B[N,K]^T + bias ============
// tile 128x128, BK=32, double-buffered cp.async. 3-MMA bf16 hi/lo split.
// __launch_bounds__(256,2): cap regs at 128 -> 2 CTAs/SM (occupancy fix)
#define SAST 40
#define PLANE_BYTES (128 * SAST * 2)   // 10240
#define BUF_BYTES (4 * PLANE_BYTES)    // 40960
#define GP_SMEM (2 * BUF_BYTES)        // 81920

template <bool GELU, int OM>
__global__ void __launch_bounds__(256, 2)
gemm_ps(const uint16_t* __restrict__ Ah, const uint16_t* __restrict__ Al,
        const uint16_t* __restrict__ Bh, const uint16_t* __restrict__ Bl,
        const float* __restrict__ bias, float* __restrict__ Cf,
        uint16_t* __restrict__ Coh, uint16_t* __restrict__ Col,
        int K, int Nvalid, int ldc)
{
    extern __shared__ char smem[];
    uint32_t sb = smem_u32(smem);
    int tid = threadIdx.x;
    int warp = tid >> 5, lane = tid & 31;
    int warp_m = warp >> 1, warp_n = warp & 1;
    int g = lane >> 2, tg = lane & 3;
    int m0 = blockIdx.y * 128, n0 = blockIdx.x * 128;

    auto load_chunk = [&](int buf, int k0) {
        uint32_t base = sb + (uint32_t)buf * BUF_BYTES;
#pragma unroll
        for (int p = 0; p < 2; p++) {
            int idx = tid + p * 256;
            int row = idx >> 2, seg = idx & 3;
            uint32_t doff = (uint32_t)(row * SAST + seg * 8) * 2;
            long ao = (long)(m0 + row) * K + k0 + seg * 8;
            long bo = (long)(n0 + row) * K + k0 + seg * 8;
            CP16(base + doff, Ah + ao);
            CP16(base + PLANE_BYTES + doff, Al + ao);
            CP16(base + 2 * PLANE_BYTES + doff, Bh + bo);
            CP16(base + 3 * PLANE_BYTES + doff, Bl + bo);
        }
    };

    float acc[2][8][4];
#pragma unroll
    for (int mt = 0; mt < 2; mt++)
#pragma unroll
        for (int nt = 0; nt < 8; nt++)
#pragma unroll
            for (int q = 0; q < 4; q++) acc[mt][nt][q] = 0.0f;

    int nch = K >> 5;
    load_chunk(0, 0);
    CPCOMMIT();
    for (int c = 0; c < nch; c++) {
        if (c + 1 < nch) { load_chunk((c + 1) & 1, (c + 1) << 5); CPCOMMIT(); CPWAIT1(); }
        else CPWAIT0();
        __syncthreads();
        const uint16_t* sAh = (const uint16_t*)smem + (c & 1) * (BUF_BYTES / 2);
        const uint16_t* sAl = sAh + 128 * SAST;
        const uint16_t* sBh = sAl + 128 * SAST;
        const uint16_t* sBl = sBh + 128 * SAST;
#pragma unroll
        for (int ks = 0; ks < 2; ks++) {
            int kb = ks * 16;
            uint32_t ah[2][4], al[2][4];
#pragma unroll
            for (int mt = 0; mt < 2; mt++) {
                int ra = warp_m * 32 + mt * 16;
                ah[mt][0] = *(const uint32_t*)&sAh[(ra + g) * SAST + kb + tg * 2];
                ah[mt][1] = *(const uint32_t*)&sAh[(ra + g + 8) * SAST + kb + tg * 2];
                ah[mt][2] = *(const uint32_t*)&sAh[(ra + g) * SAST + kb + tg * 2 + 8];
                ah[mt][3] = *(const uint32_t*)&sAh[(ra + g + 8) * SAST + kb + tg * 2 + 8];
                al[mt][0] = *(const uint32_t*)&sAl[(ra + g) * SAST + kb + tg * 2];
                al[mt][1] = *(const uint32_t*)&sAl[(ra + g + 8) * SAST + kb + tg * 2];
                al[mt][2] = *(const uint32_t*)&sAl[(ra + g) * SAST + kb + tg * 2 + 8];
                al[mt][3] = *(const uint32_t*)&sAl[(ra + g + 8) * SAST + kb + tg * 2 + 8];
            }
#pragma unroll
            for (int nt = 0; nt < 8; nt++) {
                int nb = warp_n * 64 + nt * 8 + g;
                uint32_t bh0 = *(const uint32_t*)&sBh[nb * SAST + kb + tg * 2];
                uint32_t bh1 = *(const uint32_t*)&sBh[nb * SAST + kb + tg * 2 + 8];
                uint32_t bl0 = *(const uint32_t*)&sBl[nb * SAST + kb + tg * 2];
                uint32_t bl1 = *(const uint32_t*)&sBl[nb * SAST + kb + tg * 2 + 8];
#pragma unroll
                for (int mt = 0; mt < 2; mt++) {
                    mma16816(acc[mt][nt], ah[mt], bh0, bh1);
                    mma16816(acc[mt][nt], ah[mt], bl0, bl1);
                    mma16816(acc[mt][nt], al[mt], bh0, bh1);
                }
            }
        }
        __syncthreads();
    }

    // -------- epilogue via smem stage --------
    float* stage = (float*)smem;
    for (int nh = 0; nh < 2; nh++) {
        if (warp_n == nh) {
#pragma unroll
            for (int mt = 0; mt < 2; mt++) {
#pragma unroll
                for (int nt = 0; nt < 8; nt++) {
                    int nl = nt * 8 + tg * 2;
                    int ng = n0 + nh * 64 + nl;
                    int r0 = warp_m * 32 + mt * 16 + g;
                    float b0v = (OM == 0) ? ((ng < Nvalid) ? bias[ng] : 0.0f) : bias[ng];
                    float b1v = (OM == 0) ? ((ng + 1 < Nvalid) ? bias[ng + 1] : 0.0f) : bias[ng + 1];
                    float v0 = acc[mt][nt][0] + b0v;
                    float v1 = acc[mt][nt][1] + b1v;
                    float v2 = acc[mt][nt][2] + b0v;
                    float v3 = acc[mt][nt][3] + b1v;
                    if (GELU) { v0 = gelu_f(v0); v1 = gelu_f(v1); v2 = gelu_f(v2); v3 = gelu_f(v3); }
                    if (OM == 2) {
                        stage[nl * 132 + r0] = v0;
                        stage[(nl + 1) * 132 + r0] = v1;
                        stage[nl * 132 + r0 + 8] = v2;
                        stage[(nl + 1) * 132 + r0 + 8] = v3;
                    } else {
                        stage[r0 * 68 + nl] = v0;
                        stage[r0 * 68 + nl + 1] = v1;
                        stage[(r0 + 8) * 68 + nl] = v2;
                        stage[(r0 + 8) * 68 + nl + 1] = v3;
                    }
                }
            }
        }
        __syncthreads();
        if (OM == 2) {
            int bidx = m0 >> 12;
            int l0 = m0 & 4095;
#pragma unroll
            for (int p = 0; p < 8; p++) {
                int nl = p * 8 + warp;
                int m4 = lane * 4;
                float4 v = *(float4*)&stage[nl * 132 + m4];
                int ng = n0 + nh * 64 + nl;
                long base = ((long)((bidx << 8) + ng)) * 4096 + l0 + m4;
                *(float4*)&Cf[base] = v;
            }
        } else if (OM == 1) {
#pragma unroll
            for (int p = 0; p < 8; p++) {
                int idx = tid + p * 256;
                int r = idx >> 4;
                int c4 = (idx & 15) * 4;
                int n = n0 + nh * 64 + c4;
                float4 v = *(float4*)&stage[r * 68 + c4];
                long base = (long)(m0 + r) * ldc + n;
                uint16_t h0, h1, h2, h3, q0, q1, q2, q3;
                splitf(v.x, h0, q0); splitf(v.y, h1, q1);
                splitf(v.z, h2, q2); splitf(v.w, h3, q3);
                uint64_t ph = (uint64_t)h0 | ((uint64_t)h1 << 16) | ((uint64_t)h2 << 32) | ((uint64_t)h3 << 48);
                uint64_t pq = (uint64_t)q0 | ((uint64_t)q1 << 16) | ((uint64_t)q2 << 32) | ((uint64_t)q3 << 48);
                *(uint64_t*)&Coh[base] = ph;
                *(uint64_t*)&Col[base] = pq;
            }
        } else {
#pragma unroll
            for (int p = 0; p < 8; p++) {
                int idx = tid + p * 256;
                int r = idx >> 4;
                int c4 = (idx & 15) * 4;
                int n = n0 + nh * 64 + c4;
                if (n < Nvalid) {
                    float4 v = *(float4*)&stage[r * 68 + c4];
                    *(float4*)&Cf[(long)(m0 + r) * ldc + n] = v;
                }
            }
        }
        __syncthreads();
    }
}

// ---------------- precompute per-head matrices (split output) ----------------
__global__ void precompute_kernel(const float* __restrict__ log_dt,
                                  const float* __restrict__ log_A_real,
                                  const float* __restrict__ A_imag,
                                  const float* __restrict__ B_re,
                                  const float* __restrict__ B_im,
                                  const float* __restrict__ C_re,
                                  const float* __restrict__ C_im)
{
    int h = blockIdx.x;
    int t = threadIdx.x;   // 0..63
    __shared__ float s_dtr[NST], s_dti[NST], s_c2r[NST], s_c2i[NST];
    __shared__ float s_k[CH];

    float dt = expf(log_dt[h]);
    if (t < NST) {
        int n = t;
        float Ar = -expf(log_A_real[h * NST + n]);
        float Ai = A_imag[h * NST + n];
        float dtr = dt * Ar, dti = dt * Ai;
        float er = expf(dtr);
        float Er = er * cosf(dti) - 1.0f;
        float Ei = er * sinf(dti);
        float br = B_re[h * NST + n], bi = B_im[h * NST + n];
        float cr = C_re[h * NST + n], ci = C_im[h * NST + n];
        float BCr = br * cr - bi * ci;
        float BCi = br * ci + bi * cr;
        float numr = BCr * Er - BCi * Ei;
        float numi = BCr * Ei + BCi * Er;
        float den = Ar * Ar + Ai * Ai;
        float cpr = (numr * Ar + numi * Ai) / den;
        float cpi = (numi * Ar - numr * Ai) / den;
        s_c2r[n] = 2.0f * cpr;
        s_c2i[n] = 2.0f * cpi;
        s_dtr[n] = dtr;
        s_dti[n] = dti;
        float e64 = expf(64.0f * dtr);
        g_wS[(h * NST + n) * 2 + 0] = e64 * cosf(64.0f * dti);
        g_wS[(h * NST + n) * 2 + 1] = e64 * sinf(64.0f * dti);
    }
    __syncthreads();

    float kt = 0.0f;
    for (int n = 0; n < NST; n++) {
        float dtr = s_dtr[n], dti = s_dti[n];
        float c2r = s_c2r[n], c2i = s_c2i[n];
        float p = (float)(63 - t);
        float ep = expf(p * dtr);
        float vr = ep * cosf(p * dti), vi = ep * sinf(p * dti);
        uint16_t hh, ll;
        splitf(vr, hh, ll);
        g_VSh[h * 4096 + (2 * n) * 64 + t] = hh; g_VSl[h * 4096 + (2 * n) * 64 + t] = ll;
        splitf(vi, hh, ll);
        g_VSh[h * 4096 + (2 * n + 1) * 64 + t] = hh; g_VSl[h * 4096 + (2 * n + 1) * 64 + t] = ll;
        float pt = (float)t;
        float et = expf(pt * dtr);
        float wr = et * cosf(pt * dti), wi = et * sinf(pt * dti);
        kt += c2r * wr - c2i * wi;
        float p1 = (float)(t + 1);
        float e1 = expf(p1 * dtr);
        float w1r = e1 * cosf(p1 * dti), w1i = e1 * sinf(p1 * dti);
        float gr = c2r * w1r - c2i * w1i;
        float gi = -(c2r * w1i + c2i * w1r);
        splitf(gr, hh, ll);
        g_CMSh[h * 8192 + t * 128 + 64 + 2 * n] = hh; g_CMSl[h * 8192 + t * 128 + 64 + 2 * n] = ll;
        splitf(gi, hh, ll);
        g_CMSh[h * 8192 + t * 128 + 64 + 2 * n + 1] = hh; g_CMSl[h * 8192 + t * 128 + 64 + 2 * n + 1] = ll;
    }
    s_k[t] = kt;
    __syncthreads();
    for (int j = 0; j < CH; j++) {
        float val = (j <= t) ? s_k[t - j] : 0.0f;
        uint16_t hh, ll; splitf(val, hh, ll);
        g_CMSh[h * 8192 + t * 128 + j] = hh;
        g_CMSl[h * 8192 + t * 128 + j] = ll;
    }
}

// ---------------- stage A + scan fused (8 warps): E = U V^T (mma), in-block scan -> P ----
#define SA_SMEM (4 * 64 * 72 * 2 + 64 * 66 * 4)   // 36864 + 16896 = 53760
__global__ void __launch_bounds__(256) stageA_scan()
{
    extern __shared__ char sma[];
    uint16_t* sUh = (uint16_t*)sma;
    uint16_t* sUl = sUh + 64 * 72;
    uint16_t* sVh = sUl + 64 * 72;
    uint16_t* sVl = sVh + 64 * 72;
    float* sE = (float*)(sma + 4 * 64 * 72 * 2);
    int bh = blockIdx.x, h = bh & (HH - 1);
    int tid = threadIdx.x, warp = tid >> 5, lane = tid & 31;
    int warp_m = warp >> 1, warp_n = warp & 1;
    int g = lane >> 2, tg = lane & 3;
    const float* up = g_u + (long)bh * LL;
    const uint16_t* vh = g_VSh + h * 4096;
    const uint16_t* vl = g_VSl + h * 4096;

    // load u fp32, split into smem planes ([row=c][t], stride 72)
#pragma unroll
    for (int p = 0; p < 4; p++) {
        int i = tid + p * 256;
        int e = i * 4, row = e >> 6, col = e & 63;
        float4 v = *(const float4*)(up + e);
        uint16_t h0, l0, h1, l1, h2, l2, h3, l3;
        splitf(v.x, h0, l0); splitf(v.y, h1, l1);
        splitf(v.z, h2, l2); splitf(v.w, h3, l3);
        *(uint2*)&sUh[row * 72 + col] = make_uint2((uint32_t)h0 | ((uint32_t)h1 << 16),
                                                   (uint32_t)h2 | ((uint32_t)h3 << 16));
        *(uint2*)&sUl[row * 72 + col] = make_uint2((uint32_t)l0 | ((uint32_t)l1 << 16),
                                                   (uint32_t)l2 | ((uint32_t)l3 << 16));
    }
#pragma unroll
    for (int p = 0; p < 2; p++) {
        int i = tid + p * 256;
        int row = i >> 3, seg = i & 7;
        *(uint4*)&sVh[row * 72 + seg * 8] = *(const uint4*)&vh[row * 64 + seg * 8];
        *(uint4*)&sVl[row * 72 + seg * 8] = *(const uint4*)&vl[row * 64 + seg * 8];
    }
    __syncthreads();

    float acc[4][4];
#pragma unroll
    for (int nt = 0; nt < 4; nt++)
#pragma unroll
        for (int q = 0; q < 4; q++) acc[nt][q] = 0.0f;
    int ra = warp_m * 16;
#pragma unroll
    for (int ks = 0; ks < 4; ks++) {
        int kb = ks * 16;
        uint32_t ah[4], al[4];
        ah[0] = *(const uint32_t*)&sUh[(ra + g) * 72 + kb + tg * 2];
        ah[1] = *(const uint32_t*)&sUh[(ra + g + 8) * 72 + kb + tg * 2];
        ah[2] = *(const uint32_t*)&sUh[(ra + g) * 72 + kb + tg * 2 + 8];
        ah[3] = *(const uint32_t*)&sUh[(ra + g + 8) * 72 + kb + tg * 2 + 8];
        al[0] = *(const uint32_t*)&sUl[(ra + g) * 72 + kb + tg * 2];
        al[1] = *(const uint32_t*)&sUl[(ra + g + 8) * 72 + kb + tg * 2];
        al[2] = *(const uint32_t*)&sUl[(ra + g) * 72 + kb + tg * 2 + 8];
        al[3] = *(const uint32_t*)&sUl[(ra + g + 8) * 72 + kb + tg * 2 + 8];
#pragma unroll
        for (int nt = 0; nt < 4; nt++) {
            int nb = warp_n * 32 + nt * 8 + g;
            uint32_t bh0 = *(const uint32_t*)&sVh[nb * 72 + kb + tg * 2];
            uint32_t bh1 = *(const uint32_t*)&sVh[nb * 72 + kb + tg * 2 + 8];
            uint32_t bl0 = *(const uint32_t*)&sVl[nb * 72 + kb + tg * 2];
            uint32_t bl1 = *(const uint32_t*)&sVl[nb * 72 + kb + tg * 2 + 8];
            mma16816(acc[nt], ah, bh0, bh1);
            mma16816(acc[nt], ah, bl0, bl1);
            mma16816(acc[nt], al, bh0, bh1);
        }
    }

    // E -> smem
#pragma unroll
    for (int nt = 0; nt < 4; nt++) {
        int s = warp_n * 32 + nt * 8 + tg * 2;
        sE[(ra + g) * 66 + s] = acc[nt][0];
        sE[(ra + g) * 66 + s + 1] = acc[nt][1];
        sE[(ra + g + 8) * 66 + s] = acc[nt][2];
        sE[(ra + g + 8) * 66 + s + 1] = acc[nt][3];
    }
    __syncthreads();

    // in-block scan over chunks (32 threads; n = complex state index)
    if (tid < 32) {
        int n = tid;
        float wr = g_wS[(h * NST + n) * 2 + 0];
        float wi = g_wS[(h * NST + n) * 2 + 1];
        uint32_t* ph = (uint32_t*)g_PSh + (long)bh * (LL / 2);
        uint32_t* pl = (uint32_t*)g_PSl + (long)bh * (LL / 2);
        float sr = 0.0f, si = 0.0f;
        for (int c = 0; c < NC; c++) {
            uint16_t hr, lr, hi2, li2;
            splitf(sr, hr, lr);
            splitf(si, hi2, li2);
            ph[c * 32 + n] = (uint32_t)hr | ((uint32_t)hi2 << 16);
            pl[c * 32 + n] = (uint32_t)lr | ((uint32_t)li2 << 16);
            float er = sE[c * 66 + 2 * n];
            float ei = sE[c * 66 + 2 * n + 1];
            float nsr = wr * sr - wi * si + er;
            si = wr * si + wi * sr + ei;
            sr = nsr;
        }
    }
}

// ---------------- stage C (mma, 8 warps): Y = [u|P] * CM^T, + Dskip*u, gelu, +u ----------------
#define CST 136
#define SC_SMEM (4 * 64 * CST * 2 + 64 * 68 * 4)   // 69632 + 17408 = 87040
__global__ void __launch_bounds__(256) stageC_mma(const float* __restrict__ Dskip)
{
    extern __shared__ char smemc[];
    uint16_t* sIh = (uint16_t*)smemc;
    uint16_t* sIl = sIh + 64 * CST;
    uint16_t* sCh = sIl + 64 * CST;
    uint16_t* sCl = sCh + 64 * CST;
    float* sUf = (float*)(smemc + 4 * 64 * CST * 2);
    int bh = blockIdx.x, h = bh & (HH - 1);
    int tid = threadIdx.x, warp = tid >> 5, lane = tid & 31;
    int warp_m = warp >> 1, warp_n = warp & 1;
    int g = lane >> 2, tg = lane & 3;
    const float* up = g_u + (long)bh * LL;
    const uint16_t* ph = g_PSh + (long)bh * LL;
    const uint16_t* pl = g_PSl + (long)bh * LL;
    const uint16_t* ch = g_CMSh + h * 8192;
    const uint16_t* cl = g_CMSl + h * 8192;

    // u fp32 -> sUf + split planes (cols 0..63 of sI)
#pragma unroll
    for (int p = 0; p < 4; p++) {
        int i = tid + p * 256;
        int e = i * 4, row = e >> 6, col = e & 63;
        float4 v = *(const float4*)(up + e);
        *(float4*)&sUf[row * 68 + col] = v;
        uint16_t h0, l0, h1, l1, h2, l2, h3, l3;
        splitf(v.x, h0, l0); splitf(v.y, h1, l1);
        splitf(v.z, h2, l2); splitf(v.w, h3, l3);
        *(uint2*)&sIh[row * CST + col] = make_uint2((uint32_t)h0 | ((uint32_t)h1 << 16),
                                                    (uint32_t)h2 | ((uint32_t)h3 << 16));
        *(uint2*)&sIl[row * CST + col] = make_uint2((uint32_t)l0 | ((uint32_t)l1 << 16),
                                                    (uint32_t)l2 | ((uint32_t)l3 << 16));
    }
    // P planes (cols 64..127 of sI)
#pragma unroll
    for (int p = 0; p < 2; p++) {
        int i = tid + p * 256;
        int row = i >> 3, seg = i & 7;
        *(uint4*)&sIh[row * CST + 64 + seg * 8] = *(const uint4*)&ph[row * 64 + seg * 8];
        *(uint4*)&sIl[row * CST + 64 + seg * 8] = *(const uint4*)&pl[row * 64 + seg * 8];
    }
    // CM planes
#pragma unroll
    for (int p = 0; p < 4; p++) {
        int i = tid + p * 256;
        int row = i >> 4, seg = i & 15;
        *(uint4*)&sCh[row * CST + seg * 8] = *(const uint4*)&ch[row * 128 + seg * 8];
        *(uint4*)&sCl[row * CST + seg * 8] = *(const uint4*)&cl[row * 128 + seg * 8];
    }
    __syncthreads();

    float acc[4][4];
#pragma unroll
    for (int nt = 0; nt < 4; nt++)
#pragma unroll
        for (int q = 0; q < 4; q++) acc[nt][q] = 0.0f;
    int ra = warp_m * 16;
#pragma unroll
    for (int ks = 0; ks < 8; ks++) {
        int kb = ks * 16;
        uint32_t ah[4], al[4];
        ah[0] = *(const uint32_t*)&sIh[(ra + g) * CST + kb + tg * 2];
        ah[1] = *(const uint32_t*)&sIh[(ra + g + 8) * CST + kb + tg * 2];
        ah[2] = *(const uint32_t*)&sIh[(ra + g) * CST + kb + tg * 2 + 8];
        ah[3] = *(const uint32_t*)&sIh[(ra + g + 8) * CST + kb + tg * 2 + 8];
        al[0] = *(const uint32_t*)&sIl[(ra + g) * CST + kb + tg * 2];
        al[1] = *(const uint32_t*)&sIl[(ra + g + 8) * CST + kb + tg * 2];
        al[2] = *(const uint32_t*)&sIl[(ra + g) * CST + kb + tg * 2 + 8];
        al[3] = *(const uint32_t*)&sIl[(ra + g + 8) * CST + kb + tg * 2 + 8];
#pragma unroll
        for (int nt = 0; nt < 4; nt++) {
            int nb = warp_n * 32 + nt * 8 + g;
            uint32_t bh0 = *(const uint32_t*)&sCh[nb * CST + kb + tg * 2];
            uint32_t bh1 = *(const uint32_t*)&sCh[nb * CST + kb + tg * 2 + 8];
            uint32_t bl0 = *(const uint32_t*)&sCl[nb * CST + kb + tg * 2];
            uint32_t bl1 = *(const uint32_t*)&sCl[nb * CST + kb + tg * 2 + 8];
            mma16816(acc[nt], ah, bh0, bh1);
            mma16816(acc[nt], ah, bl0, bl1);
            mma16816(acc[nt], al, bh0, bh1);
        }
    }

    float dsk = Dskip[h];
    float* hp = g_hres + (long)bh * LL;
#pragma unroll
    for (int nt = 0; nt < 4; nt++) {
        int t = warp_n * 32 + nt * 8 + tg * 2;
        float u00 = sUf[(ra + g) * 68 + t],     u01 = sUf[(ra + g) * 68 + t + 1];
        float u10 = sUf[(ra + g + 8) * 68 + t], u11 = sUf[(ra + g + 8) * 68 + t + 1];
        float y0 = gelu_f(acc[nt][0] + dsk * u00) + u00;
        float y1 = gelu_f(acc[nt][1] + dsk * u01) + u01;
        float y2 = gelu_f(acc[nt][2] + dsk * u10) + u10;
        float y3 = gelu_f(acc[nt][3] + dsk * u11) + u11;
        *(float2*)&hp[(ra + g) * 64 + t] = make_float2(y0, y1);
        *(float2*)&hp[(ra + g + 8) * 64 + t] = make_float2(y2, y3);
    }
}

// ---------------- layernorm + transpose (B,H,L) -> (B,L,H), split output ----------------
__global__ void __launch_bounds__(256, 1) layernorm_kernel(const float* __restrict__ ln_g,
                                                           const float* __restrict__ ln_b)
{
    int b = blockIdx.y;
    int l0 = blockIdx.x * 32;
    __shared__ float tile[256][33];
    int tid = threadIdx.x;
    int w = tid >> 5, lane = tid & 31;
    const float* hp = g_hres + (long)b * HH * LL;
    for (int hh = w; hh < 256; hh += 8) {
        tile[hh][lane] = hp[(long)hh * LL + l0 + lane];
    }
    __syncthreads();
    uint16_t* oph = g_tlnSh + ((long)b * LL + l0) * HH;
    uint16_t* opl = g_tlnSl + ((long)b * LL + l0) * HH;
#pragma unroll
    for (int q = 0; q < 4; q++) {
        int tok = w * 4 + q;
        float s = 0.0f, sq = 0.0f;
#pragma unroll
        for (int j = 0; j < 8; j++) {
            float v = tile[lane + 32 * j][tok];
            s += v;
            sq += v * v;
        }
#pragma unroll
        for (int o = 16; o > 0; o >>= 1) {
            s += __shfl_xor_sync(0xffffffffu, s, o);
            sq += __shfl_xor_sync(0xffffffffu, sq, o);
        }
        float mean = s * (1.0f / 256.0f);
        float var = sq * (1.0f / 256.0f) - mean * mean;
        float rstd = rsqrtf(var + 1e-5f);
#pragma unroll
        for (int j = 0; j < 8; j++) {
            int hh = lane + 32 * j;
            float v = (tile[hh][tok] - mean) * rstd * ln_g[hh] + ln_b[hh];
            uint16_t vh, vl;
            splitf(v, vh, vl);
            oph[(long)tok * HH + hh] = vh;
            opl[(long)tok * HH + hh] = vl;
        }
    }
}

// ---------------- launcher ----------------
extern "C" void kernel_launch(void* const* d_in, const int* in_sizes, int n_in,
                              void* d_out, int out_size)
{
    const float* x          = (const float*)d_in[0];
    const float* enc_w      = (const float*)d_in[1];
    const float* enc_b      = (const float*)d_in[2];
    const float* log_dt     = (const float*)d_in[3];
    const float* log_A_real = (const float*)d_in[4];
    const float* A_imag     = (const float*)d_in[5];
    const float* B_re       = (const float*)d_in[6];
    const float* B_im       = (const float*)d_in[7];
    const float* C_re       = (const float*)d_in[8];
    const float* C_im       = (const float*)d_in[9];
    const float* Dskip      = (const float*)d_in[10];
    const float* ln_g       = (const float*)d_in[11];
    const float* ln_b       = (const float*)d_in[12];
    const float* dec1_w     = (const float*)d_in[13];
    const float* dec1_b     = (const float*)d_in[14];
    const float* dec2_w     = (const float*)d_in[15];
    const float* dec2_b     = (const float*)d_in[16];
    float* out = (float*)d_out;

    void *pu = 0;
    void *pxh = 0, *pxl = 0, *pweh = 0, *pwel = 0, *pw1h = 0, *pw1l = 0, *pw2h = 0, *pw2l = 0;
    void *ptlh = 0, *ptll = 0, *pzh = 0, *pzl = 0;
    cudaGetSymbolAddress(&pu, g_u);
    cudaGetSymbolAddress(&pxh, g_xSh);   cudaGetSymbolAddress(&pxl, g_xSl);
    cudaGetSymbolAddress(&pweh, g_wencSh); cudaGetSymbolAddress(&pwel, g_wencSl);
    cudaGetSymbolAddress(&pw1h, g_w1Sh); cudaGetSymbolAddress(&pw1l, g_w1Sl);
    cudaGetSymbolAddress(&pw2h, g_w2Sh); cudaGetSymbolAddress(&pw2l, g_w2Sl);
    cudaGetSymbolAddress(&ptlh, g_tlnSh); cudaGetSymbolAddress(&ptll, g_tlnSl);
    cudaGetSymbolAddress(&pzh, g_zSh);   cudaGetSymbolAddress(&pzl, g_zSl);

    cudaFuncSetAttribute(gemm_ps<false, 2>, cudaFuncAttributeMaxDynamicSharedMemorySize, GP_SMEM);
    cudaFuncSetAttribute(gemm_ps<true, 1>,  cudaFuncAttributeMaxDynamicSharedMemorySize, GP_SMEM);
    cudaFuncSetAttribute(gemm_ps<false, 0>, cudaFuncAttributeMaxDynamicSharedMemorySize, GP_SMEM);
    cudaFuncSetAttribute(stageA_scan, cudaFuncAttributeMaxDynamicSharedMemorySize, SA_SMEM);
    cudaFuncSetAttribute(stageC_mma,  cudaFuncAttributeMaxDynamicSharedMemorySize, SC_SMEM);

    // #1..#3: splits (order keeps enc at launch #4 -> ncu capture)
    split_pad<<<(MTOK * 128 + 255) / 256, 256>>>(x, (uint16_t*)pxh, (uint16_t*)pxl,
                                                 MTOK, DIN, 128, MTOK * 128);
    split_pad<<<(HH * 128 + 255) / 256, 256>>>(enc_w, (uint16_t*)pweh, (uint16_t*)pwel,
                                               HH, DIN, 128, HH * 128);
    split_pad<<<(DMID * HH + 255) / 256, 256>>>(dec1_w, (uint16_t*)pw1h, (uint16_t*)pw1l,
                                                DMID, HH, HH, DMID * HH);

    // #4: encoder GEMM -> g_u fp32 (B,H,L)   [ncu capture target]
    gemm_ps<false, 2><<<dim3(2, 512), 256, GP_SMEM>>>(
        (const uint16_t*)pxh, (const uint16_t*)pxl,
        (const uint16_t*)pweh, (const uint16_t*)pwel,
        enc_b, (float*)pu, nullptr, nullptr,
        128, HH, 0);

    // #5, #6
    precompute_kernel<<<HH, 64>>>(log_dt, log_A_real, A_imag, B_re, B_im, C_re, C_im);
    split_pad<<<(128 * DMID + 255) / 256, 256>>>(dec2_w, (uint16_t*)pw2h, (uint16_t*)pw2l,
                                                 DOUTP, DMID, DMID, 128 * DMID);

    // #7: chunk states + fused cross-chunk scan -> P split planes
    stageA_scan<<<BB * HH, 256, SA_SMEM>>>();

    // #8: output stage (mma) + Dskip + gelu + residual
    stageC_mma<<<BB * HH, 256, SC_SMEM>>>(Dskip);

    // #9: layernorm + transpose -> split planes
    layernorm_kernel<<<dim3(LL / 32, BB), 256>>>(ln_g, ln_b);

    // #10, #11: decoder MLP
    gemm_ps<true, 1><<<dim3(4, 512), 256, GP_SMEM>>>(
        (const uint16_t*)ptlh, (const uint16_t*)ptll,
        (const uint16_t*)pw1h, (const uint16_t*)pw1l,
        dec1_b, nullptr, (uint16_t*)pzh, (uint16_t*)pzl,
        HH, DMID, DMID);

    gemm_ps<false, 0><<<dim3(1, 512), 256, GP_SMEM>>>(
        (const uint16_t*)pzh, (const uint16_t*)pzl,
        (const uint16_t*)pw2h, (const uint16_t*)pw2l,
        dec2_b, out, nullptr, nullptr,
        DMID, DOUTP, DOUTP);
}

// round 9
// speedup vs baseline: 1.2340x; 1.0095x over previous
#include <cuda_runtime.h>
#include <cuda_bf16.h>
#include <math.h>
#include <stdint.h>

#define BB   16
#define HH   256
#define LL   4096
#define DIN  100
#define DMID 512
#define DOUTP 100
#define NST  32
#define CH   64
#define NC   64
#define MTOK (BB * LL)

// ---------------- fp32 intermediates ----------------
__device__ float g_u[BB * HH * LL];       // encoder output, (B,H,L)
__device__ float g_hres[BB * HH * LL];    // post-gelu residual, (B,H,L)
__device__ float g_wS[HH * NST * 2];      // w^64 per (h,n)

// ---------------- bf16 hi/lo split planes ----------------
__device__ uint16_t g_xSh[MTOK * 128],  g_xSl[MTOK * 128];     // x padded K 100->128
__device__ uint16_t g_wencSh[HH * 128], g_wencSl[HH * 128];    // enc_w padded
__device__ uint16_t g_w1Sh[DMID * HH],  g_w1Sl[DMID * HH];
__device__ uint16_t g_w2Sh[128 * DMID], g_w2Sl[128 * DMID];    // dec2_w padded rows 100->128
__device__ uint16_t g_tlnSh[BB * LL * HH], g_tlnSl[BB * LL * HH];
__device__ uint16_t g_zSh[MTOK * DMID], g_zSl[MTOK * DMID];
__device__ uint16_t g_PSh[BB * HH * LL], g_PSl[BB * HH * LL];  // scan output P, split
__device__ uint16_t g_VSh[HH * 64 * 64], g_VSl[HH * 64 * 64];  // [h][s][t]
__device__ uint16_t g_CMSh[HH * 64 * 128], g_CMSl[HH * 64 * 128]; // [h][t][k]

__device__ __forceinline__ float gelu_f(float x) {
    return 0.5f * x * (1.0f + erff(x * 0.70710678118654752f));
}
__device__ __forceinline__ void splitf(float v, uint16_t& h, uint16_t& l) {
    __nv_bfloat16 bh = __float2bfloat16_rn(v);
    float hf = __bfloat162float(bh);
    __nv_bfloat16 bl = __float2bfloat16_rn(v - hf);
    h = *(uint16_t*)&bh; l = *(uint16_t*)&bl;
}
__device__ __forceinline__ void mma16816(float* c, const uint32_t* a, uint32_t b0, uint32_t b1) {
    asm volatile(
        "mma.sync.aligned.m16n8k16.row.col.f32.bf16.bf16.f32 "
        "{%0,%1,%2,%3}, {%4,%5,%6,%7}, {%8,%9}, {%0,%1,%2,%3};"
        : "+f"(c[0]), "+f"(c[1]), "+f"(c[2]), "+f"(c[3])
        : "r"(a[0]), "r"(a[1]), "r"(a[2]), "r"(a[3]), "r"(b0), "r"(b1));
}
__device__ __forceinline__ void ldsm_x4(uint32_t* r, uint32_t addr) {
    asm volatile("ldmatrix.sync.aligned.m8n8.x4.shared.b16 {%0,%1,%2,%3}, [%4];"
        : "=r"(r[0]), "=r"(r[1]), "=r"(r[2]), "=r"(r[3]) : "r"(addr));
}
__device__ __forceinline__ uint32_t smem_u32(const void* p) {
    uint32_t a;
    asm("{ .reg .u64 t; cvta.to.shared.u64 t, %1; cvt.u32.u64 %0, t; }" : "=r"(a) : "l"(p));
    return a;
}
#define CP16(dst, src) asm volatile("cp.async.cg.shared.global [%0], [%1], 16;" :: "r"(dst), "l"(src))
#define CPCOMMIT() asm volatile("cp.async.commit_group;" ::: "memory")
#define CPWAIT1() asm volatile("cp.async.wait_group 1;" ::: "memory")
#define CPWAIT0() asm volatile("cp.async.wait_group 0;" ::: "memory")

// ---------------- split+pad elementwise kernel ----------------
__global__ void split_pad(const float* __restrict__ src, uint16_t* __restrict__ dh,
                          uint16_t* __restrict__ dl, int M, int K, int Kp, int total)
{
    int i = blockIdx.x * 256 + threadIdx.x;
    if (i >= total) return;
    int r = i / Kp, c = i - r * Kp;
    float v = (r < M && c < K) ? src[(long)r * K + c] : 0.0f;
    uint16_t h, l; splitf(v, h, l);
    dh[i] = h; dl[i] = l;
}

// ============ pre-split tensor-core GEMM: C[M,N] = A[M,K]*B[N,K]^T + bias ============
// tile 128x128, BK=32, double-buffered cp.async, LDSM fragment loads.
#define SAST 40
#define PLANE_BYTES (128 * SAST * 2)   // 10240
#define BUF_BYTES (4 * PLANE_BYTES)    // 40960
#define GP_SMEM (2 * BUF_BYTES)        // 81920

template <bool GELU, int OM>
__global__ void __launch_bounds__(256, 2)
gemm_ps(const uint16_t* __restrict__ Ah, const uint16_t* __restrict__ Al,
        const uint16_t* __restrict__ Bh, const uint16_t* __restrict__ Bl,
        const float* __restrict__ bias, float* __restrict__ Cf,
        uint16_t* __restrict__ Coh, uint16_t* __restrict__ Col,
        int K, int Nvalid, int ldc)
{
    extern __shared__ char smem[];
    uint32_t sb = smem_u32(smem);
    int tid = threadIdx.x;
    int warp = tid >> 5, lane = tid & 31;
    int warp_m = warp >> 1, warp_n = warp & 1;
    int g = lane >> 2, tg = lane & 3;
    int m0 = blockIdx.y * 128, n0 = blockIdx.x * 128;

    // per-lane LDSM offsets (bytes, relative to plane base)
    uint32_t a_row = (uint32_t)(lane & 15) * (SAST * 2) + ((lane & 16) ? 16u : 0u);
    uint32_t b_row = ((uint32_t)(lane & 7) + ((lane & 16) ? 8u : 0u)) * (SAST * 2)
                   + ((lane & 8) ? 16u : 0u);

    auto load_chunk = [&](int buf, int k0) {
        uint32_t base = sb + (uint32_t)buf * BUF_BYTES;
#pragma unroll
        for (int p = 0; p < 2; p++) {
            int idx = tid + p * 256;
            int row = idx >> 2, seg = idx & 3;
            uint32_t doff = (uint32_t)(row * SAST + seg * 8) * 2;
            long ao = (long)(m0 + row) * K + k0 + seg * 8;
            long bo = (long)(n0 + row) * K + k0 + seg * 8;
            CP16(base + doff, Ah + ao);
            CP16(base + PLANE_BYTES + doff, Al + ao);
            CP16(base + 2 * PLANE_BYTES + doff, Bh + bo);
            CP16(base + 3 * PLANE_BYTES + doff, Bl + bo);
        }
    };

    float acc[2][8][4];
#pragma unroll
    for (int mt = 0; mt < 2; mt++)
#pragma unroll
        for (int nt = 0; nt < 8; nt++)
#pragma unroll
            for (int q = 0; q < 4; q++) acc[mt][nt][q] = 0.0f;

    int nch = K >> 5;
    load_chunk(0, 0);
    CPCOMMIT();
    for (int c = 0; c < nch; c++) {
        if (c + 1 < nch) { load_chunk((c + 1) & 1, (c + 1) << 5); CPCOMMIT(); CPWAIT1(); }
        else CPWAIT0();
        __syncthreads();
        uint32_t bufb = sb + (uint32_t)(c & 1) * BUF_BYTES;
        uint32_t pAh = bufb, pAl = bufb + PLANE_BYTES;
        uint32_t pBh = bufb + 2 * PLANE_BYTES, pBl = bufb + 3 * PLANE_BYTES;
#pragma unroll
        for (int ks = 0; ks < 2; ks++) {
            uint32_t kboff = (uint32_t)(ks * 16) * 2;
            uint32_t ah[2][4], al[2][4];
#pragma unroll
            for (int mt = 0; mt < 2; mt++) {
                uint32_t ro = (uint32_t)(warp_m * 32 + mt * 16) * (SAST * 2) + a_row + kboff;
                ldsm_x4(ah[mt], pAh + ro);
                ldsm_x4(al[mt], pAl + ro);
            }
#pragma unroll
            for (int ntp = 0; ntp < 4; ntp++) {
                uint32_t nb = (uint32_t)(warp_n * 64 + ntp * 16) * (SAST * 2) + b_row + kboff;
                uint32_t bhp[4], blp[4];
                ldsm_x4(bhp, pBh + nb);
                ldsm_x4(blp, pBl + nb);
#pragma unroll
                for (int sub = 0; sub < 2; sub++) {
                    int nt = ntp * 2 + sub;
                    uint32_t bh0 = bhp[sub * 2], bh1 = bhp[sub * 2 + 1];
                    uint32_t bl0 = blp[sub * 2], bl1 = blp[sub * 2 + 1];
#pragma unroll
                    for (int mt = 0; mt < 2; mt++) {
                        mma16816(acc[mt][nt], ah[mt], bh0, bh1);
                        mma16816(acc[mt][nt], ah[mt], bl0, bl1);
                        mma16816(acc[mt][nt], al[mt], bh0, bh1);
                    }
                }
            }
        }
        __syncthreads();
    }

    // -------- epilogue via smem stage --------
    float* stage = (float*)smem;
    for (int nh = 0; nh < 2; nh++) {
        if (warp_n == nh) {
#pragma unroll
            for (int mt = 0; mt < 2; mt++) {
#pragma unroll
                for (int nt = 0; nt < 8; nt++) {
                    int nl = nt * 8 + tg * 2;
                    int ng = n0 + nh * 64 + nl;
                    int r0 = warp_m * 32 + mt * 16 + g;
                    float b0v = (OM == 0) ? ((ng < Nvalid) ? bias[ng] : 0.0f) : bias[ng];
                    float b1v = (OM == 0) ? ((ng + 1 < Nvalid) ? bias[ng + 1] : 0.0f) : bias[ng + 1];
                    float v0 = acc[mt][nt][0] + b0v;
                    float v1 = acc[mt][nt][1] + b1v;
                    float v2 = acc[mt][nt][2] + b0v;
                    float v3 = acc[mt][nt][3] + b1v;
                    if (GELU) { v0 = gelu_f(v0); v1 = gelu_f(v1); v2 = gelu_f(v2); v3 = gelu_f(v3); }
                    if (OM == 2) {
                        stage[nl * 132 + r0] = v0;
                        stage[(nl + 1) * 132 + r0] = v1;
                        stage[nl * 132 + r0 + 8] = v2;
                        stage[(nl + 1) * 132 + r0 + 8] = v3;
                    } else {
                        stage[r0 * 68 + nl] = v0;
                        stage[r0 * 68 + nl + 1] = v1;
                        stage[(r0 + 8) * 68 + nl] = v2;
                        stage[(r0 + 8) * 68 + nl + 1] = v3;
                    }
                }
            }
        }
        __syncthreads();
        if (OM == 2) {
            int bidx = m0 >> 12;
            int l0 = m0 & 4095;
#pragma unroll
            for (int p = 0; p < 8; p++) {
                int nl = p * 8 + warp;
                int m4 = lane * 4;
                float4 v = *(float4*)&stage[nl * 132 + m4];
                int ng = n0 + nh * 64 + nl;
                long base = ((long)((bidx << 8) + ng)) * 4096 + l0 + m4;
                *(float4*)&Cf[base] = v;
            }
        } else if (OM == 1) {
#pragma unroll
            for (int p = 0; p < 8; p++) {
                int idx = tid + p * 256;
                int r = idx >> 4;
                int c4 = (idx & 15) * 4;
                int n = n0 + nh * 64 + c4;
                float4 v = *(float4*)&stage[r * 68 + c4];
                long base = (long)(m0 + r) * ldc + n;
                uint16_t h0, h1, h2, h3, q0, q1, q2, q3;
                splitf(v.x, h0, q0); splitf(v.y, h1, q1);
                splitf(v.z, h2, q2); splitf(v.w, h3, q3);
                uint64_t ph = (uint64_t)h0 | ((uint64_t)h1 << 16) | ((uint64_t)h2 << 32) | ((uint64_t)h3 << 48);
                uint64_t pq = (uint64_t)q0 | ((uint64_t)q1 << 16) | ((uint64_t)q2 << 32) | ((uint64_t)q3 << 48);
                *(uint64_t*)&Coh[base] = ph;
                *(uint64_t*)&Col[base] = pq;
            }
        } else {
#pragma unroll
            for (int p = 0; p < 8; p++) {
                int idx = tid + p * 256;
                int r = idx >> 4;
                int c4 = (idx & 15) * 4;
                int n = n0 + nh * 64 + c4;
                if (n < Nvalid) {
                    float4 v = *(float4*)&stage[r * 68 + c4];
                    *(float4*)&Cf[(long)(m0 + r) * ldc + n] = v;
                }
            }
        }
        __syncthreads();
    }
}

// ---------------- precompute per-head matrices (split output) ----------------
__global__ void precompute_kernel(const float* __restrict__ log_dt,
                                  const float* __restrict__ log_A_real,
                                  const float* __restrict__ A_imag,
                                  const float* __restrict__ B_re,
                                  const float* __restrict__ B_im,
                                  const float* __restrict__ C_re,
                                  const float* __restrict__ C_im)
{
    int h = blockIdx.x;
    int t = threadIdx.x;   // 0..63
    __shared__ float s_dtr[NST], s_dti[NST], s_c2r[NST], s_c2i[NST];
    __shared__ float s_k[CH];

    float dt = expf(log_dt[h]);
    if (t < NST) {
        int n = t;
        float Ar = -expf(log_A_real[h * NST + n]);
        float Ai = A_imag[h * NST + n];
        float dtr = dt * Ar, dti = dt * Ai;
        float er = expf(dtr);
        float Er = er * cosf(dti) - 1.0f;
        float Ei = er * sinf(dti);
        float br = B_re[h * NST + n], bi = B_im[h * NST + n];
        float cr = C_re[h * NST + n], ci = C_im[h * NST + n];
        float BCr = br * cr - bi * ci;
        float BCi = br * ci + bi * cr;
        float numr = BCr * Er - BCi * Ei;
        float numi = BCr * Ei + BCi * Er;
        float den = Ar * Ar + Ai * Ai;
        float cpr = (numr * Ar + numi * Ai) / den;
        float cpi = (numi * Ar - numr * Ai) / den;
        s_c2r[n] = 2.0f * cpr;
        s_c2i[n] = 2.0f * cpi;
        s_dtr[n] = dtr;
        s_dti[n] = dti;
        float e64 = expf(64.0f * dtr);
        g_wS[(h * NST + n) * 2 + 0] = e64 * cosf(64.0f * dti);
        g_wS[(h * NST + n) * 2 + 1] = e64 * sinf(64.0f * dti);
    }
    __syncthreads();

    float kt = 0.0f;
    for (int n = 0; n < NST; n++) {
        float dtr = s_dtr[n], dti = s_dti[n];
        float c2r = s_c2r[n], c2i = s_c2i[n];
        float p = (float)(63 - t);
        float ep = expf(p * dtr);
        float vr = ep * cosf(p * dti), vi = ep * sinf(p * dti);
        uint16_t hh, ll;
        splitf(vr, hh, ll);
        g_VSh[h * 4096 + (2 * n) * 64 + t] = hh; g_VSl[h * 4096 + (2 * n) * 64 + t] = ll;
        splitf(vi, hh, ll);
        g_VSh[h * 4096 + (2 * n + 1) * 64 + t] = hh; g_VSl[h * 4096 + (2 * n + 1) * 64 + t] = ll;
        float pt = (float)t;
        float et = expf(pt * dtr);
        float wr = et * cosf(pt * dti), wi = et * sinf(pt * dti);
        kt += c2r * wr - c2i * wi;
        float p1 = (float)(t + 1);
        float e1 = expf(p1 * dtr);
        float w1r = e1 * cosf(p1 * dti), w1i = e1 * sinf(p1 * dti);
        float gr = c2r * w1r - c2i * w1i;
        float gi = -(c2r * w1i + c2i * w1r);
        splitf(gr, hh, ll);
        g_CMSh[h * 8192 + t * 128 + 64 + 2 * n] = hh; g_CMSl[h * 8192 + t * 128 + 64 + 2 * n] = ll;
        splitf(gi, hh, ll);
        g_CMSh[h * 8192 + t * 128 + 64 + 2 * n + 1] = hh; g_CMSl[h * 8192 + t * 128 + 64 + 2 * n + 1] = ll;
    }
    s_k[t] = kt;
    __syncthreads();
    for (int j = 0; j < CH; j++) {
        float val = (j <= t) ? s_k[t - j] : 0.0f;
        uint16_t hh, ll; splitf(val, hh, ll);
        g_CMSh[h * 8192 + t * 128 + j] = hh;
        g_CMSl[h * 8192 + t * 128 + j] = ll;
    }
}

// ---------------- stage A + scan fused (8 warps): E = U V^T (mma), in-block scan -> P ----
#define SA_SMEM (4 * 64 * 72 * 2 + 64 * 66 * 4)   // 36864 + 16896 = 53760
__global__ void __launch_bounds__(256) stageA_scan()
{
    extern __shared__ char sma[];
    uint16_t* sUh = (uint16_t*)sma;
    uint16_t* sUl = sUh + 64 * 72;
    uint16_t* sVh = sUl + 64 * 72;
    uint16_t* sVl = sVh + 64 * 72;
    float* sE = (float*)(sma + 4 * 64 * 72 * 2);
    uint32_t pUh = smem_u32(sUh), pUl = smem_u32(sUl);
    uint32_t pVh = smem_u32(sVh), pVl = smem_u32(sVl);
    int bh = blockIdx.x, h = bh & (HH - 1);
    int tid = threadIdx.x, warp = tid >> 5, lane = tid & 31;
    int warp_m = warp >> 1, warp_n = warp & 1;
    int g = lane >> 2, tg = lane & 3;
    const float* up = g_u + (long)bh * LL;
    const uint16_t* vh = g_VSh + h * 4096;
    const uint16_t* vl = g_VSl + h * 4096;

    uint32_t a_row = (uint32_t)(lane & 15) * (72 * 2) + ((lane & 16) ? 16u : 0u);
    uint32_t b_row = ((uint32_t)(lane & 7) + ((lane & 16) ? 8u : 0u)) * (72 * 2)
                   + ((lane & 8) ? 16u : 0u);

    // load u fp32, split into smem planes ([row=c][t], stride 72)
#pragma unroll
    for (int p = 0; p < 4; p++) {
        int i = tid + p * 256;
        int e = i * 4, row = e >> 6, col = e & 63;
        float4 v = *(const float4*)(up + e);
        uint16_t h0, l0, h1, l1, h2, l2, h3, l3;
        splitf(v.x, h0, l0); splitf(v.y, h1, l1);
        splitf(v.z, h2, l2); splitf(v.w, h3, l3);
        *(uint2*)&sUh[row * 72 + col] = make_uint2((uint32_t)h0 | ((uint32_t)h1 << 16),
                                                   (uint32_t)h2 | ((uint32_t)h3 << 16));
        *(uint2*)&sUl[row * 72 + col] = make_uint2((uint32_t)l0 | ((uint32_t)l1 << 16),
                                                   (uint32_t)l2 | ((uint32_t)l3 << 16));
    }
#pragma unroll
    for (int p = 0; p < 2; p++) {
        int i = tid + p * 256;
        int row = i >> 3, seg = i & 7;
        *(uint4*)&sVh[row * 72 + seg * 8] = *(const uint4*)&vh[row * 64 + seg * 8];
        *(uint4*)&sVl[row * 72 + seg * 8] = *(const uint4*)&vl[row * 64 + seg * 8];
    }
    __syncthreads();

    float acc[4][4];
#pragma unroll
    for (int nt = 0; nt < 4; nt++)
#pragma unroll
        for (int q = 0; q < 4; q++) acc[nt][q] = 0.0f;
    int ra = warp_m * 16;
#pragma unroll
    for (int ks = 0; ks < 4; ks++) {
        uint32_t kboff = (uint32_t)(ks * 16) * 2;
        uint32_t ah[4], al[4];
        uint32_t ro = (uint32_t)ra * (72 * 2) + a_row + kboff;
        ldsm_x4(ah, pUh + ro);
        ldsm_x4(al, pUl + ro);
#pragma unroll
        for (int ntp = 0; ntp < 2; ntp++) {
            uint32_t nb = (uint32_t)(warp_n * 32 + ntp * 16) * (72 * 2) + b_row + kboff;
            uint32_t bhp[4], blp[4];
            ldsm_x4(bhp, pVh + nb);
            ldsm_x4(blp, pVl + nb);
#pragma unroll
            for (int sub = 0; sub < 2; sub++) {
                int nt = ntp * 2 + sub;
                mma16816(acc[nt], ah, bhp[sub * 2], bhp[sub * 2 + 1]);
                mma16816(acc[nt], ah, blp[sub * 2], blp[sub * 2 + 1]);
                mma16816(acc[nt], al, bhp[sub * 2], bhp[sub * 2 + 1]);
            }
        }
    }

    // E -> smem
#pragma unroll
    for (int nt = 0; nt < 4; nt++) {
        int s = warp_n * 32 + nt * 8 + tg * 2;
        sE[(ra + g) * 66 + s] = acc[nt][0];
        sE[(ra + g) * 66 + s + 1] = acc[nt][1];
        sE[(ra + g + 8) * 66 + s] = acc[nt][2];
        sE[(ra + g + 8) * 66 + s + 1] = acc[nt][3];
    }
    __syncthreads();

    // in-block scan over chunks (32 threads; n = complex state index)
    if (tid < 32) {
        int n = tid;
        float wr = g_wS[(h * NST + n) * 2 + 0];
        float wi = g_wS[(h * NST + n) * 2 + 1];
        uint32_t* ph = (uint32_t*)g_PSh + (long)bh * (LL / 2);
        uint32_t* pl = (uint32_t*)g_PSl + (long)bh * (LL / 2);
        float sr = 0.0f, si = 0.0f;
        for (int c = 0; c < NC; c++) {
            uint16_t hr, lr, hi2, li2;
            splitf(sr, hr, lr);
            splitf(si, hi2, li2);
            ph[c * 32 + n] = (uint32_t)hr | ((uint32_t)hi2 << 16);
            pl[c * 32 + n] = (uint32_t)lr | ((uint32_t)li2 << 16);
            float er = sE[c * 66 + 2 * n];
            float ei = sE[c * 66 + 2 * n + 1];
            float nsr = wr * sr - wi * si + er;
            si = wr * si + wi * sr + ei;
            sr = nsr;
        }
    }
}

// ---------------- stage C (mma, 8 warps): Y = [u|P] * CM^T, + Dskip*u, gelu, +u ----------------
#define CST 136
#define SC_SMEM (4 * 64 * CST * 2 + 64 * 68 * 4)   // 69632 + 17408 = 87040
__global__ void __launch_bounds__(256) stageC_mma(const float* __restrict__ Dskip)
{
    extern __shared__ char smemc[];
    uint16_t* sIh = (uint16_t*)smemc;
    uint16_t* sIl = sIh + 64 * CST;
    uint16_t* sCh = sIl + 64 * CST;
    uint16_t* sCl = sCh + 64 * CST;
    float* sUf = (float*)(smemc + 4 * 64 * CST * 2);
    uint32_t pIh = smem_u32(sIh), pIl = smem_u32(sIl);
    uint32_t pCh = smem_u32(sCh), pCl = smem_u32(sCl);
    int bh = blockIdx.x, h = bh & (HH - 1);
    int tid = threadIdx.x, warp = tid >> 5, lane = tid & 31;
    int warp_m = warp >> 1, warp_n = warp & 1;
    int g = lane >> 2, tg = lane & 3;
    const float* up = g_u + (long)bh * LL;
    const uint16_t* ph = g_PSh + (long)bh * LL;
    const uint16_t* pl = g_PSl + (long)bh * LL;
    const uint16_t* ch = g_CMSh + h * 8192;
    const uint16_t* cl = g_CMSl + h * 8192;

    uint32_t a_row = (uint32_t)(lane & 15) * (CST * 2) + ((lane & 16) ? 16u : 0u);
    uint32_t b_row = ((uint32_t)(lane & 7) + ((lane & 16) ? 8u : 0u)) * (CST * 2)
                   + ((lane & 8) ? 16u : 0u);

    // u fp32 -> sUf + split planes (cols 0..63 of sI)
#pragma unroll
    for (int p = 0; p < 4; p++) {
        int i = tid + p * 256;
        int e = i * 4, row = e >> 6, col = e & 63;
        float4 v = *(const float4*)(up + e);
        *(float4*)&sUf[row * 68 + col] = v;
        uint16_t h0, l0, h1, l1, h2, l2, h3, l3;
        splitf(v.x, h0, l0); splitf(v.y, h1, l1);
        splitf(v.z, h2, l2); splitf(v.w, h3, l3);
        *(uint2*)&sIh[row * CST + col] = make_uint2((uint32_t)h0 | ((uint32_t)h1 << 16),
                                                    (uint32_t)h2 | ((uint32_t)h3 << 16));
        *(uint2*)&sIl[row * CST + col] = make_uint2((uint32_t)l0 | ((uint32_t)l1 << 16),
                                                    (uint32_t)l2 | ((uint32_t)l3 << 16));
    }
    // P planes (cols 64..127 of sI)
#pragma unroll
    for (int p = 0; p < 2; p++) {
        int i = tid + p * 256;
        int row = i >> 3, seg = i & 7;
        *(uint4*)&sIh[row * CST + 64 + seg * 8] = *(const uint4*)&ph[row * 64 + seg * 8];
        *(uint4*)&sIl[row * CST + 64 + seg * 8] = *(const uint4*)&pl[row * 64 + seg * 8];
    }
    // CM planes
#pragma unroll
    for (int p = 0; p < 4; p++) {
        int i = tid + p * 256;
        int row = i >> 4, seg = i & 15;
        *(uint4*)&sCh[row * CST + seg * 8] = *(const uint4*)&ch[row * 128 + seg * 8];
        *(uint4*)&sCl[row * CST + seg * 8] = *(const uint4*)&cl[row * 128 + seg * 8];
    }
    __syncthreads();

    float acc[4][4];
#pragma unroll
    for (int nt = 0; nt < 4; nt++)
#pragma unroll
        for (int q = 0; q < 4; q++) acc[nt][q] = 0.0f;
    int ra = warp_m * 16;
#pragma unroll
    for (int ks = 0; ks < 8; ks++) {
        uint32_t kboff = (uint32_t)(ks * 16) * 2;
        uint32_t ah[4], al[4];
        uint32_t ro = (uint32_t)ra * (CST * 2) + a_row + kboff;
        ldsm_x4(ah, pIh + ro);
        ldsm_x4(al, pIl + ro);
#pragma unroll
        for (int ntp = 0; ntp < 2; ntp++) {
            uint32_t nb = (uint32_t)(warp_n * 32 + ntp * 16) * (CST * 2) + b_row + kboff;
            uint32_t bhp[4], blp[4];
            ldsm_x4(bhp, pCh + nb);
            ldsm_x4(blp, pCl + nb);
#pragma unroll
            for (int sub = 0; sub < 2; sub++) {
                int nt = ntp * 2 + sub;
                mma16816(acc[nt], ah, bhp[sub * 2], bhp[sub * 2 + 1]);
                mma16816(acc[nt], ah, blp[sub * 2], blp[sub * 2 + 1]);
                mma16816(acc[nt], al, bhp[sub * 2], bhp[sub * 2 + 1]);
            }
        }
    }

    float dsk = Dskip[h];
    float* hp = g_hres + (long)bh * LL;
#pragma unroll
    for (int nt = 0; nt < 4; nt++) {
        int t = warp_n * 32 + nt * 8 + tg * 2;
        float u00 = sUf[(ra + g) * 68 + t],     u01 = sUf[(ra + g) * 68 + t + 1];
        float u10 = sUf[(ra + g + 8) * 68 + t], u11 = sUf[(ra + g + 8) * 68 + t + 1];
        float y0 = gelu_f(acc[nt][0] + dsk * u00) + u00;
        float y1 = gelu_f(acc[nt][1] + dsk * u01) + u01;
        float y2 = gelu_f(acc[nt][2] + dsk * u10) + u10;
        float y3 = gelu_f(acc[nt][3] + dsk * u11) + u11;
        *(float2*)&hp[(ra + g) * 64 + t] = make_float2(y0, y1);
        *(float2*)&hp[(ra + g + 8) * 64 + t] = make_float2(y2, y3);
    }
}

// ---------------- layernorm + transpose (B,H,L) -> (B,L,H), split output ----------------
__global__ void __launch_bounds__(256, 1) layernorm_kernel(const float* __restrict__ ln_g,
                                                           const float* __restrict__ ln_b)
{
    int b = blockIdx.y;
    int l0 = blockIdx.x * 32;
    __shared__ float tile[256][33];
    int tid = threadIdx.x;
    int w = tid >> 5, lane = tid & 31;
    const float* hp = g_hres + (long)b * HH * LL;
    for (int hh = w; hh < 256; hh += 8) {
        tile[hh][lane] = hp[(long)hh * LL + l0 + lane];
    }
    __syncthreads();
    uint16_t* oph = g_tlnSh + ((long)b * LL + l0) * HH;
    uint16_t* opl = g_tlnSl + ((long)b * LL + l0) * HH;
#pragma unroll
    for (int q = 0; q < 4; q++) {
        int tok = w * 4 + q;
        float s = 0.0f, sq = 0.0f;
#pragma unroll
        for (int j = 0; j < 8; j++) {
            float v = tile[lane + 32 * j][tok];
            s += v;
            sq += v * v;
        }
#pragma unroll
        for (int o = 16; o > 0; o >>= 1) {
            s += __shfl_xor_sync(0xffffffffu, s, o);
            sq += __shfl_xor_sync(0xffffffffu, sq, o);
        }
        float mean = s * (1.0f / 256.0f);
        float var = sq * (1.0f / 256.0f) - mean * mean;
        float rstd = rsqrtf(var + 1e-5f);
#pragma unroll
        for (int j = 0; j < 8; j++) {
            int hh = lane + 32 * j;
            float v = (tile[hh][tok] - mean) * rstd * ln_g[hh] + ln_b[hh];
            uint16_t vh, vl;
            splitf(v, vh, vl);
            oph[(long)tok * HH + hh] = vh;
            opl[(long)tok * HH + hh] = vl;
        }
    }
}

// ---------------- launcher ----------------
extern "C" void kernel_launch(void* const* d_in, const int* in_sizes, int n_in,
                              void* d_out, int out_size)
{
    const float* x          = (const float*)d_in[0];
    const float* enc_w      = (const float*)d_in[1];
    const float* enc_b      = (const float*)d_in[2];
    const float* log_dt     = (const float*)d_in[3];
    const float* log_A_real = (const float*)d_in[4];
    const float* A_imag     = (const float*)d_in[5];
    const float* B_re       = (const float*)d_in[6];
    const float* B_im       = (const float*)d_in[7];
    const float* C_re       = (const float*)d_in[8];
    const float* C_im       = (const float*)d_in[9];
    const float* Dskip      = (const float*)d_in[10];
    const float* ln_g       = (const float*)d_in[11];
    const float* ln_b       = (const float*)d_in[12];
    const float* dec1_w     = (const float*)d_in[13];
    const float* dec1_b     = (const float*)d_in[14];
    const float* dec2_w     = (const float*)d_in[15];
    const float* dec2_b     = (const float*)d_in[16];
    float* out = (float*)d_out;

    void *pu = 0;
    void *pxh = 0, *pxl = 0, *pweh = 0, *pwel = 0, *pw1h = 0, *pw1l = 0, *pw2h = 0, *pw2l = 0;
    void *ptlh = 0, *ptll = 0, *pzh = 0, *pzl = 0;
    cudaGetSymbolAddress(&pu, g_u);
    cudaGetSymbolAddress(&pxh, g_xSh);   cudaGetSymbolAddress(&pxl, g_xSl);
    cudaGetSymbolAddress(&pweh, g_wencSh); cudaGetSymbolAddress(&pwel, g_wencSl);
    cudaGetSymbolAddress(&pw1h, g_w1Sh); cudaGetSymbolAddress(&pw1l, g_w1Sl);
    cudaGetSymbolAddress(&pw2h, g_w2Sh); cudaGetSymbolAddress(&pw2l, g_w2Sl);
    cudaGetSymbolAddress(&ptlh, g_tlnSh); cudaGetSymbolAddress(&ptll, g_tlnSl);
    cudaGetSymbolAddress(&pzh, g_zSh);   cudaGetSymbolAddress(&pzl, g_zSl);

    cudaFuncSetAttribute(gemm_ps<false, 2>, cudaFuncAttributeMaxDynamicSharedMemorySize, GP_SMEM);
    cudaFuncSetAttribute(gemm_ps<true, 1>,  cudaFuncAttributeMaxDynamicSharedMemorySize, GP_SMEM);
    cudaFuncSetAttribute(gemm_ps<false, 0>, cudaFuncAttributeMaxDynamicSharedMemorySize, GP_SMEM);
    cudaFuncSetAttribute(stageA_scan, cudaFuncAttributeMaxDynamicSharedMemorySize, SA_SMEM);
    cudaFuncSetAttribute(stageC_mma,  cudaFuncAttributeMaxDynamicSharedMemorySize, SC_SMEM);

    // #1..#3: splits (order keeps enc at launch #4 -> ncu capture)
    split_pad<<<(MTOK * 128 + 255) / 256, 256>>>(x, (uint16_t*)pxh, (uint16_t*)pxl,
                                                 MTOK, DIN, 128, MTOK * 128);
    split_pad<<<(HH * 128 + 255) / 256, 256>>>(enc_w, (uint16_t*)pweh, (uint16_t*)pwel,
                                               HH, DIN, 128, HH * 128);
    split_pad<<<(DMID * HH + 255) / 256, 256>>>(dec1_w, (uint16_t*)pw1h, (uint16_t*)pw1l,
                                                DMID, HH, HH, DMID * HH);

    // #4: encoder GEMM -> g_u fp32 (B,H,L)   [ncu capture target]
    gemm_ps<false, 2><<<dim3(2, 512), 256, GP_SMEM>>>(
        (const uint16_t*)pxh, (const uint16_t*)pxl,
        (const uint16_t*)pweh, (const uint16_t*)pwel,
        enc_b, (float*)pu, nullptr, nullptr,
        128, HH, 0);

    // #5, #6
    precompute_kernel<<<HH, 64>>>(log_dt, log_A_real, A_imag, B_re, B_im, C_re, C_im);
    split_pad<<<(128 * DMID + 255) / 256, 256>>>(dec2_w, (uint16_t*)pw2h, (uint16_t*)pw2l,
                                                 DOUTP, DMID, DMID, 128 * DMID);

    // #7: chunk states + fused cross-chunk scan -> P split planes
    stageA_scan<<<BB * HH, 256, SA_SMEM>>>();

    // #8: output stage (mma) + Dskip + gelu + residual
    stageC_mma<<<BB * HH, 256, SC_SMEM>>>(Dskip);

    // #9: layernorm + transpose -> split planes
    layernorm_kernel<<<dim3(LL / 32, BB), 256>>>(ln_g, ln_b);

    // #10, #11: decoder MLP
    gemm_ps<true, 1><<<dim3(4, 512), 256, GP_SMEM>>>(
        (const uint16_t*)ptlh, (const uint16_t*)ptll,
        (const uint16_t*)pw1h, (const uint16_t*)pw1l,
        dec1_b, nullptr, (uint16_t*)pzh, (uint16_t*)pzl,
        HH, DMID, DMID);

    gemm_ps<false, 0><<<dim3(1, 512), 256, GP_SMEM>>>(
        (const uint16_t*)pzh, (const uint16_t*)pzl,
        (const uint16_t*)pw2h, (const uint16_t*)pw2l,
        dec2_b, out, nullptr, nullptr,
        DMID, DOUTP, DOUTP);
}

// round 11
// speedup vs baseline: 1.3215x; 1.0709x over previous
#include <cuda_runtime.h>
#include <cuda_bf16.h>
#include <math.h>
#include <stdint.h>

#define BB   16
#define HH   256
#define LL   4096
#define DIN  100
#define DMID 512
#define DOUTP 100
#define NST  32
#define CH   64
#define NC   64
#define MTOK (BB * LL)

// ---------------- fp32 intermediates ----------------
__device__ float g_u[BB * HH * LL];       // encoder output, (B,H,L)
__device__ float g_hres[BB * HH * LL];    // post-gelu residual, (B,H,L)
__device__ float g_wS[HH * NST * 2];      // w^64 per (h,n)

// ---------------- bf16 hi/lo split planes ----------------
__device__ uint16_t g_xSh[MTOK * 128],  g_xSl[MTOK * 128];     // x padded K 100->128
__device__ uint16_t g_wencSh[HH * 128], g_wencSl[HH * 128];    // enc_w padded
__device__ uint16_t g_w1Sh[DMID * HH],  g_w1Sl[DMID * HH];
__device__ uint16_t g_w2Sh[128 * DMID], g_w2Sl[128 * DMID];    // dec2_w padded rows 100->128
__device__ uint16_t g_tlnSh[BB * LL * HH], g_tlnSl[BB * LL * HH];
__device__ uint16_t g_zSh[MTOK * DMID], g_zSl[MTOK * DMID];
__device__ uint16_t g_VSh[HH * 64 * 64], g_VSl[HH * 64 * 64];  // [h][s][t]
__device__ uint16_t g_CMSh[HH * 64 * 128], g_CMSl[HH * 64 * 128]; // [h][t][k]

__device__ __forceinline__ float gelu_f(float x) {
    return 0.5f * x * (1.0f + erff(x * 0.70710678118654752f));
}
__device__ __forceinline__ void splitf(float v, uint16_t& h, uint16_t& l) {
    __nv_bfloat16 bh = __float2bfloat16_rn(v);
    float hf = __bfloat162float(bh);
    __nv_bfloat16 bl = __float2bfloat16_rn(v - hf);
    h = *(uint16_t*)&bh; l = *(uint16_t*)&bl;
}
__device__ __forceinline__ void mma16816(float* c, const uint32_t* a, uint32_t b0, uint32_t b1) {
    asm volatile(
        "mma.sync.aligned.m16n8k16.row.col.f32.bf16.bf16.f32 "
        "{%0,%1,%2,%3}, {%4,%5,%6,%7}, {%8,%9}, {%0,%1,%2,%3};"
        : "+f"(c[0]), "+f"(c[1]), "+f"(c[2]), "+f"(c[3])
        : "r"(a[0]), "r"(a[1]), "r"(a[2]), "r"(a[3]), "r"(b0), "r"(b1));
}
__device__ __forceinline__ void ldsm_x4(uint32_t* r, uint32_t addr) {
    asm volatile("ldmatrix.sync.aligned.m8n8.x4.shared.b16 {%0,%1,%2,%3}, [%4];"
        : "=r"(r[0]), "=r"(r[1]), "=r"(r[2]), "=r"(r[3]) : "r"(addr));
}
__device__ __forceinline__ uint32_t smem_u32(const void* p) {
    uint32_t a;
    asm("{ .reg .u64 t; cvta.to.shared.u64 t, %1; cvt.u32.u64 %0, t; }" : "=r"(a) : "l"(p));
    return a;
}
#define CP16(dst, src) asm volatile("cp.async.cg.shared.global [%0], [%1], 16;" :: "r"(dst), "l"(src))
#define CPCOMMIT() asm volatile("cp.async.commit_group;" ::: "memory")
#define CPWAIT1() asm volatile("cp.async.wait_group 1;" ::: "memory")
#define CPWAIT0() asm volatile("cp.async.wait_group 0;" ::: "memory")

// ---------------- split+pad elementwise kernel ----------------
__global__ void split_pad(const float* __restrict__ src, uint16_t* __restrict__ dh,
                          uint16_t* __restrict__ dl, int M, int K, int Kp, int total)
{
    int i = blockIdx.x * 256 + threadIdx.x;
    if (i >= total) return;
    int r = i / Kp, c = i - r * Kp;
    float v = (r < M && c < K) ? src[(long)r * K + c] : 0.0f;
    uint16_t h, l; splitf(v, h, l);
    dh[i] = h; dl[i] = l;
}

// ============ pre-split tensor-core GEMM: C[M,N] = A[M,K]*B[N,K]^T + bias ============
#define SAST 40
#define PLANE_BYTES (128 * SAST * 2)   // 10240
#define BUF_BYTES (4 * PLANE_BYTES)    // 40960
#define GP_SMEM (2 * BUF_BYTES)        // 81920

template <bool GELU, int OM>
__global__ void __launch_bounds__(256, 2)
gemm_ps(const uint16_t* __restrict__ Ah, const uint16_t* __restrict__ Al,
        const uint16_t* __restrict__ Bh, const uint16_t* __restrict__ Bl,
        const float* __restrict__ bias, float* __restrict__ Cf,
        uint16_t* __restrict__ Coh, uint16_t* __restrict__ Col,
        int K, int Nvalid, int ldc)
{
    extern __shared__ char smem[];
    uint32_t sb = smem_u32(smem);
    int tid = threadIdx.x;
    int warp = tid >> 5, lane = tid & 31;
    int warp_m = warp >> 1, warp_n = warp & 1;
    int g = lane >> 2, tg = lane & 3;
    int m0 = blockIdx.y * 128, n0 = blockIdx.x * 128;

    uint32_t a_row = (uint32_t)(lane & 15) * (SAST * 2) + ((lane & 16) ? 16u : 0u);
    uint32_t b_row = ((uint32_t)(lane & 7) + ((lane & 16) ? 8u : 0u)) * (SAST * 2)
                   + ((lane & 8) ? 16u : 0u);

    auto load_chunk = [&](int buf, int k0) {
        uint32_t base = sb + (uint32_t)buf * BUF_BYTES;
#pragma unroll
        for (int p = 0; p < 2; p++) {
            int idx = tid + p * 256;
            int row = idx >> 2, seg = idx & 3;
            uint32_t doff = (uint32_t)(row * SAST + seg * 8) * 2;
            long ao = (long)(m0 + row) * K + k0 + seg * 8;
            long bo = (long)(n0 + row) * K + k0 + seg * 8;
            CP16(base + doff, Ah + ao);
            CP16(base + PLANE_BYTES + doff, Al + ao);
            CP16(base + 2 * PLANE_BYTES + doff, Bh + bo);
            CP16(base + 3 * PLANE_BYTES + doff, Bl + bo);
        }
    };

    float acc[2][8][4];
#pragma unroll
    for (int mt = 0; mt < 2; mt++)
#pragma unroll
        for (int nt = 0; nt < 8; nt++)
#pragma unroll
            for (int q = 0; q < 4; q++) acc[mt][nt][q] = 0.0f;

    int nch = K >> 5;
    load_chunk(0, 0);
    CPCOMMIT();
    for (int c = 0; c < nch; c++) {
        if (c + 1 < nch) { load_chunk((c + 1) & 1, (c + 1) << 5); CPCOMMIT(); CPWAIT1(); }
        else CPWAIT0();
        __syncthreads();
        uint32_t bufb = sb + (uint32_t)(c & 1) * BUF_BYTES;
        uint32_t pAh = bufb, pAl = bufb + PLANE_BYTES;
        uint32_t pBh = bufb + 2 * PLANE_BYTES, pBl = bufb + 3 * PLANE_BYTES;
#pragma unroll
        for (int ks = 0; ks < 2; ks++) {
            uint32_t kboff = (uint32_t)(ks * 16) * 2;
            uint32_t ah[2][4], al[2][4];
#pragma unroll
            for (int mt = 0; mt < 2; mt++) {
                uint32_t ro = (uint32_t)(warp_m * 32 + mt * 16) * (SAST * 2) + a_row + kboff;
                ldsm_x4(ah[mt], pAh + ro);
                ldsm_x4(al[mt], pAl + ro);
            }
#pragma unroll
            for (int ntp = 0; ntp < 4; ntp++) {
                uint32_t nb = (uint32_t)(warp_n * 64 + ntp * 16) * (SAST * 2) + b_row + kboff;
                uint32_t bhp[4], blp[4];
                ldsm_x4(bhp, pBh + nb);
                ldsm_x4(blp, pBl + nb);
                // term-major ordering: same-acc dependency distance = 4
#pragma unroll
                for (int sub = 0; sub < 2; sub++)
#pragma unroll
                    for (int mt = 0; mt < 2; mt++)
                        mma16816(acc[mt][ntp * 2 + sub], ah[mt], bhp[sub * 2], bhp[sub * 2 + 1]);
#pragma unroll
                for (int sub = 0; sub < 2; sub++)
#pragma unroll
                    for (int mt = 0; mt < 2; mt++)
                        mma16816(acc[mt][ntp * 2 + sub], ah[mt], blp[sub * 2], blp[sub * 2 + 1]);
#pragma unroll
                for (int sub = 0; sub < 2; sub++)
#pragma unroll
                    for (int mt = 0; mt < 2; mt++)
                        mma16816(acc[mt][ntp * 2 + sub], al[mt], bhp[sub * 2], bhp[sub * 2 + 1]);
            }
        }
        __syncthreads();
    }

    // -------- epilogue via smem stage --------
    float* stage = (float*)smem;
    for (int nh = 0; nh < 2; nh++) {
        if (warp_n == nh) {
#pragma unroll
            for (int mt = 0; mt < 2; mt++) {
#pragma unroll
                for (int nt = 0; nt < 8; nt++) {
                    int nl = nt * 8 + tg * 2;
                    int ng = n0 + nh * 64 + nl;
                    int r0 = warp_m * 32 + mt * 16 + g;
                    float b0v = (OM == 0) ? ((ng < Nvalid) ? bias[ng] : 0.0f) : bias[ng];
                    float b1v = (OM == 0) ? ((ng + 1 < Nvalid) ? bias[ng + 1] : 0.0f) : bias[ng + 1];
                    float v0 = acc[mt][nt][0] + b0v;
                    float v1 = acc[mt][nt][1] + b1v;
                    float v2 = acc[mt][nt][2] + b0v;
                    float v3 = acc[mt][nt][3] + b1v;
                    if (GELU) { v0 = gelu_f(v0); v1 = gelu_f(v1); v2 = gelu_f(v2); v3 = gelu_f(v3); }
                    if (OM == 2) {
                        stage[nl * 132 + r0] = v0;
                        stage[(nl + 1) * 132 + r0] = v1;
                        stage[nl * 132 + r0 + 8] = v2;
                        stage[(nl + 1) * 132 + r0 + 8] = v3;
                    } else {
                        stage[r0 * 68 + nl] = v0;
                        stage[r0 * 68 + nl + 1] = v1;
                        stage[(r0 + 8) * 68 + nl] = v2;
                        stage[(r0 + 8) * 68 + nl + 1] = v3;
                    }
                }
            }
        }
        __syncthreads();
        if (OM == 2) {
            int bidx = m0 >> 12;
            int l0 = m0 & 4095;
#pragma unroll
            for (int p = 0; p < 8; p++) {
                int nl = p * 8 + warp;
                int m4 = lane * 4;
                float4 v = *(float4*)&stage[nl * 132 + m4];
                int ng = n0 + nh * 64 + nl;
                long base = ((long)((bidx << 8) + ng)) * 4096 + l0 + m4;
                *(float4*)&Cf[base] = v;
            }
        } else if (OM == 1) {
#pragma unroll
            for (int p = 0; p < 8; p++) {
                int idx = tid + p * 256;
                int r = idx >> 4;
                int c4 = (idx & 15) * 4;
                int n = n0 + nh * 64 + c4;
                float4 v = *(float4*)&stage[r * 68 + c4];
                long base = (long)(m0 + r) * ldc + n;
                uint16_t h0, h1, h2, h3, q0, q1, q2, q3;
                splitf(v.x, h0, q0); splitf(v.y, h1, q1);
                splitf(v.z, h2, q2); splitf(v.w, h3, q3);
                uint64_t ph = (uint64_t)h0 | ((uint64_t)h1 << 16) | ((uint64_t)h2 << 32) | ((uint64_t)h3 << 48);
                uint64_t pq = (uint64_t)q0 | ((uint64_t)q1 << 16) | ((uint64_t)q2 << 32) | ((uint64_t)q3 << 48);
                *(uint64_t*)&Coh[base] = ph;
                *(uint64_t*)&Col[base] = pq;
            }
        } else {
#pragma unroll
            for (int p = 0; p < 8; p++) {
                int idx = tid + p * 256;
                int r = idx >> 4;
                int c4 = (idx & 15) * 4;
                int n = n0 + nh * 64 + c4;
                if (n < Nvalid) {
                    float4 v = *(float4*)&stage[r * 68 + c4];
                    *(float4*)&Cf[(long)(m0 + r) * ldc + n] = v;
                }
            }
        }
        __syncthreads();
    }
}

// ---------------- precompute per-head matrices (split output) ----------------
__global__ void precompute_kernel(const float* __restrict__ log_dt,
                                  const float* __restrict__ log_A_real,
                                  const float* __restrict__ A_imag,
                                  const float* __restrict__ B_re,
                                  const float* __restrict__ B_im,
                                  const float* __restrict__ C_re,
                                  const float* __restrict__ C_im)
{
    int h = blockIdx.x;
    int t = threadIdx.x;   // 0..63
    __shared__ float s_dtr[NST], s_dti[NST], s_c2r[NST], s_c2i[NST];
    __shared__ float s_k[CH];

    float dt = expf(log_dt[h]);
    if (t < NST) {
        int n = t;
        float Ar = -expf(log_A_real[h * NST + n]);
        float Ai = A_imag[h * NST + n];
        float dtr = dt * Ar, dti = dt * Ai;
        float er = expf(dtr);
        float Er = er * cosf(dti) - 1.0f;
        float Ei = er * sinf(dti);
        float br = B_re[h * NST + n], bi = B_im[h * NST + n];
        float cr = C_re[h * NST + n], ci = C_im[h * NST + n];
        float BCr = br * cr - bi * ci;
        float BCi = br * ci + bi * cr;
        float numr = BCr * Er - BCi * Ei;
        float numi = BCr * Ei + BCi * Er;
        float den = Ar * Ar + Ai * Ai;
        float cpr = (numr * Ar + numi * Ai) / den;
        float cpi = (numi * Ar - numr * Ai) / den;
        s_c2r[n] = 2.0f * cpr;
        s_c2i[n] = 2.0f * cpi;
        s_dtr[n] = dtr;
        s_dti[n] = dti;
        float e64 = expf(64.0f * dtr);
        g_wS[(h * NST + n) * 2 + 0] = e64 * cosf(64.0f * dti);
        g_wS[(h * NST + n) * 2 + 1] = e64 * sinf(64.0f * dti);
    }
    __syncthreads();

    float kt = 0.0f;
    for (int n = 0; n < NST; n++) {
        float dtr = s_dtr[n], dti = s_dti[n];
        float c2r = s_c2r[n], c2i = s_c2i[n];
        float p = (float)(63 - t);
        float ep = expf(p * dtr);
        float vr = ep * cosf(p * dti), vi = ep * sinf(p * dti);
        uint16_t hh, ll;
        splitf(vr, hh, ll);
        g_VSh[h * 4096 + (2 * n) * 64 + t] = hh; g_VSl[h * 4096 + (2 * n) * 64 + t] = ll;
        splitf(vi, hh, ll);
        g_VSh[h * 4096 + (2 * n + 1) * 64 + t] = hh; g_VSl[h * 4096 + (2 * n + 1) * 64 + t] = ll;
        float pt = (float)t;
        float et = expf(pt * dtr);
        float wr = et * cosf(pt * dti), wi = et * sinf(pt * dti);
        kt += c2r * wr - c2i * wi;
        float p1 = (float)(t + 1);
        float e1 = expf(p1 * dtr);
        float w1r = e1 * cosf(p1 * dti), w1i = e1 * sinf(p1 * dti);
        float gr = c2r * w1r - c2i * w1i;
        float gi = -(c2r * w1i + c2i * w1r);
        splitf(gr, hh, ll);
        g_CMSh[h * 8192 + t * 128 + 64 + 2 * n] = hh; g_CMSl[h * 8192 + t * 128 + 64 + 2 * n] = ll;
        splitf(gi, hh, ll);
        g_CMSh[h * 8192 + t * 128 + 64 + 2 * n + 1] = hh; g_CMSl[h * 8192 + t * 128 + 64 + 2 * n + 1] = ll;
    }
    s_k[t] = kt;
    __syncthreads();
    for (int j = 0; j < CH; j++) {
        float val = (j <= t) ? s_k[t - j] : 0.0f;
        uint16_t hh, ll; splitf(val, hh, ll);
        g_CMSh[h * 8192 + t * 128 + j] = hh;
        g_CMSl[h * 8192 + t * 128 + j] = ll;
    }
}

// ================= fused stageA + scan + stageC =================
// smem layout (bytes):
#define FU_UH 0
#define FU_UL 9216
#define FU_W  18432                 // V planes (phase1) then CM planes (phase3)
#define FU_VH FU_W
#define FU_VL (FU_W + 9216)
#define FU_CH FU_W
#define FU_CL (FU_W + 17408)
#define FU_E  53248                 // fp32, stride 66
#define FU_PH 70144                 // P hi plane (stride 72) ; temp: segment totals (fp32)
#define FU_PL 79360                 // P lo plane ; temp: segment prefixes (fp32)
#define FU_SMEM 88576

__global__ void __launch_bounds__(256, 2) stageAC(const float* __restrict__ Dskip)
{
    extern __shared__ char sm[];
    uint16_t* sUh = (uint16_t*)(sm + FU_UH);
    uint16_t* sUl = (uint16_t*)(sm + FU_UL);
    uint16_t* sVh = (uint16_t*)(sm + FU_VH);
    uint16_t* sVl = (uint16_t*)(sm + FU_VL);
    uint16_t* sCh = (uint16_t*)(sm + FU_CH);
    uint16_t* sCl = (uint16_t*)(sm + FU_CL);
    float*    sE  = (float*)(sm + FU_E);
    uint16_t* sPh = (uint16_t*)(sm + FU_PH);
    uint16_t* sPl = (uint16_t*)(sm + FU_PL);
    float*    sTf   = (float*)(sm + FU_PH);   // temp in P-plane space
    float*    sPref = (float*)(sm + FU_PL);

    uint32_t pUh = smem_u32(sUh), pUl = smem_u32(sUl);
    uint32_t pVh = smem_u32(sVh), pVl = smem_u32(sVl);
    uint32_t pCh = smem_u32(sCh), pCl = smem_u32(sCl);
    uint32_t pPh = smem_u32(sPh), pPl = smem_u32(sPl);

    int bh = blockIdx.x, h = bh & (HH - 1);
    int tid = threadIdx.x, warp = tid >> 5, lane = tid & 31;
    int warp_m = warp >> 1, warp_n = warp & 1;
    int g = lane >> 2, tg = lane & 3;
    const float* up = g_u + (long)bh * LL;

    uint32_t a_row72 = (uint32_t)(lane & 15) * 144 + ((lane & 16) ? 16u : 0u);
    uint32_t b_row72 = ((uint32_t)(lane & 7) + ((lane & 16) ? 8u : 0u)) * 144 + ((lane & 8) ? 16u : 0u);
    uint32_t b_row136 = ((uint32_t)(lane & 7) + ((lane & 16) ? 8u : 0u)) * 272 + ((lane & 8) ? 16u : 0u);

    // ---- load u -> split planes; load V planes ----
    {
        const uint16_t* vh = g_VSh + h * 4096;
        const uint16_t* vl = g_VSl + h * 4096;
#pragma unroll
        for (int p = 0; p < 4; p++) {
            int i = tid + p * 256;
            int e = i * 4, row = e >> 6, col = e & 63;
            float4 v = *(const float4*)(up + e);
            uint16_t h0, l0, h1, l1, h2, l2, h3, l3;
            splitf(v.x, h0, l0); splitf(v.y, h1, l1);
            splitf(v.z, h2, l2); splitf(v.w, h3, l3);
            *(uint2*)&sUh[row * 72 + col] = make_uint2((uint32_t)h0 | ((uint32_t)h1 << 16),
                                                       (uint32_t)h2 | ((uint32_t)h3 << 16));
            *(uint2*)&sUl[row * 72 + col] = make_uint2((uint32_t)l0 | ((uint32_t)l1 << 16),
                                                       (uint32_t)l2 | ((uint32_t)l3 << 16));
        }
#pragma unroll
        for (int p = 0; p < 2; p++) {
            int i = tid + p * 256;
            int row = i >> 3, seg = i & 7;
            *(uint4*)&sVh[row * 72 + seg * 8] = *(const uint4*)&vh[row * 64 + seg * 8];
            *(uint4*)&sVl[row * 72 + seg * 8] = *(const uint4*)&vl[row * 64 + seg * 8];
        }
    }
    __syncthreads();

    // ---- phase 1: E = U V^T ----
    {
        float acc[4][4];
#pragma unroll
        for (int nt = 0; nt < 4; nt++)
#pragma unroll
            for (int q = 0; q < 4; q++) acc[nt][q] = 0.0f;
        int ra = warp_m * 16;
#pragma unroll
        for (int ks = 0; ks < 4; ks++) {
            uint32_t kboff = (uint32_t)(ks * 16) * 2;
            uint32_t ah[4], al[4];
            uint32_t ro = (uint32_t)ra * 144 + a_row72 + kboff;
            ldsm_x4(ah, pUh + ro);
            ldsm_x4(al, pUl + ro);
            uint32_t bhp[2][4], blp[2][4];
#pragma unroll
            for (int ntp = 0; ntp < 2; ntp++) {
                uint32_t nb = (uint32_t)(warp_n * 32 + ntp * 16) * 144 + b_row72 + kboff;
                ldsm_x4(bhp[ntp], pVh + nb);
                ldsm_x4(blp[ntp], pVl + nb);
            }
            // term-major, distance-4 chains
#pragma unroll
            for (int ntp = 0; ntp < 2; ntp++)
#pragma unroll
                for (int sub = 0; sub < 2; sub++)
                    mma16816(acc[ntp * 2 + sub], ah, bhp[ntp][sub * 2], bhp[ntp][sub * 2 + 1]);
#pragma unroll
            for (int ntp = 0; ntp < 2; ntp++)
#pragma unroll
                for (int sub = 0; sub < 2; sub++)
                    mma16816(acc[ntp * 2 + sub], ah, blp[ntp][sub * 2], blp[ntp][sub * 2 + 1]);
#pragma unroll
            for (int ntp = 0; ntp < 2; ntp++)
#pragma unroll
                for (int sub = 0; sub < 2; sub++)
                    mma16816(acc[ntp * 2 + sub], al, bhp[ntp][sub * 2], bhp[ntp][sub * 2 + 1]);
        }
        int ra2 = warp_m * 16;
#pragma unroll
        for (int nt = 0; nt < 4; nt++) {
            int s = warp_n * 32 + nt * 8 + tg * 2;
            sE[(ra2 + g) * 66 + s] = acc[nt][0];
            sE[(ra2 + g) * 66 + s + 1] = acc[nt][1];
            sE[(ra2 + g + 8) * 66 + s] = acc[nt][2];
            sE[(ra2 + g + 8) * 66 + s + 1] = acc[nt][3];
        }
    }
    __syncthreads();

    // ---- load CM planes (overwrites V region) ----
    {
        const uint16_t* ch = g_CMSh + h * 8192;
        const uint16_t* cl = g_CMSl + h * 8192;
#pragma unroll
        for (int p = 0; p < 4; p++) {
            int i = tid + p * 256;
            int row = i >> 4, seg = i & 15;
            *(uint4*)&sCh[row * 136 + seg * 8] = *(const uint4*)&ch[row * 128 + seg * 8];
            *(uint4*)&sCl[row * 136 + seg * 8] = *(const uint4*)&cl[row * 128 + seg * 8];
        }
    }

    // ---- phase 2: hierarchical scan -> P planes ----
    int segi = tid >> 5;          // 0..7  (8 chunks each)
    int n = tid & 31;
    float wr = g_wS[(h * NST + n) * 2 + 0];
    float wi = g_wS[(h * NST + n) * 2 + 1];
    {
        // pass 1: segment totals
        float sr = 0.0f, si = 0.0f;
#pragma unroll
        for (int j = 0; j < 8; j++) {
            int c = segi * 8 + j;
            float er = sE[c * 66 + 2 * n], ei = sE[c * 66 + 2 * n + 1];
            float nsr = wr * sr - wi * si + er;
            si = wr * si + wi * sr + ei;
            sr = nsr;
        }
        sTf[segi * 64 + 2 * n] = sr;
        sTf[segi * 64 + 2 * n + 1] = si;
    }
    __syncthreads();
    if (tid < 32) {
        // w^512 via 3 squarings of w^64
        float w2r = wr * wr - wi * wi, w2i = 2.0f * wr * wi;
        float w4r = w2r * w2r - w2i * w2i, w4i = 2.0f * w2r * w2i;
        float w8r = w4r * w4r - w4i * w4i, w8i = 2.0f * w4r * w4i;
        float pr = 0.0f, pi = 0.0f;
#pragma unroll
        for (int s = 0; s < 8; s++) {
            sPref[s * 64 + 2 * n] = pr;
            sPref[s * 64 + 2 * n + 1] = pi;
            float tr = sTf[s * 64 + 2 * n], ti = sTf[s * 64 + 2 * n + 1];
            float npr = w8r * pr - w8i * pi + tr;
            pi = w8r * pi + w8i * pr + ti;
            pr = npr;
        }
    }
    __syncthreads();
    {
        float pr = sPref[segi * 64 + 2 * n];
        float pi = sPref[segi * 64 + 2 * n + 1];
        __syncthreads();   // everyone has read prefixes before overwrite
#pragma unroll
        for (int j = 0; j < 8; j++) {
            int c = segi * 8 + j;
            uint16_t hr, lr, hi2, li2;
            splitf(pr, hr, lr);
            splitf(pi, hi2, li2);
            sPh[c * 72 + 2 * n] = hr;  sPh[c * 72 + 2 * n + 1] = hi2;
            sPl[c * 72 + 2 * n] = lr;  sPl[c * 72 + 2 * n + 1] = li2;
            float er = sE[c * 66 + 2 * n], ei = sE[c * 66 + 2 * n + 1];
            float npr = wr * pr - wi * pi + er;
            pi = wr * pi + wi * pr + ei;
            pr = npr;
        }
    }
    __syncthreads();

    // ---- phase 3: Y = [u|P] * CM^T + Dskip*u, gelu, +u ----
    {
        float acc[4][4];
#pragma unroll
        for (int nt = 0; nt < 4; nt++)
#pragma unroll
            for (int q = 0; q < 4; q++) acc[nt][q] = 0.0f;
        int ra = warp_m * 16;
#pragma unroll
        for (int ks = 0; ks < 8; ks++) {
            uint32_t aH = (ks < 4) ? pUh : pPh;
            uint32_t aL = (ks < 4) ? pUl : pPl;
            uint32_t kloc = (uint32_t)((ks & 3) * 16) * 2;
            uint32_t ah[4], al[4];
            uint32_t ro = (uint32_t)ra * 144 + a_row72 + kloc;
            ldsm_x4(ah, aH + ro);
            ldsm_x4(al, aL + ro);
            uint32_t kb136 = (uint32_t)(ks * 16) * 2;
            uint32_t bhp[2][4], blp[2][4];
#pragma unroll
            for (int ntp = 0; ntp < 2; ntp++) {
                uint32_t nb = (uint32_t)(warp_n * 32 + ntp * 16) * 272 + b_row136 + kb136;
                ldsm_x4(bhp[ntp], pCh + nb);
                ldsm_x4(blp[ntp], pCl + nb);
            }
#pragma unroll
            for (int ntp = 0; ntp < 2; ntp++)
#pragma unroll
                for (int sub = 0; sub < 2; sub++)
                    mma16816(acc[ntp * 2 + sub], ah, bhp[ntp][sub * 2], bhp[ntp][sub * 2 + 1]);
#pragma unroll
            for (int ntp = 0; ntp < 2; ntp++)
#pragma unroll
                for (int sub = 0; sub < 2; sub++)
                    mma16816(acc[ntp * 2 + sub], ah, blp[ntp][sub * 2], blp[ntp][sub * 2 + 1]);
#pragma unroll
            for (int ntp = 0; ntp < 2; ntp++)
#pragma unroll
                for (int sub = 0; sub < 2; sub++)
                    mma16816(acc[ntp * 2 + sub], al, bhp[ntp][sub * 2], bhp[ntp][sub * 2 + 1]);
        }

        float dsk = Dskip[h];
        float* hp = g_hres + (long)bh * LL;
        int ra2 = warp_m * 16;
#pragma unroll
        for (int nt = 0; nt < 4; nt++) {
            int t = warp_n * 32 + nt * 8 + tg * 2;
            // reconstruct u from split planes (error ~2^-19, fine for skip/residual)
            float u00 = __bfloat162float(*(__nv_bfloat16*)&sUh[(ra2 + g) * 72 + t])
                      + __bfloat162float(*(__nv_bfloat16*)&sUl[(ra2 + g) * 72 + t]);
            float u01 = __bfloat162float(*(__nv_bfloat16*)&sUh[(ra2 + g) * 72 + t + 1])
                      + __bfloat162float(*(__nv_bfloat16*)&sUl[(ra2 + g) * 72 + t + 1]);
            float u10 = __bfloat162float(*(__nv_bfloat16*)&sUh[(ra2 + g + 8) * 72 + t])
                      + __bfloat162float(*(__nv_bfloat16*)&sUl[(ra2 + g + 8) * 72 + t]);
            float u11 = __bfloat162float(*(__nv_bfloat16*)&sUh[(ra2 + g + 8) * 72 + t + 1])
                      + __bfloat162float(*(__nv_bfloat16*)&sUl[(ra2 + g + 8) * 72 + t + 1]);
            float y0 = gelu_f(acc[nt][0] + dsk * u00) + u00;
            float y1 = gelu_f(acc[nt][1] + dsk * u01) + u01;
            float y2 = gelu_f(acc[nt][2] + dsk * u10) + u10;
            float y3 = gelu_f(acc[nt][3] + dsk * u11) + u11;
            *(float2*)&hp[(ra2 + g) * 64 + t] = make_float2(y0, y1);
            *(float2*)&hp[(ra2 + g + 8) * 64 + t] = make_float2(y2, y3);
        }
    }
}

// ---------------- layernorm + transpose (B,H,L) -> (B,L,H), split output ----------------
__global__ void __launch_bounds__(256, 1) layernorm_kernel(const float* __restrict__ ln_g,
                                                           const float* __restrict__ ln_b)
{
    int b = blockIdx.y;
    int l0 = blockIdx.x * 32;
    __shared__ float tile[256][33];
    int tid = threadIdx.x;
    int w = tid >> 5, lane = tid & 31;
    const float* hp = g_hres + (long)b * HH * LL;
    for (int hh = w; hh < 256; hh += 8) {
        tile[hh][lane] = hp[(long)hh * LL + l0 + lane];
    }
    __syncthreads();
    uint16_t* oph = g_tlnSh + ((long)b * LL + l0) * HH;
    uint16_t* opl = g_tlnSl + ((long)b * LL + l0) * HH;
#pragma unroll
    for (int q = 0; q < 4; q++) {
        int tok = w * 4 + q;
        float s = 0.0f, sq = 0.0f;
#pragma unroll
        for (int j = 0; j < 8; j++) {
            float v = tile[lane + 32 * j][tok];
            s += v;
            sq += v * v;
        }
#pragma unroll
        for (int o = 16; o > 0; o >>= 1) {
            s += __shfl_xor_sync(0xffffffffu, s, o);
            sq += __shfl_xor_sync(0xffffffffu, sq, o);
        }
        float mean = s * (1.0f / 256.0f);
        float var = sq * (1.0f / 256.0f) - mean * mean;
        float rstd = rsqrtf(var + 1e-5f);
#pragma unroll
        for (int j = 0; j < 8; j++) {
            int hh = lane + 32 * j;
            float v = (tile[hh][tok] - mean) * rstd * ln_g[hh] + ln_b[hh];
            uint16_t vh, vl;
            splitf(v, vh, vl);
            oph[(long)tok * HH + hh] = vh;
            opl[(long)tok * HH + hh] = vl;
        }
    }
}

// ---------------- launcher ----------------
extern "C" void kernel_launch(void* const* d_in, const int* in_sizes, int n_in,
                              void* d_out, int out_size)
{
    const float* x          = (const float*)d_in[0];
    const float* enc_w      = (const float*)d_in[1];
    const float* enc_b      = (const float*)d_in[2];
    const float* log_dt     = (const float*)d_in[3];
    const float* log_A_real = (const float*)d_in[4];
    const float* A_imag     = (const float*)d_in[5];
    const float* B_re       = (const float*)d_in[6];
    const float* B_im       = (const float*)d_in[7];
    const float* C_re       = (const float*)d_in[8];
    const float* C_im       = (const float*)d_in[9];
    const float* Dskip      = (const float*)d_in[10];
    const float* ln_g       = (const float*)d_in[11];
    const float* ln_b       = (const float*)d_in[12];
    const float* dec1_w     = (const float*)d_in[13];
    const float* dec1_b     = (const float*)d_in[14];
    const float* dec2_w     = (const float*)d_in[15];
    const float* dec2_b     = (const float*)d_in[16];
    float* out = (float*)d_out;

    void *pu = 0;
    void *pxh = 0, *pxl = 0, *pweh = 0, *pwel = 0, *pw1h = 0, *pw1l = 0, *pw2h = 0, *pw2l = 0;
    void *ptlh = 0, *ptll = 0, *pzh = 0, *pzl = 0;
    cudaGetSymbolAddress(&pu, g_u);
    cudaGetSymbolAddress(&pxh, g_xSh);   cudaGetSymbolAddress(&pxl, g_xSl);
    cudaGetSymbolAddress(&pweh, g_wencSh); cudaGetSymbolAddress(&pwel, g_wencSl);
    cudaGetSymbolAddress(&pw1h, g_w1Sh); cudaGetSymbolAddress(&pw1l, g_w1Sl);
    cudaGetSymbolAddress(&pw2h, g_w2Sh); cudaGetSymbolAddress(&pw2l, g_w2Sl);
    cudaGetSymbolAddress(&ptlh, g_tlnSh); cudaGetSymbolAddress(&ptll, g_tlnSl);
    cudaGetSymbolAddress(&pzh, g_zSh);   cudaGetSymbolAddress(&pzl, g_zSl);

    cudaFuncSetAttribute(gemm_ps<false, 2>, cudaFuncAttributeMaxDynamicSharedMemorySize, GP_SMEM);
    cudaFuncSetAttribute(gemm_ps<true, 1>,  cudaFuncAttributeMaxDynamicSharedMemorySize, GP_SMEM);
    cudaFuncSetAttribute(gemm_ps<false, 0>, cudaFuncAttributeMaxDynamicSharedMemorySize, GP_SMEM);
    cudaFuncSetAttribute(stageAC, cudaFuncAttributeMaxDynamicSharedMemorySize, FU_SMEM);

    // #1..#3: splits (order keeps enc at launch #4 -> ncu capture)
    split_pad<<<(MTOK * 128 + 255) / 256, 256>>>(x, (uint16_t*)pxh, (uint16_t*)pxl,
                                                 MTOK, DIN, 128, MTOK * 128);
    split_pad<<<(HH * 128 + 255) / 256, 256>>>(enc_w, (uint16_t*)pweh, (uint16_t*)pwel,
                                               HH, DIN, 128, HH * 128);
    split_pad<<<(DMID * HH + 255) / 256, 256>>>(dec1_w, (uint16_t*)pw1h, (uint16_t*)pw1l,
                                                DMID, HH, HH, DMID * HH);

    // #4: encoder GEMM -> g_u fp32 (B,H,L)   [ncu capture target]
    gemm_ps<false, 2><<<dim3(2, 512), 256, GP_SMEM>>>(
        (const uint16_t*)pxh, (const uint16_t*)pxl,
        (const uint16_t*)pweh, (const uint16_t*)pwel,
        enc_b, (float*)pu, nullptr, nullptr,
        128, HH, 0);

    // #5, #6
    precompute_kernel<<<HH, 64>>>(log_dt, log_A_real, A_imag, B_re, B_im, C_re, C_im);
    split_pad<<<(128 * DMID + 255) / 256, 256>>>(dec2_w, (uint16_t*)pw2h, (uint16_t*)pw2l,
                                                 DOUTP, DMID, DMID, 128 * DMID);

    // #7: fused chunk-states + scan + output stage
    stageAC<<<BB * HH, 256, FU_SMEM>>>(Dskip);

    // #8: layernorm + transpose -> split planes
    layernorm_kernel<<<dim3(LL / 32, BB), 256>>>(ln_g, ln_b);

    // #9, #10: decoder MLP
    gemm_ps<true, 1><<<dim3(4, 512), 256, GP_SMEM>>>(
        (const uint16_t*)ptlh, (const uint16_t*)ptll,
        (const uint16_t*)pw1h, (const uint16_t*)pw1l,
        dec1_b, nullptr, (uint16_t*)pzh, (uint16_t*)pzl,
        HH, DMID, DMID);

    gemm_ps<false, 0><<<dim3(1, 512), 256, GP_SMEM>>>(
        (const uint16_t*)pzh, (const uint16_t*)pzl,
        (const uint16_t*)pw2h, (const uint16_t*)pw2l,
        dec2_b, out, nullptr, nullptr,
        DMID, DOUTP, DOUTP);
}

// round 12
// speedup vs baseline: 1.5334x; 1.1604x over previous
#include <cuda_runtime.h>
#include <cuda_bf16.h>
#include <cuda_fp16.h>
#include <math.h>
#include <stdint.h>

#define BB   16
#define HH   256
#define LL   4096
#define DIN  100
#define DMID 512
#define DOUTP 100
#define NST  32
#define CH   64
#define NC   64
#define MTOK (BB * LL)

// ---------------- fp32 intermediates ----------------
__device__ float g_u[BB * HH * LL];       // encoder output, (B,H,L)
__device__ float g_hres[BB * HH * LL];    // post-gelu residual, (B,H,L)
__device__ float g_wS[HH * NST * 2];      // w^64 per (h,n)

// ---------------- fp16 planes (GEMM path) ----------------
__device__ uint16_t g_xH[MTOK * 128];                         // x fp16, padded 100->128
__device__ uint16_t g_wencHh[HH * 128],  g_wencHl[HH * 128];  // enc_w fp16 hi/lo
__device__ uint16_t g_w1Hh[DMID * HH],   g_w1Hl[DMID * HH];
__device__ uint16_t g_w2Hh[128 * DMID],  g_w2Hl[128 * DMID];  // dec2_w padded rows
__device__ uint16_t g_tlnH[BB * LL * HH];                     // LN out fp16
__device__ uint16_t g_zH[MTOK * DMID];                        // MLP hidden fp16

// ---------------- bf16 split planes (S4 path, high precision) ----------------
__device__ uint16_t g_VSh[HH * 64 * 64], g_VSl[HH * 64 * 64];     // [h][s][t]
__device__ uint16_t g_CMSh[HH * 64 * 128], g_CMSl[HH * 64 * 128]; // [h][t][k]

__device__ __forceinline__ float gelu_f(float x) {
    return 0.5f * x * (1.0f + erff(x * 0.70710678118654752f));
}
__device__ __forceinline__ void splitf(float v, uint16_t& h, uint16_t& l) {
    __nv_bfloat16 bh = __float2bfloat16_rn(v);
    float hf = __bfloat162float(bh);
    __nv_bfloat16 bl = __float2bfloat16_rn(v - hf);
    h = *(uint16_t*)&bh; l = *(uint16_t*)&bl;
}
__device__ __forceinline__ void splith(float v, uint16_t& h, uint16_t& l) {
    __half hh = __float2half_rn(v);
    __half ll = __float2half_rn(v - __half2float(hh));
    h = *(uint16_t*)&hh; l = *(uint16_t*)&ll;
}
__device__ __forceinline__ void mma16816(float* c, const uint32_t* a, uint32_t b0, uint32_t b1) {
    asm volatile(
        "mma.sync.aligned.m16n8k16.row.col.f32.bf16.bf16.f32 "
        "{%0,%1,%2,%3}, {%4,%5,%6,%7}, {%8,%9}, {%0,%1,%2,%3};"
        : "+f"(c[0]), "+f"(c[1]), "+f"(c[2]), "+f"(c[3])
        : "r"(a[0]), "r"(a[1]), "r"(a[2]), "r"(a[3]), "r"(b0), "r"(b1));
}
__device__ __forceinline__ void mma16816h(float* c, const uint32_t* a, uint32_t b0, uint32_t b1) {
    asm volatile(
        "mma.sync.aligned.m16n8k16.row.col.f32.f16.f16.f32 "
        "{%0,%1,%2,%3}, {%4,%5,%6,%7}, {%8,%9}, {%0,%1,%2,%3};"
        : "+f"(c[0]), "+f"(c[1]), "+f"(c[2]), "+f"(c[3])
        : "r"(a[0]), "r"(a[1]), "r"(a[2]), "r"(a[3]), "r"(b0), "r"(b1));
}
__device__ __forceinline__ void ldsm_x4(uint32_t* r, uint32_t addr) {
    asm volatile("ldmatrix.sync.aligned.m8n8.x4.shared.b16 {%0,%1,%2,%3}, [%4];"
        : "=r"(r[0]), "=r"(r[1]), "=r"(r[2]), "=r"(r[3]) : "r"(addr));
}
__device__ __forceinline__ uint32_t smem_u32(const void* p) {
    uint32_t a;
    asm("{ .reg .u64 t; cvta.to.shared.u64 t, %1; cvt.u32.u64 %0, t; }" : "=r"(a) : "l"(p));
    return a;
}
#define CP16(dst, src) asm volatile("cp.async.cg.shared.global [%0], [%1], 16;" :: "r"(dst), "l"(src))
#define CPCOMMIT() asm volatile("cp.async.commit_group;" ::: "memory")
#define CPWAIT1() asm volatile("cp.async.wait_group 1;" ::: "memory")
#define CPWAIT0() asm volatile("cp.async.wait_group 0;" ::: "memory")

// ---------------- fp16 convert/pad kernels ----------------
__global__ void conv_pad_h(const float* __restrict__ src, uint16_t* __restrict__ d,
                           int M, int K, int Kp, int total)
{
    int i = blockIdx.x * 256 + threadIdx.x;
    if (i >= total) return;
    int r = i / Kp, c = i - r * Kp;
    float v = (r < M && c < K) ? src[(long)r * K + c] : 0.0f;
    __half hv = __float2half_rn(v);
    d[i] = *(uint16_t*)&hv;
}
__global__ void split_pad_h(const float* __restrict__ src, uint16_t* __restrict__ dh,
                            uint16_t* __restrict__ dl, int M, int K, int Kp, int total)
{
    int i = blockIdx.x * 256 + threadIdx.x;
    if (i >= total) return;
    int r = i / Kp, c = i - r * Kp;
    float v = (r < M && c < K) ? src[(long)r * K + c] : 0.0f;
    uint16_t h, l; splith(v, h, l);
    dh[i] = h; dl[i] = l;
}

// ============ fp16 tensor-core GEMM: C[M,N] = A[M,K]*B[N,K]^T + bias ============
// A: single fp16 plane; B: fp16 hi/lo split (2 MMAs). tile 128x128, BK=32.
// OM: 0 = fp32 out + Nvalid guard (dec2); 1 = fp16 out + gelu (dec1);
//     2 = transposed fp32 out (encoder -> (B,H,L))
#define SAST 40
#define PLANE_BYTES (128 * SAST * 2)   // 10240
#define HBUF_BYTES (3 * PLANE_BYTES)   // 30720
#define GH_SMEM (2 * HBUF_BYTES)       // 61440

template <bool GELU, int OM>
__global__ void __launch_bounds__(256, 2)
gemm_h(const uint16_t* __restrict__ A,
       const uint16_t* __restrict__ Bh, const uint16_t* __restrict__ Bl,
       const float* __restrict__ bias, float* __restrict__ Cf,
       uint16_t* __restrict__ Co, int K, int Nvalid, int ldc)
{
    extern __shared__ char smem[];
    uint32_t sb = smem_u32(smem);
    int tid = threadIdx.x;
    int warp = tid >> 5, lane = tid & 31;
    int warp_m = warp >> 1, warp_n = warp & 1;
    int g = lane >> 2, tg = lane & 3;
    int m0 = blockIdx.y * 128, n0 = blockIdx.x * 128;

    uint32_t a_row = (uint32_t)(lane & 15) * (SAST * 2) + ((lane & 16) ? 16u : 0u);
    uint32_t b_row = ((uint32_t)(lane & 7) + ((lane & 16) ? 8u : 0u)) * (SAST * 2)
                   + ((lane & 8) ? 16u : 0u);

    auto load_chunk = [&](int buf, int k0) {
        uint32_t base = sb + (uint32_t)buf * HBUF_BYTES;
#pragma unroll
        for (int p = 0; p < 2; p++) {
            int idx = tid + p * 256;
            int row = idx >> 2, seg = idx & 3;
            uint32_t doff = (uint32_t)(row * SAST + seg * 8) * 2;
            long ao = (long)(m0 + row) * K + k0 + seg * 8;
            long bo = (long)(n0 + row) * K + k0 + seg * 8;
            CP16(base + doff, A + ao);
            CP16(base + PLANE_BYTES + doff, Bh + bo);
            CP16(base + 2 * PLANE_BYTES + doff, Bl + bo);
        }
    };

    float acc[2][8][4];
#pragma unroll
    for (int mt = 0; mt < 2; mt++)
#pragma unroll
        for (int nt = 0; nt < 8; nt++)
#pragma unroll
            for (int q = 0; q < 4; q++) acc[mt][nt][q] = 0.0f;

    int nch = K >> 5;
    load_chunk(0, 0);
    CPCOMMIT();
    for (int c = 0; c < nch; c++) {
        if (c + 1 < nch) { load_chunk((c + 1) & 1, (c + 1) << 5); CPCOMMIT(); CPWAIT1(); }
        else CPWAIT0();
        __syncthreads();
        uint32_t bufb = sb + (uint32_t)(c & 1) * HBUF_BYTES;
        uint32_t pA = bufb, pBh = bufb + PLANE_BYTES, pBl = bufb + 2 * PLANE_BYTES;
#pragma unroll
        for (int ks = 0; ks < 2; ks++) {
            uint32_t kboff = (uint32_t)(ks * 16) * 2;
            uint32_t ah[2][4];
#pragma unroll
            for (int mt = 0; mt < 2; mt++) {
                uint32_t ro = (uint32_t)(warp_m * 32 + mt * 16) * (SAST * 2) + a_row + kboff;
                ldsm_x4(ah[mt], pA + ro);
            }
#pragma unroll
            for (int ntp = 0; ntp < 4; ntp++) {
                uint32_t nb = (uint32_t)(warp_n * 64 + ntp * 16) * (SAST * 2) + b_row + kboff;
                uint32_t bhp[4], blp[4];
                ldsm_x4(bhp, pBh + nb);
                ldsm_x4(blp, pBl + nb);
                // term-major: hi terms then lo terms (distance-4 acc chains)
#pragma unroll
                for (int sub = 0; sub < 2; sub++)
#pragma unroll
                    for (int mt = 0; mt < 2; mt++)
                        mma16816h(acc[mt][ntp * 2 + sub], ah[mt], bhp[sub * 2], bhp[sub * 2 + 1]);
#pragma unroll
                for (int sub = 0; sub < 2; sub++)
#pragma unroll
                    for (int mt = 0; mt < 2; mt++)
                        mma16816h(acc[mt][ntp * 2 + sub], ah[mt], blp[sub * 2], blp[sub * 2 + 1]);
            }
        }
        __syncthreads();
    }

    // -------- epilogue via smem stage --------
    float* stage = (float*)smem;
    for (int nh = 0; nh < 2; nh++) {
        if (warp_n == nh) {
#pragma unroll
            for (int mt = 0; mt < 2; mt++) {
#pragma unroll
                for (int nt = 0; nt < 8; nt++) {
                    int nl = nt * 8 + tg * 2;
                    int ng = n0 + nh * 64 + nl;
                    int r0 = warp_m * 32 + mt * 16 + g;
                    float b0v = (OM == 0) ? ((ng < Nvalid) ? bias[ng] : 0.0f) : bias[ng];
                    float b1v = (OM == 0) ? ((ng + 1 < Nvalid) ? bias[ng + 1] : 0.0f) : bias[ng + 1];
                    float v0 = acc[mt][nt][0] + b0v;
                    float v1 = acc[mt][nt][1] + b1v;
                    float v2 = acc[mt][nt][2] + b0v;
                    float v3 = acc[mt][nt][3] + b1v;
                    if (GELU) { v0 = gelu_f(v0); v1 = gelu_f(v1); v2 = gelu_f(v2); v3 = gelu_f(v3); }
                    if (OM == 2) {
                        stage[nl * 132 + r0] = v0;
                        stage[(nl + 1) * 132 + r0] = v1;
                        stage[nl * 132 + r0 + 8] = v2;
                        stage[(nl + 1) * 132 + r0 + 8] = v3;
                    } else {
                        stage[r0 * 68 + nl] = v0;
                        stage[r0 * 68 + nl + 1] = v1;
                        stage[(r0 + 8) * 68 + nl] = v2;
                        stage[(r0 + 8) * 68 + nl + 1] = v3;
                    }
                }
            }
        }
        __syncthreads();
        if (OM == 2) {
            int bidx = m0 >> 12;
            int l0 = m0 & 4095;
#pragma unroll
            for (int p = 0; p < 8; p++) {
                int nl = p * 8 + warp;
                int m4 = lane * 4;
                float4 v = *(float4*)&stage[nl * 132 + m4];
                int ng = n0 + nh * 64 + nl;
                long base = ((long)((bidx << 8) + ng)) * 4096 + l0 + m4;
                *(float4*)&Cf[base] = v;
            }
        } else if (OM == 1) {
#pragma unroll
            for (int p = 0; p < 8; p++) {
                int idx = tid + p * 256;
                int r = idx >> 4;
                int c4 = (idx & 15) * 4;
                int n = n0 + nh * 64 + c4;
                float4 v = *(float4*)&stage[r * 68 + c4];
                long base = (long)(m0 + r) * ldc + n;
                __half z0 = __float2half_rn(v.x), z1 = __float2half_rn(v.y);
                __half z2 = __float2half_rn(v.z), z3 = __float2half_rn(v.w);
                uint64_t pk = (uint64_t)*(uint16_t*)&z0 | ((uint64_t)*(uint16_t*)&z1 << 16)
                            | ((uint64_t)*(uint16_t*)&z2 << 32) | ((uint64_t)*(uint16_t*)&z3 << 48);
                *(uint64_t*)&Co[base] = pk;
            }
        } else {
#pragma unroll
            for (int p = 0; p < 8; p++) {
                int idx = tid + p * 256;
                int r = idx >> 4;
                int c4 = (idx & 15) * 4;
                int n = n0 + nh * 64 + c4;
                if (n < Nvalid) {
                    float4 v = *(float4*)&stage[r * 68 + c4];
                    *(float4*)&Cf[(long)(m0 + r) * ldc + n] = v;
                }
            }
        }
        __syncthreads();
    }
}

// ---------------- precompute per-head matrices (bf16 split output) ----------------
__global__ void precompute_kernel(const float* __restrict__ log_dt,
                                  const float* __restrict__ log_A_real,
                                  const float* __restrict__ A_imag,
                                  const float* __restrict__ B_re,
                                  const float* __restrict__ B_im,
                                  const float* __restrict__ C_re,
                                  const float* __restrict__ C_im)
{
    int h = blockIdx.x;
    int t = threadIdx.x;   // 0..63
    __shared__ float s_dtr[NST], s_dti[NST], s_c2r[NST], s_c2i[NST];
    __shared__ float s_k[CH];

    float dt = expf(log_dt[h]);
    if (t < NST) {
        int n = t;
        float Ar = -expf(log_A_real[h * NST + n]);
        float Ai = A_imag[h * NST + n];
        float dtr = dt * Ar, dti = dt * Ai;
        float er = expf(dtr);
        float Er = er * cosf(dti) - 1.0f;
        float Ei = er * sinf(dti);
        float br = B_re[h * NST + n], bi = B_im[h * NST + n];
        float cr = C_re[h * NST + n], ci = C_im[h * NST + n];
        float BCr = br * cr - bi * ci;
        float BCi = br * ci + bi * cr;
        float numr = BCr * Er - BCi * Ei;
        float numi = BCr * Ei + BCi * Er;
        float den = Ar * Ar + Ai * Ai;
        float cpr = (numr * Ar + numi * Ai) / den;
        float cpi = (numi * Ar - numr * Ai) / den;
        s_c2r[n] = 2.0f * cpr;
        s_c2i[n] = 2.0f * cpi;
        s_dtr[n] = dtr;
        s_dti[n] = dti;
        float e64 = expf(64.0f * dtr);
        g_wS[(h * NST + n) * 2 + 0] = e64 * cosf(64.0f * dti);
        g_wS[(h * NST + n) * 2 + 1] = e64 * sinf(64.0f * dti);
    }
    __syncthreads();

    float kt = 0.0f;
    for (int n = 0; n < NST; n++) {
        float dtr = s_dtr[n], dti = s_dti[n];
        float c2r = s_c2r[n], c2i = s_c2i[n];
        float p = (float)(63 - t);
        float ep = expf(p * dtr);
        float vr = ep * cosf(p * dti), vi = ep * sinf(p * dti);
        uint16_t hh, ll;
        splitf(vr, hh, ll);
        g_VSh[h * 4096 + (2 * n) * 64 + t] = hh; g_VSl[h * 4096 + (2 * n) * 64 + t] = ll;
        splitf(vi, hh, ll);
        g_VSh[h * 4096 + (2 * n + 1) * 64 + t] = hh; g_VSl[h * 4096 + (2 * n + 1) * 64 + t] = ll;
        float pt = (float)t;
        float et = expf(pt * dtr);
        float wr = et * cosf(pt * dti), wi = et * sinf(pt * dti);
        kt += c2r * wr - c2i * wi;
        float p1 = (float)(t + 1);
        float e1 = expf(p1 * dtr);
        float w1r = e1 * cosf(p1 * dti), w1i = e1 * sinf(p1 * dti);
        float gr = c2r * w1r - c2i * w1i;
        float gi = -(c2r * w1i + c2i * w1r);
        splitf(gr, hh, ll);
        g_CMSh[h * 8192 + t * 128 + 64 + 2 * n] = hh; g_CMSl[h * 8192 + t * 128 + 64 + 2 * n] = ll;
        splitf(gi, hh, ll);
        g_CMSh[h * 8192 + t * 128 + 64 + 2 * n + 1] = hh; g_CMSl[h * 8192 + t * 128 + 64 + 2 * n + 1] = ll;
    }
    s_k[t] = kt;
    __syncthreads();
    for (int j = 0; j < CH; j++) {
        float val = (j <= t) ? s_k[t - j] : 0.0f;
        uint16_t hh, ll; splitf(val, hh, ll);
        g_CMSh[h * 8192 + t * 128 + j] = hh;
        g_CMSl[h * 8192 + t * 128 + j] = ll;
    }
}

// ================= fused stageA + scan + stageC (bf16 3-term, unchanged) =================
#define FU_UH 0
#define FU_UL 9216
#define FU_W  18432
#define FU_VH FU_W
#define FU_VL (FU_W + 9216)
#define FU_CH FU_W
#define FU_CL (FU_W + 17408)
#define FU_E  53248
#define FU_PH 70144
#define FU_PL 79360
#define FU_SMEM 88576

__global__ void __launch_bounds__(256, 2) stageAC(const float* __restrict__ Dskip)
{
    extern __shared__ char sm[];
    uint16_t* sUh = (uint16_t*)(sm + FU_UH);
    uint16_t* sUl = (uint16_t*)(sm + FU_UL);
    uint16_t* sVh = (uint16_t*)(sm + FU_VH);
    uint16_t* sVl = (uint16_t*)(sm + FU_VL);
    uint16_t* sCh = (uint16_t*)(sm + FU_CH);
    uint16_t* sCl = (uint16_t*)(sm + FU_CL);
    float*    sE  = (float*)(sm + FU_E);
    uint16_t* sPh = (uint16_t*)(sm + FU_PH);
    uint16_t* sPl = (uint16_t*)(sm + FU_PL);
    float*    sTf   = (float*)(sm + FU_PH);
    float*    sPref = (float*)(sm + FU_PL);

    uint32_t pUh = smem_u32(sUh), pUl = smem_u32(sUl);
    uint32_t pVh = smem_u32(sVh), pVl = smem_u32(sVl);
    uint32_t pCh = smem_u32(sCh), pCl = smem_u32(sCl);
    uint32_t pPh = smem_u32(sPh), pPl = smem_u32(sPl);

    int bh = blockIdx.x, h = bh & (HH - 1);
    int tid = threadIdx.x, warp = tid >> 5, lane = tid & 31;
    int warp_m = warp >> 1, warp_n = warp & 1;
    int g = lane >> 2, tg = lane & 3;
    const float* up = g_u + (long)bh * LL;

    uint32_t a_row72 = (uint32_t)(lane & 15) * 144 + ((lane & 16) ? 16u : 0u);
    uint32_t b_row72 = ((uint32_t)(lane & 7) + ((lane & 16) ? 8u : 0u)) * 144 + ((lane & 8) ? 16u : 0u);
    uint32_t b_row136 = ((uint32_t)(lane & 7) + ((lane & 16) ? 8u : 0u)) * 272 + ((lane & 8) ? 16u : 0u);

    {
        const uint16_t* vh = g_VSh + h * 4096;
        const uint16_t* vl = g_VSl + h * 4096;
#pragma unroll
        for (int p = 0; p < 4; p++) {
            int i = tid + p * 256;
            int e = i * 4, row = e >> 6, col = e & 63;
            float4 v = *(const float4*)(up + e);
            uint16_t h0, l0, h1, l1, h2, l2, h3, l3;
            splitf(v.x, h0, l0); splitf(v.y, h1, l1);
            splitf(v.z, h2, l2); splitf(v.w, h3, l3);
            *(uint2*)&sUh[row * 72 + col] = make_uint2((uint32_t)h0 | ((uint32_t)h1 << 16),
                                                       (uint32_t)h2 | ((uint32_t)h3 << 16));
            *(uint2*)&sUl[row * 72 + col] = make_uint2((uint32_t)l0 | ((uint32_t)l1 << 16),
                                                       (uint32_t)l2 | ((uint32_t)l3 << 16));
        }
#pragma unroll
        for (int p = 0; p < 2; p++) {
            int i = tid + p * 256;
            int row = i >> 3, seg = i & 7;
            *(uint4*)&sVh[row * 72 + seg * 8] = *(const uint4*)&vh[row * 64 + seg * 8];
            *(uint4*)&sVl[row * 72 + seg * 8] = *(const uint4*)&vl[row * 64 + seg * 8];
        }
    }
    __syncthreads();

    {
        float acc[4][4];
#pragma unroll
        for (int nt = 0; nt < 4; nt++)
#pragma unroll
            for (int q = 0; q < 4; q++) acc[nt][q] = 0.0f;
        int ra = warp_m * 16;
#pragma unroll
        for (int ks = 0; ks < 4; ks++) {
            uint32_t kboff = (uint32_t)(ks * 16) * 2;
            uint32_t ah[4], al[4];
            uint32_t ro = (uint32_t)ra * 144 + a_row72 + kboff;
            ldsm_x4(ah, pUh + ro);
            ldsm_x4(al, pUl + ro);
            uint32_t bhp[2][4], blp[2][4];
#pragma unroll
            for (int ntp = 0; ntp < 2; ntp++) {
                uint32_t nb = (uint32_t)(warp_n * 32 + ntp * 16) * 144 + b_row72 + kboff;
                ldsm_x4(bhp[ntp], pVh + nb);
                ldsm_x4(blp[ntp], pVl + nb);
            }
#pragma unroll
            for (int ntp = 0; ntp < 2; ntp++)
#pragma unroll
                for (int sub = 0; sub < 2; sub++)
                    mma16816(acc[ntp * 2 + sub], ah, bhp[ntp][sub * 2], bhp[ntp][sub * 2 + 1]);
#pragma unroll
            for (int ntp = 0; ntp < 2; ntp++)
#pragma unroll
                for (int sub = 0; sub < 2; sub++)
                    mma16816(acc[ntp * 2 + sub], ah, blp[ntp][sub * 2], blp[ntp][sub * 2 + 1]);
#pragma unroll
            for (int ntp = 0; ntp < 2; ntp++)
#pragma unroll
                for (int sub = 0; sub < 2; sub++)
                    mma16816(acc[ntp * 2 + sub], al, bhp[ntp][sub * 2], bhp[ntp][sub * 2 + 1]);
        }
        int ra2 = warp_m * 16;
#pragma unroll
        for (int nt = 0; nt < 4; nt++) {
            int s = warp_n * 32 + nt * 8 + tg * 2;
            sE[(ra2 + g) * 66 + s] = acc[nt][0];
            sE[(ra2 + g) * 66 + s + 1] = acc[nt][1];
            sE[(ra2 + g + 8) * 66 + s] = acc[nt][2];
            sE[(ra2 + g + 8) * 66 + s + 1] = acc[nt][3];
        }
    }
    __syncthreads();

    {
        const uint16_t* ch = g_CMSh + h * 8192;
        const uint16_t* cl = g_CMSl + h * 8192;
#pragma unroll
        for (int p = 0; p < 4; p++) {
            int i = tid + p * 256;
            int row = i >> 4, seg = i & 15;
            *(uint4*)&sCh[row * 136 + seg * 8] = *(const uint4*)&ch[row * 128 + seg * 8];
            *(uint4*)&sCl[row * 136 + seg * 8] = *(const uint4*)&cl[row * 128 + seg * 8];
        }
    }

    int segi = tid >> 5;
    int n = tid & 31;
    float wr = g_wS[(h * NST + n) * 2 + 0];
    float wi = g_wS[(h * NST + n) * 2 + 1];
    {
        float sr = 0.0f, si = 0.0f;
#pragma unroll
        for (int j = 0; j < 8; j++) {
            int c = segi * 8 + j;
            float er = sE[c * 66 + 2 * n], ei = sE[c * 66 + 2 * n + 1];
            float nsr = wr * sr - wi * si + er;
            si = wr * si + wi * sr + ei;
            sr = nsr;
        }
        sTf[segi * 64 + 2 * n] = sr;
        sTf[segi * 64 + 2 * n + 1] = si;
    }
    __syncthreads();
    if (tid < 32) {
        float w2r = wr * wr - wi * wi, w2i = 2.0f * wr * wi;
        float w4r = w2r * w2r - w2i * w2i, w4i = 2.0f * w2r * w2i;
        float w8r = w4r * w4r - w4i * w4i, w8i = 2.0f * w4r * w4i;
        float pr = 0.0f, pi = 0.0f;
#pragma unroll
        for (int s = 0; s < 8; s++) {
            sPref[s * 64 + 2 * n] = pr;
            sPref[s * 64 + 2 * n + 1] = pi;
            float tr = sTf[s * 64 + 2 * n], ti = sTf[s * 64 + 2 * n + 1];
            float npr = w8r * pr - w8i * pi + tr;
            pi = w8r * pi + w8i * pr + ti;
            pr = npr;
        }
    }
    __syncthreads();
    {
        float pr = sPref[segi * 64 + 2 * n];
        float pi = sPref[segi * 64 + 2 * n + 1];
        __syncthreads();
#pragma unroll
        for (int j = 0; j < 8; j++) {
            int c = segi * 8 + j;
            uint16_t hr, lr, hi2, li2;
            splitf(pr, hr, lr);
            splitf(pi, hi2, li2);
            sPh[c * 72 + 2 * n] = hr;  sPh[c * 72 + 2 * n + 1] = hi2;
            sPl[c * 72 + 2 * n] = lr;  sPl[c * 72 + 2 * n + 1] = li2;
            float er = sE[c * 66 + 2 * n], ei = sE[c * 66 + 2 * n + 1];
            float npr = wr * pr - wi * pi + er;
            pi = wr * pi + wi * pr + ei;
            pr = npr;
        }
    }
    __syncthreads();

    {
        float acc[4][4];
#pragma unroll
        for (int nt = 0; nt < 4; nt++)
#pragma unroll
            for (int q = 0; q < 4; q++) acc[nt][q] = 0.0f;
        int ra = warp_m * 16;
#pragma unroll
        for (int ks = 0; ks < 8; ks++) {
            uint32_t aH = (ks < 4) ? pUh : pPh;
            uint32_t aL = (ks < 4) ? pUl : pPl;
            uint32_t kloc = (uint32_t)((ks & 3) * 16) * 2;
            uint32_t ah[4], al[4];
            uint32_t ro = (uint32_t)ra * 144 + a_row72 + kloc;
            ldsm_x4(ah, aH + ro);
            ldsm_x4(al, aL + ro);
            uint32_t kb136 = (uint32_t)(ks * 16) * 2;
            uint32_t bhp[2][4], blp[2][4];
#pragma unroll
            for (int ntp = 0; ntp < 2; ntp++) {
                uint32_t nb = (uint32_t)(warp_n * 32 + ntp * 16) * 272 + b_row136 + kb136;
                ldsm_x4(bhp[ntp], pCh + nb);
                ldsm_x4(blp[ntp], pCl + nb);
            }
#pragma unroll
            for (int ntp = 0; ntp < 2; ntp++)
#pragma unroll
                for (int sub = 0; sub < 2; sub++)
                    mma16816(acc[ntp * 2 + sub], ah, bhp[ntp][sub * 2], bhp[ntp][sub * 2 + 1]);
#pragma unroll
            for (int ntp = 0; ntp < 2; ntp++)
#pragma unroll
                for (int sub = 0; sub < 2; sub++)
                    mma16816(acc[ntp * 2 + sub], ah, blp[ntp][sub * 2], blp[ntp][sub * 2 + 1]);
#pragma unroll
            for (int ntp = 0; ntp < 2; ntp++)
#pragma unroll
                for (int sub = 0; sub < 2; sub++)
                    mma16816(acc[ntp * 2 + sub], al, bhp[ntp][sub * 2], bhp[ntp][sub * 2 + 1]);
        }

        float dsk = Dskip[h];
        float* hp = g_hres + (long)bh * LL;
        int ra2 = warp_m * 16;
#pragma unroll
        for (int nt = 0; nt < 4; nt++) {
            int t = warp_n * 32 + nt * 8 + tg * 2;
            float u00 = __bfloat162float(*(__nv_bfloat16*)&sUh[(ra2 + g) * 72 + t])
                      + __bfloat162float(*(__nv_bfloat16*)&sUl[(ra2 + g) * 72 + t]);
            float u01 = __bfloat162float(*(__nv_bfloat16*)&sUh[(ra2 + g) * 72 + t + 1])
                      + __bfloat162float(*(__nv_bfloat16*)&sUl[(ra2 + g) * 72 + t + 1]);
            float u10 = __bfloat162float(*(__nv_bfloat16*)&sUh[(ra2 + g + 8) * 72 + t])
                      + __bfloat162float(*(__nv_bfloat16*)&sUl[(ra2 + g + 8) * 72 + t]);
            float u11 = __bfloat162float(*(__nv_bfloat16*)&sUh[(ra2 + g + 8) * 72 + t + 1])
                      + __bfloat162float(*(__nv_bfloat16*)&sUl[(ra2 + g + 8) * 72 + t + 1]);
            float y0 = gelu_f(acc[nt][0] + dsk * u00) + u00;
            float y1 = gelu_f(acc[nt][1] + dsk * u01) + u01;
            float y2 = gelu_f(acc[nt][2] + dsk * u10) + u10;
            float y3 = gelu_f(acc[nt][3] + dsk * u11) + u11;
            *(float2*)&hp[(ra2 + g) * 64 + t] = make_float2(y0, y1);
            *(float2*)&hp[(ra2 + g + 8) * 64 + t] = make_float2(y2, y3);
        }
    }
}

// ---------------- layernorm + transpose (B,H,L) -> (B,L,H), fp16 output ----------------
__global__ void __launch_bounds__(256, 1) layernorm_kernel(const float* __restrict__ ln_g,
                                                           const float* __restrict__ ln_b)
{
    int b = blockIdx.y;
    int l0 = blockIdx.x * 32;
    __shared__ float tile[256][33];
    int tid = threadIdx.x;
    int w = tid >> 5, lane = tid & 31;
    const float* hp = g_hres + (long)b * HH * LL;
    for (int hh = w; hh < 256; hh += 8) {
        tile[hh][lane] = hp[(long)hh * LL + l0 + lane];
    }
    __syncthreads();
    uint16_t* op = g_tlnH + ((long)b * LL + l0) * HH;
#pragma unroll
    for (int q = 0; q < 4; q++) {
        int tok = w * 4 + q;
        float s = 0.0f, sq = 0.0f;
#pragma unroll
        for (int j = 0; j < 8; j++) {
            float v = tile[lane + 32 * j][tok];
            s += v;
            sq += v * v;
        }
#pragma unroll
        for (int o = 16; o > 0; o >>= 1) {
            s += __shfl_xor_sync(0xffffffffu, s, o);
            sq += __shfl_xor_sync(0xffffffffu, sq, o);
        }
        float mean = s * (1.0f / 256.0f);
        float var = sq * (1.0f / 256.0f) - mean * mean;
        float rstd = rsqrtf(var + 1e-5f);
#pragma unroll
        for (int j = 0; j < 8; j++) {
            int hh = lane + 32 * j;
            float v = (tile[hh][tok] - mean) * rstd * ln_g[hh] + ln_b[hh];
            __half hv = __float2half_rn(v);
            op[(long)tok * HH + hh] = *(uint16_t*)&hv;
        }
    }
}

// ---------------- launcher ----------------
extern "C" void kernel_launch(void* const* d_in, const int* in_sizes, int n_in,
                              void* d_out, int out_size)
{
    const float* x          = (const float*)d_in[0];
    const float* enc_w      = (const float*)d_in[1];
    const float* enc_b      = (const float*)d_in[2];
    const float* log_dt     = (const float*)d_in[3];
    const float* log_A_real = (const float*)d_in[4];
    const float* A_imag     = (const float*)d_in[5];
    const float* B_re       = (const float*)d_in[6];
    const float* B_im       = (const float*)d_in[7];
    const float* C_re       = (const float*)d_in[8];
    const float* C_im       = (const float*)d_in[9];
    const float* Dskip      = (const float*)d_in[10];
    const float* ln_g       = (const float*)d_in[11];
    const float* ln_b       = (const float*)d_in[12];
    const float* dec1_w     = (const float*)d_in[13];
    const float* dec1_b     = (const float*)d_in[14];
    const float* dec2_w     = (const float*)d_in[15];
    const float* dec2_b     = (const float*)d_in[16];
    float* out = (float*)d_out;

    void *pu = 0;
    void *pxh = 0, *pweh = 0, *pwel = 0, *pw1h = 0, *pw1l = 0, *pw2h = 0, *pw2l = 0;
    void *ptl = 0, *pz = 0;
    cudaGetSymbolAddress(&pu, g_u);
    cudaGetSymbolAddress(&pxh, g_xH);
    cudaGetSymbolAddress(&pweh, g_wencHh); cudaGetSymbolAddress(&pwel, g_wencHl);
    cudaGetSymbolAddress(&pw1h, g_w1Hh);   cudaGetSymbolAddress(&pw1l, g_w1Hl);
    cudaGetSymbolAddress(&pw2h, g_w2Hh);   cudaGetSymbolAddress(&pw2l, g_w2Hl);
    cudaGetSymbolAddress(&ptl, g_tlnH);    cudaGetSymbolAddress(&pz, g_zH);

    cudaFuncSetAttribute(gemm_h<false, 2>, cudaFuncAttributeMaxDynamicSharedMemorySize, GH_SMEM);
    cudaFuncSetAttribute(gemm_h<true, 1>,  cudaFuncAttributeMaxDynamicSharedMemorySize, GH_SMEM);
    cudaFuncSetAttribute(gemm_h<false, 0>, cudaFuncAttributeMaxDynamicSharedMemorySize, GH_SMEM);
    cudaFuncSetAttribute(stageAC, cudaFuncAttributeMaxDynamicSharedMemorySize, FU_SMEM);

    // #1..#3 (keeps enc at launch #4 for ncu capture)
    conv_pad_h<<<(MTOK * 128 + 255) / 256, 256>>>(x, (uint16_t*)pxh, MTOK, DIN, 128, MTOK * 128);
    split_pad_h<<<(HH * 128 + 255) / 256, 256>>>(enc_w, (uint16_t*)pweh, (uint16_t*)pwel,
                                                 HH, DIN, 128, HH * 128);
    split_pad_h<<<(DMID * HH + 255) / 256, 256>>>(dec1_w, (uint16_t*)pw1h, (uint16_t*)pw1l,
                                                  DMID, HH, HH, DMID * HH);

    // #4: encoder GEMM -> g_u fp32 (B,H,L)   [ncu capture target]
    gemm_h<false, 2><<<dim3(2, 512), 256, GH_SMEM>>>(
        (const uint16_t*)pxh, (const uint16_t*)pweh, (const uint16_t*)pwel,
        enc_b, (float*)pu, nullptr, 128, HH, 0);

    // #5, #6
    precompute_kernel<<<HH, 64>>>(log_dt, log_A_real, A_imag, B_re, B_im, C_re, C_im);
    split_pad_h<<<(128 * DMID + 255) / 256, 256>>>(dec2_w, (uint16_t*)pw2h, (uint16_t*)pw2l,
                                                   DOUTP, DMID, DMID, 128 * DMID);

    // #7: fused chunk-states + scan + output stage (bf16 precision path)
    stageAC<<<BB * HH, 256, FU_SMEM>>>(Dskip);

    // #8: layernorm + transpose -> fp16 plane
    layernorm_kernel<<<dim3(LL / 32, BB), 256>>>(ln_g, ln_b);

    // #9, #10: decoder MLP (fp16 2-term)
    gemm_h<true, 1><<<dim3(4, 512), 256, GH_SMEM>>>(
        (const uint16_t*)ptl, (const uint16_t*)pw1h, (const uint16_t*)pw1l,
        dec1_b, nullptr, (uint16_t*)pz, HH, DMID, DMID);

    gemm_h<false, 0><<<dim3(1, 512), 256, GH_SMEM>>>(
        (const uint16_t*)pz, (const uint16_t*)pw2h, (const uint16_t*)pw2l,
        dec2_b, out, nullptr, DMID, DOUTP, DOUTP);
}

// round 13
// speedup vs baseline: 1.6042x; 1.0461x over previous
#include <cuda_runtime.h>
#include <cuda_bf16.h>
#include <cuda_fp16.h>
#include <math.h>
#include <stdint.h>

#define BB   16
#define HH   256
#define LL   4096
#define DIN  100
#define DMID 512
#define DOUTP 100
#define NST  32
#define CH   64
#define NC   64
#define MTOK (BB * LL)

// ---------------- fp32 intermediates ----------------
__device__ float g_u[BB * HH * LL];       // encoder output, (B,H,L)
__device__ float g_hres[BB * HH * LL];    // post-gelu residual, (B,H,L)
__device__ float g_wS[HH * NST * 2];      // w^64 per (h,n)

// ---------------- fp16 planes (GEMM path) ----------------
__device__ uint16_t g_xH[MTOK * 128];                         // x fp16, padded 100->128
__device__ uint16_t g_wencHh[HH * 128],  g_wencHl[HH * 128];  // enc_w fp16 hi/lo
__device__ uint16_t g_w1Hh[DMID * HH],   g_w1Hl[DMID * HH];
__device__ uint16_t g_w2Hh[128 * DMID],  g_w2Hl[128 * DMID];  // dec2_w padded rows
__device__ uint16_t g_tlnH[BB * LL * HH];                     // LN out fp16
__device__ uint16_t g_zH[MTOK * DMID];                        // MLP hidden fp16

// ---------------- bf16 split planes (S4 path, high precision) ----------------
__device__ uint16_t g_VSh[HH * 64 * 64], g_VSl[HH * 64 * 64];     // [h][s][t]
__device__ uint16_t g_CMSh[HH * 64 * 128], g_CMSl[HH * 64 * 128]; // [h][t][k]

__device__ __forceinline__ float gelu_f(float x) {
    return 0.5f * x * (1.0f + erff(x * 0.70710678118654752f));
}
__device__ __forceinline__ void splitf(float v, uint16_t& h, uint16_t& l) {
    __nv_bfloat16 bh = __float2bfloat16_rn(v);
    float hf = __bfloat162float(bh);
    __nv_bfloat16 bl = __float2bfloat16_rn(v - hf);
    h = *(uint16_t*)&bh; l = *(uint16_t*)&bl;
}
__device__ __forceinline__ void splith(float v, uint16_t& h, uint16_t& l) {
    __half hh = __float2half_rn(v);
    __half ll = __float2half_rn(v - __half2float(hh));
    h = *(uint16_t*)&hh; l = *(uint16_t*)&ll;
}
__device__ __forceinline__ void mma16816(float* c, const uint32_t* a, uint32_t b0, uint32_t b1) {
    asm volatile(
        "mma.sync.aligned.m16n8k16.row.col.f32.bf16.bf16.f32 "
        "{%0,%1,%2,%3}, {%4,%5,%6,%7}, {%8,%9}, {%0,%1,%2,%3};"
        : "+f"(c[0]), "+f"(c[1]), "+f"(c[2]), "+f"(c[3])
        : "r"(a[0]), "r"(a[1]), "r"(a[2]), "r"(a[3]), "r"(b0), "r"(b1));
}
__device__ __forceinline__ void mma16816h(float* c, const uint32_t* a, uint32_t b0, uint32_t b1) {
    asm volatile(
        "mma.sync.aligned.m16n8k16.row.col.f32.f16.f16.f32 "
        "{%0,%1,%2,%3}, {%4,%5,%6,%7}, {%8,%9}, {%0,%1,%2,%3};"
        : "+f"(c[0]), "+f"(c[1]), "+f"(c[2]), "+f"(c[3])
        : "r"(a[0]), "r"(a[1]), "r"(a[2]), "r"(a[3]), "r"(b0), "r"(b1));
}
__device__ __forceinline__ void ldsm_x4(uint32_t* r, uint32_t addr) {
    asm volatile("ldmatrix.sync.aligned.m8n8.x4.shared.b16 {%0,%1,%2,%3}, [%4];"
        : "=r"(r[0]), "=r"(r[1]), "=r"(r[2]), "=r"(r[3]) : "r"(addr));
}
__device__ __forceinline__ uint32_t smem_u32(const void* p) {
    uint32_t a;
    asm("{ .reg .u64 t; cvta.to.shared.u64 t, %1; cvt.u32.u64 %0, t; }" : "=r"(a) : "l"(p));
    return a;
}
#define CP16(dst, src) asm volatile("cp.async.cg.shared.global [%0], [%1], 16;" :: "r"(dst), "l"(src))
#define CPCOMMIT() asm volatile("cp.async.commit_group;" ::: "memory")
#define CPWAIT1() asm volatile("cp.async.wait_group 1;" ::: "memory")
#define CPWAIT0() asm volatile("cp.async.wait_group 0;" ::: "memory")

// ---------------- fp16 convert/pad kernels ----------------
__global__ void conv_pad_h(const float* __restrict__ src, uint16_t* __restrict__ d,
                           int M, int K, int Kp, int total)
{
    int i = blockIdx.x * 256 + threadIdx.x;
    if (i >= total) return;
    int r = i / Kp, c = i - r * Kp;
    float v = (r < M && c < K) ? src[(long)r * K + c] : 0.0f;
    __half hv = __float2half_rn(v);
    d[i] = *(uint16_t*)&hv;
}
__global__ void split_pad_h(const float* __restrict__ src, uint16_t* __restrict__ dh,
                            uint16_t* __restrict__ dl, int M, int K, int Kp, int total)
{
    int i = blockIdx.x * 256 + threadIdx.x;
    if (i >= total) return;
    int r = i / Kp, c = i - r * Kp;
    float v = (r < M && c < K) ? src[(long)r * K + c] : 0.0f;
    uint16_t h, l; splith(v, h, l);
    dh[i] = h; dl[i] = l;
}

// ============ fp16 tensor-core GEMM: C[M,N] = A[M,K]*B[N,K]^T + bias ============
// A: single fp16 plane; B: fp16 hi/lo split (2 MMAs). tile 128x128, BK=64,
// double-buffered cp.async + in-loop B-fragment prefetch.
#define SAST 72                         // halfwords per smem row (64 + 8 pad)
#define PLANE_BYTES (128 * SAST * 2)    // 18432
#define HBUF_BYTES (3 * PLANE_BYTES)    // 55296
#define GH_SMEM (2 * HBUF_BYTES)        // 110592

template <bool GELU, int OM>
__global__ void __launch_bounds__(256, 2)
gemm_h(const uint16_t* __restrict__ A,
       const uint16_t* __restrict__ Bh, const uint16_t* __restrict__ Bl,
       const float* __restrict__ bias, float* __restrict__ Cf,
       uint16_t* __restrict__ Co, int K, int Nvalid, int ldc)
{
    extern __shared__ char smem[];
    uint32_t sb = smem_u32(smem);
    int tid = threadIdx.x;
    int warp = tid >> 5, lane = tid & 31;
    int warp_m = warp >> 1, warp_n = warp & 1;
    int g = lane >> 2, tg = lane & 3;
    int m0 = blockIdx.y * 128, n0 = blockIdx.x * 128;

    uint32_t a_row = (uint32_t)(lane & 15) * (SAST * 2) + ((lane & 16) ? 16u : 0u);
    uint32_t b_row = ((uint32_t)(lane & 7) + ((lane & 16) ? 8u : 0u)) * (SAST * 2)
                   + ((lane & 8) ? 16u : 0u);

    // chunk = 64 K-values. 3 planes x 128 rows x 8 segs of 16B = 3072 cp.async / 256 thr = 12 each
    auto load_chunk = [&](int buf, int k0) {
        uint32_t base = sb + (uint32_t)buf * HBUF_BYTES;
#pragma unroll
        for (int p = 0; p < 12; p++) {
            int idx = tid + p * 256;
            int pl = idx >> 10;
            int rem = idx & 1023;
            int row = rem >> 3, seg = rem & 7;
            uint32_t doff = (uint32_t)pl * PLANE_BYTES + (uint32_t)(row * SAST + seg * 8) * 2;
            const uint16_t* src = (pl == 0) ? (A + (long)(m0 + row) * K + k0 + seg * 8)
                                : (pl == 1) ? (Bh + (long)(n0 + row) * K + k0 + seg * 8)
                                            : (Bl + (long)(n0 + row) * K + k0 + seg * 8);
            CP16(base + doff, src);
        }
    };

    float acc[2][8][4];
#pragma unroll
    for (int mt = 0; mt < 2; mt++)
#pragma unroll
        for (int nt = 0; nt < 8; nt++)
#pragma unroll
            for (int q = 0; q < 4; q++) acc[mt][nt][q] = 0.0f;

    int nch = K >> 6;
    load_chunk(0, 0);
    CPCOMMIT();
    for (int c = 0; c < nch; c++) {
        if (c + 1 < nch) { load_chunk((c + 1) & 1, (c + 1) << 6); CPCOMMIT(); CPWAIT1(); }
        else CPWAIT0();
        __syncthreads();
        uint32_t bufb = sb + (uint32_t)(c & 1) * HBUF_BYTES;
        uint32_t pA = bufb, pBh = bufb + PLANE_BYTES, pBl = bufb + 2 * PLANE_BYTES;
#pragma unroll
        for (int ks = 0; ks < 4; ks++) {
            uint32_t kboff = (uint32_t)(ks * 16) * 2;
            uint32_t ah[2][4];
#pragma unroll
            for (int mt = 0; mt < 2; mt++) {
                uint32_t ro = (uint32_t)(warp_m * 32 + mt * 16) * (SAST * 2) + a_row + kboff;
                ldsm_x4(ah[mt], pA + ro);
            }
            uint32_t bhA[4], blA[4], bhB[4], blB[4];
            {
                uint32_t nb0 = (uint32_t)(warp_n * 64) * (SAST * 2) + b_row + kboff;
                ldsm_x4(bhA, pBh + nb0);
                ldsm_x4(blA, pBl + nb0);
            }
#define NTP_BODY(CURH, CURL, NXTH, NXTL, NTP)                                         \
            {                                                                          \
                if ((NTP) < 3) {                                                       \
                    uint32_t nbn = (uint32_t)(warp_n * 64 + ((NTP) + 1) * 16) * (SAST * 2) \
                                 + b_row + kboff;                                      \
                    ldsm_x4(NXTH, pBh + nbn);                                          \
                    ldsm_x4(NXTL, pBl + nbn);                                          \
                }                                                                      \
                _Pragma("unroll")                                                      \
                for (int sub = 0; sub < 2; sub++)                                      \
                    _Pragma("unroll")                                                  \
                    for (int mt = 0; mt < 2; mt++)                                     \
                        mma16816h(acc[mt][(NTP) * 2 + sub], ah[mt],                    \
                                  CURH[sub * 2], CURH[sub * 2 + 1]);                   \
                _Pragma("unroll")                                                      \
                for (int sub = 0; sub < 2; sub++)                                      \
                    _Pragma("unroll")                                                  \
                    for (int mt = 0; mt < 2; mt++)                                     \
                        mma16816h(acc[mt][(NTP) * 2 + sub], ah[mt],                    \
                                  CURL[sub * 2], CURL[sub * 2 + 1]);                   \
            }
            NTP_BODY(bhA, blA, bhB, blB, 0)
            NTP_BODY(bhB, blB, bhA, blA, 1)
            NTP_BODY(bhA, blA, bhB, blB, 2)
            NTP_BODY(bhB, blB, bhA, blA, 3)
#undef NTP_BODY
        }
        __syncthreads();
    }

    // -------- epilogue via smem stage --------
    float* stage = (float*)smem;
    for (int nh = 0; nh < 2; nh++) {
        if (warp_n == nh) {
#pragma unroll
            for (int mt = 0; mt < 2; mt++) {
#pragma unroll
                for (int nt = 0; nt < 8; nt++) {
                    int nl = nt * 8 + tg * 2;
                    int ng = n0 + nh * 64 + nl;
                    int r0 = warp_m * 32 + mt * 16 + g;
                    float b0v = (OM == 0) ? ((ng < Nvalid) ? bias[ng] : 0.0f) : bias[ng];
                    float b1v = (OM == 0) ? ((ng + 1 < Nvalid) ? bias[ng + 1] : 0.0f) : bias[ng + 1];
                    float v0 = acc[mt][nt][0] + b0v;
                    float v1 = acc[mt][nt][1] + b1v;
                    float v2 = acc[mt][nt][2] + b0v;
                    float v3 = acc[mt][nt][3] + b1v;
                    if (GELU) { v0 = gelu_f(v0); v1 = gelu_f(v1); v2 = gelu_f(v2); v3 = gelu_f(v3); }
                    if (OM == 2) {
                        stage[nl * 132 + r0] = v0;
                        stage[(nl + 1) * 132 + r0] = v1;
                        stage[nl * 132 + r0 + 8] = v2;
                        stage[(nl + 1) * 132 + r0 + 8] = v3;
                    } else {
                        stage[r0 * 68 + nl] = v0;
                        stage[r0 * 68 + nl + 1] = v1;
                        stage[(r0 + 8) * 68 + nl] = v2;
                        stage[(r0 + 8) * 68 + nl + 1] = v3;
                    }
                }
            }
        }
        __syncthreads();
        if (OM == 2) {
            int bidx = m0 >> 12;
            int l0 = m0 & 4095;
#pragma unroll
            for (int p = 0; p < 8; p++) {
                int nl = p * 8 + warp;
                int m4 = lane * 4;
                float4 v = *(float4*)&stage[nl * 132 + m4];
                int ng = n0 + nh * 64 + nl;
                long base = ((long)((bidx << 8) + ng)) * 4096 + l0 + m4;
                *(float4*)&Cf[base] = v;
            }
        } else if (OM == 1) {
#pragma unroll
            for (int p = 0; p < 8; p++) {
                int idx = tid + p * 256;
                int r = idx >> 4;
                int c4 = (idx & 15) * 4;
                int n = n0 + nh * 64 + c4;
                float4 v = *(float4*)&stage[r * 68 + c4];
                long base = (long)(m0 + r) * ldc + n;
                __half z0 = __float2half_rn(v.x), z1 = __float2half_rn(v.y);
                __half z2 = __float2half_rn(v.z), z3 = __float2half_rn(v.w);
                uint64_t pk = (uint64_t)*(uint16_t*)&z0 | ((uint64_t)*(uint16_t*)&z1 << 16)
                            | ((uint64_t)*(uint16_t*)&z2 << 32) | ((uint64_t)*(uint16_t*)&z3 << 48);
                *(uint64_t*)&Co[base] = pk;
            }
        } else {
#pragma unroll
            for (int p = 0; p < 8; p++) {
                int idx = tid + p * 256;
                int r = idx >> 4;
                int c4 = (idx & 15) * 4;
                int n = n0 + nh * 64 + c4;
                if (n < Nvalid) {
                    float4 v = *(float4*)&stage[r * 68 + c4];
                    *(float4*)&Cf[(long)(m0 + r) * ldc + n] = v;
                }
            }
        }
        __syncthreads();
    }
}

// ---------------- precompute per-head matrices (bf16 split output) ----------------
__global__ void precompute_kernel(const float* __restrict__ log_dt,
                                  const float* __restrict__ log_A_real,
                                  const float* __restrict__ A_imag,
                                  const float* __restrict__ B_re,
                                  const float* __restrict__ B_im,
                                  const float* __restrict__ C_re,
                                  const float* __restrict__ C_im)
{
    int h = blockIdx.x;
    int t = threadIdx.x;   // 0..63
    __shared__ float s_dtr[NST], s_dti[NST], s_c2r[NST], s_c2i[NST];
    __shared__ float s_k[CH];

    float dt = expf(log_dt[h]);
    if (t < NST) {
        int n = t;
        float Ar = -expf(log_A_real[h * NST + n]);
        float Ai = A_imag[h * NST + n];
        float dtr = dt * Ar, dti = dt * Ai;
        float er = expf(dtr);
        float Er = er * cosf(dti) - 1.0f;
        float Ei = er * sinf(dti);
        float br = B_re[h * NST + n], bi = B_im[h * NST + n];
        float cr = C_re[h * NST + n], ci = C_im[h * NST + n];
        float BCr = br * cr - bi * ci;
        float BCi = br * ci + bi * cr;
        float numr = BCr * Er - BCi * Ei;
        float numi = BCr * Ei + BCi * Er;
        float den = Ar * Ar + Ai * Ai;
        float cpr = (numr * Ar + numi * Ai) / den;
        float cpi = (numi * Ar - numr * Ai) / den;
        s_c2r[n] = 2.0f * cpr;
        s_c2i[n] = 2.0f * cpi;
        s_dtr[n] = dtr;
        s_dti[n] = dti;
        float e64 = expf(64.0f * dtr);
        g_wS[(h * NST + n) * 2 + 0] = e64 * cosf(64.0f * dti);
        g_wS[(h * NST + n) * 2 + 1] = e64 * sinf(64.0f * dti);
    }
    __syncthreads();

    float kt = 0.0f;
    for (int n = 0; n < NST; n++) {
        float dtr = s_dtr[n], dti = s_dti[n];
        float c2r = s_c2r[n], c2i = s_c2i[n];
        float p = (float)(63 - t);
        float ep = expf(p * dtr);
        float vr = ep * cosf(p * dti), vi = ep * sinf(p * dti);
        uint16_t hh, ll;
        splitf(vr, hh, ll);
        g_VSh[h * 4096 + (2 * n) * 64 + t] = hh; g_VSl[h * 4096 + (2 * n) * 64 + t] = ll;
        splitf(vi, hh, ll);
        g_VSh[h * 4096 + (2 * n + 1) * 64 + t] = hh; g_VSl[h * 4096 + (2 * n + 1) * 64 + t] = ll;
        float pt = (float)t;
        float et = expf(pt * dtr);
        float wr = et * cosf(pt * dti), wi = et * sinf(pt * dti);
        kt += c2r * wr - c2i * wi;
        float p1 = (float)(t + 1);
        float e1 = expf(p1 * dtr);
        float w1r = e1 * cosf(p1 * dti), w1i = e1 * sinf(p1 * dti);
        float gr = c2r * w1r - c2i * w1i;
        float gi = -(c2r * w1i + c2i * w1r);
        splitf(gr, hh, ll);
        g_CMSh[h * 8192 + t * 128 + 64 + 2 * n] = hh; g_CMSl[h * 8192 + t * 128 + 64 + 2 * n] = ll;
        splitf(gi, hh, ll);
        g_CMSh[h * 8192 + t * 128 + 64 + 2 * n + 1] = hh; g_CMSl[h * 8192 + t * 128 + 64 + 2 * n + 1] = ll;
    }
    s_k[t] = kt;
    __syncthreads();
    for (int j = 0; j < CH; j++) {
        float val = (j <= t) ? s_k[t - j] : 0.0f;
        uint16_t hh, ll; splitf(val, hh, ll);
        g_CMSh[h * 8192 + t * 128 + j] = hh;
        g_CMSl[h * 8192 + t * 128 + j] = ll;
    }
}

// ================= fused stageA + scan + stageC (bf16 3-term) =================
#define FU_UH 0
#define FU_UL 9216
#define FU_W  18432
#define FU_VH FU_W
#define FU_VL (FU_W + 9216)
#define FU_CH FU_W
#define FU_CL (FU_W + 17408)
#define FU_E  53248
#define FU_PH 70144
#define FU_PL 79360
#define FU_SMEM 88576

__global__ void __launch_bounds__(256, 2) stageAC(const float* __restrict__ Dskip)
{
    extern __shared__ char sm[];
    uint16_t* sUh = (uint16_t*)(sm + FU_UH);
    uint16_t* sUl = (uint16_t*)(sm + FU_UL);
    uint16_t* sVh = (uint16_t*)(sm + FU_VH);
    uint16_t* sVl = (uint16_t*)(sm + FU_VL);
    uint16_t* sCh = (uint16_t*)(sm + FU_CH);
    uint16_t* sCl = (uint16_t*)(sm + FU_CL);
    float*    sE  = (float*)(sm + FU_E);
    uint16_t* sPh = (uint16_t*)(sm + FU_PH);
    uint16_t* sPl = (uint16_t*)(sm + FU_PL);
    float*    sTf   = (float*)(sm + FU_PH);
    float*    sPref = (float*)(sm + FU_PL);

    uint32_t pUh = smem_u32(sUh), pUl = smem_u32(sUl);
    uint32_t pVh = smem_u32(sVh), pVl = smem_u32(sVl);
    uint32_t pCh = smem_u32(sCh), pCl = smem_u32(sCl);
    uint32_t pPh = smem_u32(sPh), pPl = smem_u32(sPl);

    int bh = blockIdx.x, h = bh & (HH - 1);
    int tid = threadIdx.x, warp = tid >> 5, lane = tid & 31;
    int warp_m = warp >> 1, warp_n = warp & 1;
    int g = lane >> 2, tg = lane & 3;
    const float* up = g_u + (long)bh * LL;

    uint32_t a_row72 = (uint32_t)(lane & 15) * 144 + ((lane & 16) ? 16u : 0u);
    uint32_t b_row72 = ((uint32_t)(lane & 7) + ((lane & 16) ? 8u : 0u)) * 144 + ((lane & 8) ? 16u : 0u);
    uint32_t b_row136 = ((uint32_t)(lane & 7) + ((lane & 16) ? 8u : 0u)) * 272 + ((lane & 8) ? 16u : 0u);

    {
        const uint16_t* vh = g_VSh + h * 4096;
        const uint16_t* vl = g_VSl + h * 4096;
#pragma unroll
        for (int p = 0; p < 4; p++) {
            int i = tid + p * 256;
            int e = i * 4, row = e >> 6, col = e & 63;
            float4 v = *(const float4*)(up + e);
            uint16_t h0, l0, h1, l1, h2, l2, h3, l3;
            splitf(v.x, h0, l0); splitf(v.y, h1, l1);
            splitf(v.z, h2, l2); splitf(v.w, h3, l3);
            *(uint2*)&sUh[row * 72 + col] = make_uint2((uint32_t)h0 | ((uint32_t)h1 << 16),
                                                       (uint32_t)h2 | ((uint32_t)h3 << 16));
            *(uint2*)&sUl[row * 72 + col] = make_uint2((uint32_t)l0 | ((uint32_t)l1 << 16),
                                                       (uint32_t)l2 | ((uint32_t)l3 << 16));
        }
#pragma unroll
        for (int p = 0; p < 2; p++) {
            int i = tid + p * 256;
            int row = i >> 3, seg = i & 7;
            *(uint4*)&sVh[row * 72 + seg * 8] = *(const uint4*)&vh[row * 64 + seg * 8];
            *(uint4*)&sVl[row * 72 + seg * 8] = *(const uint4*)&vl[row * 64 + seg * 8];
        }
    }
    __syncthreads();

    {
        float acc[4][4];
#pragma unroll
        for (int nt = 0; nt < 4; nt++)
#pragma unroll
            for (int q = 0; q < 4; q++) acc[nt][q] = 0.0f;
        int ra = warp_m * 16;
#pragma unroll
        for (int ks = 0; ks < 4; ks++) {
            uint32_t kboff = (uint32_t)(ks * 16) * 2;
            uint32_t ah[4], al[4];
            uint32_t ro = (uint32_t)ra * 144 + a_row72 + kboff;
            ldsm_x4(ah, pUh + ro);
            ldsm_x4(al, pUl + ro);
            uint32_t bhp[2][4], blp[2][4];
#pragma unroll
            for (int ntp = 0; ntp < 2; ntp++) {
                uint32_t nb = (uint32_t)(warp_n * 32 + ntp * 16) * 144 + b_row72 + kboff;
                ldsm_x4(bhp[ntp], pVh + nb);
                ldsm_x4(blp[ntp], pVl + nb);
            }
#pragma unroll
            for (int ntp = 0; ntp < 2; ntp++)
#pragma unroll
                for (int sub = 0; sub < 2; sub++)
                    mma16816(acc[ntp * 2 + sub], ah, bhp[ntp][sub * 2], bhp[ntp][sub * 2 + 1]);
#pragma unroll
            for (int ntp = 0; ntp < 2; ntp++)
#pragma unroll
                for (int sub = 0; sub < 2; sub++)
                    mma16816(acc[ntp * 2 + sub], ah, blp[ntp][sub * 2], blp[ntp][sub * 2 + 1]);
#pragma unroll
            for (int ntp = 0; ntp < 2; ntp++)
#pragma unroll
                for (int sub = 0; sub < 2; sub++)
                    mma16816(acc[ntp * 2 + sub], al, bhp[ntp][sub * 2], bhp[ntp][sub * 2 + 1]);
        }
        int ra2 = warp_m * 16;
#pragma unroll
        for (int nt = 0; nt < 4; nt++) {
            int s = warp_n * 32 + nt * 8 + tg * 2;
            sE[(ra2 + g) * 66 + s] = acc[nt][0];
            sE[(ra2 + g) * 66 + s + 1] = acc[nt][1];
            sE[(ra2 + g + 8) * 66 + s] = acc[nt][2];
            sE[(ra2 + g + 8) * 66 + s + 1] = acc[nt][3];
        }
    }
    __syncthreads();

    {
        const uint16_t* ch = g_CMSh + h * 8192;
        const uint16_t* cl = g_CMSl + h * 8192;
#pragma unroll
        for (int p = 0; p < 4; p++) {
            int i = tid + p * 256;
            int row = i >> 4, seg = i & 15;
            *(uint4*)&sCh[row * 136 + seg * 8] = *(const uint4*)&ch[row * 128 + seg * 8];
            *(uint4*)&sCl[row * 136 + seg * 8] = *(const uint4*)&cl[row * 128 + seg * 8];
        }
    }

    int segi = tid >> 5;
    int n = tid & 31;
    float wr = g_wS[(h * NST + n) * 2 + 0];
    float wi = g_wS[(h * NST + n) * 2 + 1];
    {
        float sr = 0.0f, si = 0.0f;
#pragma unroll
        for (int j = 0; j < 8; j++) {
            int c = segi * 8 + j;
            float er = sE[c * 66 + 2 * n], ei = sE[c * 66 + 2 * n + 1];
            float nsr = wr * sr - wi * si + er;
            si = wr * si + wi * sr + ei;
            sr = nsr;
        }
        sTf[segi * 64 + 2 * n] = sr;
        sTf[segi * 64 + 2 * n + 1] = si;
    }
    __syncthreads();
    if (tid < 32) {
        float w2r = wr * wr - wi * wi, w2i = 2.0f * wr * wi;
        float w4r = w2r * w2r - w2i * w2i, w4i = 2.0f * w2r * w2i;
        float w8r = w4r * w4r - w4i * w4i, w8i = 2.0f * w4r * w4i;
        float pr = 0.0f, pi = 0.0f;
#pragma unroll
        for (int s = 0; s < 8; s++) {
            sPref[s * 64 + 2 * n] = pr;
            sPref[s * 64 + 2 * n + 1] = pi;
            float tr = sTf[s * 64 + 2 * n], ti = sTf[s * 64 + 2 * n + 1];
            float npr = w8r * pr - w8i * pi + tr;
            pi = w8r * pi + w8i * pr + ti;
            pr = npr;
        }
    }
    __syncthreads();
    {
        float pr = sPref[segi * 64 + 2 * n];
        float pi = sPref[segi * 64 + 2 * n + 1];
        __syncthreads();
#pragma unroll
        for (int j = 0; j < 8; j++) {
            int c = segi * 8 + j;
            uint16_t hr, lr, hi2, li2;
            splitf(pr, hr, lr);
            splitf(pi, hi2, li2);
            sPh[c * 72 + 2 * n] = hr;  sPh[c * 72 + 2 * n + 1] = hi2;
            sPl[c * 72 + 2 * n] = lr;  sPl[c * 72 + 2 * n + 1] = li2;
            float er = sE[c * 66 + 2 * n], ei = sE[c * 66 + 2 * n + 1];
            float npr = wr * pr - wi * pi + er;
            pi = wr * pi + wi * pr + ei;
            pr = npr;
        }
    }
    __syncthreads();

    {
        float acc[4][4];
#pragma unroll
        for (int nt = 0; nt < 4; nt++)
#pragma unroll
            for (int q = 0; q < 4; q++) acc[nt][q] = 0.0f;
        int ra = warp_m * 16;
#pragma unroll
        for (int ks = 0; ks < 8; ks++) {
            uint32_t aH = (ks < 4) ? pUh : pPh;
            uint32_t aL = (ks < 4) ? pUl : pPl;
            uint32_t kloc = (uint32_t)((ks & 3) * 16) * 2;
            uint32_t ah[4], al[4];
            uint32_t ro = (uint32_t)ra * 144 + a_row72 + kloc;
            ldsm_x4(ah, aH + ro);
            ldsm_x4(al, aL + ro);
            uint32_t kb136 = (uint32_t)(ks * 16) * 2;
            uint32_t bhp[2][4], blp[2][4];
#pragma unroll
            for (int ntp = 0; ntp < 2; ntp++) {
                uint32_t nb = (uint32_t)(warp_n * 32 + ntp * 16) * 272 + b_row136 + kb136;
                ldsm_x4(bhp[ntp], pCh + nb);
                ldsm_x4(blp[ntp], pCl + nb);
            }
#pragma unroll
            for (int ntp = 0; ntp < 2; ntp++)
#pragma unroll
                for (int sub = 0; sub < 2; sub++)
                    mma16816(acc[ntp * 2 + sub], ah, bhp[ntp][sub * 2], bhp[ntp][sub * 2 + 1]);
#pragma unroll
            for (int ntp = 0; ntp < 2; ntp++)
#pragma unroll
                for (int sub = 0; sub < 2; sub++)
                    mma16816(acc[ntp * 2 + sub], ah, blp[ntp][sub * 2], blp[ntp][sub * 2 + 1]);
#pragma unroll
            for (int ntp = 0; ntp < 2; ntp++)
#pragma unroll
                for (int sub = 0; sub < 2; sub++)
                    mma16816(acc[ntp * 2 + sub], al, bhp[ntp][sub * 2], bhp[ntp][sub * 2 + 1]);
        }

        float dsk = Dskip[h];
        float* hp = g_hres + (long)bh * LL;
        int ra2 = warp_m * 16;
#pragma unroll
        for (int nt = 0; nt < 4; nt++) {
            int t = warp_n * 32 + nt * 8 + tg * 2;
            float u00 = __bfloat162float(*(__nv_bfloat16*)&sUh[(ra2 + g) * 72 + t])
                      + __bfloat162float(*(__nv_bfloat16*)&sUl[(ra2 + g) * 72 + t]);
            float u01 = __bfloat162float(*(__nv_bfloat16*)&sUh[(ra2 + g) * 72 + t + 1])
                      + __bfloat162float(*(__nv_bfloat16*)&sUl[(ra2 + g) * 72 + t + 1]);
            float u10 = __bfloat162float(*(__nv_bfloat16*)&sUh[(ra2 + g + 8) * 72 + t])
                      + __bfloat162float(*(__nv_bfloat16*)&sUl[(ra2 + g + 8) * 72 + t]);
            float u11 = __bfloat162float(*(__nv_bfloat16*)&sUh[(ra2 + g + 8) * 72 + t + 1])
                      + __bfloat162float(*(__nv_bfloat16*)&sUl[(ra2 + g + 8) * 72 + t + 1]);
            float y0 = gelu_f(acc[nt][0] + dsk * u00) + u00;
            float y1 = gelu_f(acc[nt][1] + dsk * u01) + u01;
            float y2 = gelu_f(acc[nt][2] + dsk * u10) + u10;
            float y3 = gelu_f(acc[nt][3] + dsk * u11) + u11;
            *(float2*)&hp[(ra2 + g) * 64 + t] = make_float2(y0, y1);
            *(float2*)&hp[(ra2 + g + 8) * 64 + t] = make_float2(y2, y3);
        }
    }
}

// ---------------- layernorm + transpose (B,H,L) -> (B,L,H), fp16 output ----------------
__global__ void __launch_bounds__(256, 1) layernorm_kernel(const float* __restrict__ ln_g,
                                                           const float* __restrict__ ln_b)
{
    int b = blockIdx.y;
    int l0 = blockIdx.x * 32;
    __shared__ float tile[256][33];
    int tid = threadIdx.x;
    int w = tid >> 5, lane = tid & 31;
    const float* hp = g_hres + (long)b * HH * LL;
    for (int hh = w; hh < 256; hh += 8) {
        tile[hh][lane] = hp[(long)hh * LL + l0 + lane];
    }
    __syncthreads();
    uint16_t* op = g_tlnH + ((long)b * LL + l0) * HH;
#pragma unroll
    for (int q = 0; q < 4; q++) {
        int tok = w * 4 + q;
        float s = 0.0f, sq = 0.0f;
#pragma unroll
        for (int j = 0; j < 8; j++) {
            float v = tile[lane + 32 * j][tok];
            s += v;
            sq += v * v;
        }
#pragma unroll
        for (int o = 16; o > 0; o >>= 1) {
            s += __shfl_xor_sync(0xffffffffu, s, o);
            sq += __shfl_xor_sync(0xffffffffu, sq, o);
        }
        float mean = s * (1.0f / 256.0f);
        float var = sq * (1.0f / 256.0f) - mean * mean;
        float rstd = rsqrtf(var + 1e-5f);
#pragma unroll
        for (int j = 0; j < 8; j++) {
            int hh = lane + 32 * j;
            float v = (tile[hh][tok] - mean) * rstd * ln_g[hh] + ln_b[hh];
            __half hv = __float2half_rn(v);
            op[(long)tok * HH + hh] = *(uint16_t*)&hv;
        }
    }
}

// ---------------- launcher ----------------
extern "C" void kernel_launch(void* const* d_in, const int* in_sizes, int n_in,
                              void* d_out, int out_size)
{
    const float* x          = (const float*)d_in[0];
    const float* enc_w      = (const float*)d_in[1];
    const float* enc_b      = (const float*)d_in[2];
    const float* log_dt     = (const float*)d_in[3];
    const float* log_A_real = (const float*)d_in[4];
    const float* A_imag     = (const float*)d_in[5];
    const float* B_re       = (const float*)d_in[6];
    const float* B_im       = (const float*)d_in[7];
    const float* C_re       = (const float*)d_in[8];
    const float* C_im       = (const float*)d_in[9];
    const float* Dskip      = (const float*)d_in[10];
    const float* ln_g       = (const float*)d_in[11];
    const float* ln_b       = (const float*)d_in[12];
    const float* dec1_w     = (const float*)d_in[13];
    const float* dec1_b     = (const float*)d_in[14];
    const float* dec2_w     = (const float*)d_in[15];
    const float* dec2_b     = (const float*)d_in[16];
    float* out = (float*)d_out;

    void *pu = 0;
    void *pxh = 0, *pweh = 0, *pwel = 0, *pw1h = 0, *pw1l = 0, *pw2h = 0, *pw2l = 0;
    void *ptl = 0, *pz = 0;
    cudaGetSymbolAddress(&pu, g_u);
    cudaGetSymbolAddress(&pxh, g_xH);
    cudaGetSymbolAddress(&pweh, g_wencHh); cudaGetSymbolAddress(&pwel, g_wencHl);
    cudaGetSymbolAddress(&pw1h, g_w1Hh);   cudaGetSymbolAddress(&pw1l, g_w1Hl);
    cudaGetSymbolAddress(&pw2h, g_w2Hh);   cudaGetSymbolAddress(&pw2l, g_w2Hl);
    cudaGetSymbolAddress(&ptl, g_tlnH);    cudaGetSymbolAddress(&pz, g_zH);

    cudaFuncSetAttribute(gemm_h<false, 2>, cudaFuncAttributeMaxDynamicSharedMemorySize, GH_SMEM);
    cudaFuncSetAttribute(gemm_h<true, 1>,  cudaFuncAttributeMaxDynamicSharedMemorySize, GH_SMEM);
    cudaFuncSetAttribute(gemm_h<false, 0>, cudaFuncAttributeMaxDynamicSharedMemorySize, GH_SMEM);
    cudaFuncSetAttribute(stageAC, cudaFuncAttributeMaxDynamicSharedMemorySize, FU_SMEM);

    // #1..#3 (keeps enc at launch #4 for ncu capture)
    conv_pad_h<<<(MTOK * 128 + 255) / 256, 256>>>(x, (uint16_t*)pxh, MTOK, DIN, 128, MTOK * 128);
    split_pad_h<<<(HH * 128 + 255) / 256, 256>>>(enc_w, (uint16_t*)pweh, (uint16_t*)pwel,
                                                 HH, DIN, 128, HH * 128);
    split_pad_h<<<(DMID * HH + 255) / 256, 256>>>(dec1_w, (uint16_t*)pw1h, (uint16_t*)pw1l,
                                                  DMID, HH, HH, DMID * HH);

    // #4: encoder GEMM -> g_u fp32 (B,H,L)   [ncu capture target]
    gemm_h<false, 2><<<dim3(2, 512), 256, GH_SMEM>>>(
        (const uint16_t*)pxh, (const uint16_t*)pweh, (const uint16_t*)pwel,
        enc_b, (float*)pu, nullptr, 128, HH, 0);

    // #5, #6
    precompute_kernel<<<HH, 64>>>(log_dt, log_A_real, A_imag, B_re, B_im, C_re, C_im);
    split_pad_h<<<(128 * DMID + 255) / 256, 256>>>(dec2_w, (uint16_t*)pw2h, (uint16_t*)pw2l,
                                                   DOUTP, DMID, DMID, 128 * DMID);

    // #7: fused chunk-states + scan + output stage (bf16 precision path)
    stageAC<<<BB * HH, 256, FU_SMEM>>>(Dskip);

    // #8: layernorm + transpose -> fp16 plane
    layernorm_kernel<<<dim3(LL / 32, BB), 256>>>(ln_g, ln_b);

    // #9, #10: decoder MLP (fp16 2-term)
    gemm_h<true, 1><<<dim3(4, 512), 256, GH_SMEM>>>(
        (const uint16_t*)ptl, (const uint16_t*)pw1h, (const uint16_t*)pw1l,
        dec1_b, nullptr, (uint16_t*)pz, HH, DMID, DMID);

    gemm_h<false, 0><<<dim3(1, 512), 256, GH_SMEM>>>(
        (const uint16_t*)pz, (const uint16_t*)pw2h, (const uint16_t*)pw2l,
        dec2_b, out, nullptr, DMID, DOUTP, DOUTP);
}

// round 14
// speedup vs baseline: 1.8554x; 1.1566x over previous
#include <cuda_runtime.h>
#include <cuda_bf16.h>
#include <cuda_fp16.h>
#include <math.h>
#include <stdint.h>

#define BB   16
#define HH   256
#define LL   4096
#define DIN  100
#define DMID 512
#define DOUTP 100
#define NST  32
#define CH   64
#define NC   64
#define MTOK (BB * LL)

// ---------------- fp32 intermediates ----------------
__device__ float g_u[BB * HH * LL];       // encoder output, (B,H,L)
__device__ float g_hres[BB * HH * LL];    // post-gelu residual, (B,H,L)
__device__ float g_wS[HH * NST * 2];      // w^64 per (h,n)

// ---------------- fp16 planes (GEMM path) ----------------
__device__ uint16_t g_xH[MTOK * 128];                         // x fp16, padded 100->128
__device__ uint16_t g_wencH[HH * 128];                        // enc_w fp16
__device__ uint16_t g_w1H[DMID * HH];
__device__ uint16_t g_w2H[128 * DMID];                        // dec2_w padded rows
__device__ uint16_t g_tlnH[BB * LL * HH];                     // LN out fp16
__device__ uint16_t g_zH[MTOK * DMID];                        // MLP hidden fp16

// ---------------- bf16 split planes (S4 path, high precision) ----------------
__device__ uint16_t g_VSh[HH * 64 * 64], g_VSl[HH * 64 * 64];     // [h][s][t]
__device__ uint16_t g_CMSh[HH * 64 * 128], g_CMSl[HH * 64 * 128]; // [h][t][k]

__device__ __forceinline__ float gelu_f(float x) {
    return 0.5f * x * (1.0f + erff(x * 0.70710678118654752f));
}
__device__ __forceinline__ void splitf(float v, uint16_t& h, uint16_t& l) {
    __nv_bfloat16 bh = __float2bfloat16_rn(v);
    float hf = __bfloat162float(bh);
    __nv_bfloat16 bl = __float2bfloat16_rn(v - hf);
    h = *(uint16_t*)&bh; l = *(uint16_t*)&bl;
}
__device__ __forceinline__ void mma16816(float* c, const uint32_t* a, uint32_t b0, uint32_t b1) {
    asm volatile(
        "mma.sync.aligned.m16n8k16.row.col.f32.bf16.bf16.f32 "
        "{%0,%1,%2,%3}, {%4,%5,%6,%7}, {%8,%9}, {%0,%1,%2,%3};"
        : "+f"(c[0]), "+f"(c[1]), "+f"(c[2]), "+f"(c[3])
        : "r"(a[0]), "r"(a[1]), "r"(a[2]), "r"(a[3]), "r"(b0), "r"(b1));
}
__device__ __forceinline__ void mma16816h(float* c, const uint32_t* a, uint32_t b0, uint32_t b1) {
    asm volatile(
        "mma.sync.aligned.m16n8k16.row.col.f32.f16.f16.f32 "
        "{%0,%1,%2,%3}, {%4,%5,%6,%7}, {%8,%9}, {%0,%1,%2,%3};"
        : "+f"(c[0]), "+f"(c[1]), "+f"(c[2]), "+f"(c[3])
        : "r"(a[0]), "r"(a[1]), "r"(a[2]), "r"(a[3]), "r"(b0), "r"(b1));
}
__device__ __forceinline__ void ldsm_x4(uint32_t* r, uint32_t addr) {
    asm volatile("ldmatrix.sync.aligned.m8n8.x4.shared.b16 {%0,%1,%2,%3}, [%4];"
        : "=r"(r[0]), "=r"(r[1]), "=r"(r[2]), "=r"(r[3]) : "r"(addr));
}
__device__ __forceinline__ uint32_t smem_u32(const void* p) {
    uint32_t a;
    asm("{ .reg .u64 t; cvta.to.shared.u64 t, %1; cvt.u32.u64 %0, t; }" : "=r"(a) : "l"(p));
    return a;
}
#define CP16(dst, src) asm volatile("cp.async.cg.shared.global [%0], [%1], 16;" :: "r"(dst), "l"(src))
#define CPCOMMIT() asm volatile("cp.async.commit_group;" ::: "memory")
#define CPWAIT1() asm volatile("cp.async.wait_group 1;" ::: "memory")
#define CPWAIT0() asm volatile("cp.async.wait_group 0;" ::: "memory")

// ---------------- fp16 convert/pad kernel ----------------
__global__ void conv_pad_h(const float* __restrict__ src, uint16_t* __restrict__ d,
                           int M, int K, int Kp, int total)
{
    int i = blockIdx.x * 256 + threadIdx.x;
    if (i >= total) return;
    int r = i / Kp, c = i - r * Kp;
    float v = (r < M && c < K) ? src[(long)r * K + c] : 0.0f;
    __half hv = __float2half_rn(v);
    d[i] = *(uint16_t*)&hv;
}

// ============ pure fp16 tensor-core GEMM: C[M,N] = A[M,K]*B[N,K]^T + bias ============
// tile 128x128, BK=64, double-buffered cp.async + in-loop B-fragment ping-pong.
#define SAST 72                         // halfwords per smem row (64 + 8 pad)
#define PLANE_BYTES (128 * SAST * 2)    // 18432
#define HBUF_BYTES (2 * PLANE_BYTES)    // 36864
#define GH_SMEM (2 * HBUF_BYTES)        // 73728

template <bool GELU, int OM>
__global__ void __launch_bounds__(256, 2)
gemm_h(const uint16_t* __restrict__ A, const uint16_t* __restrict__ B,
       const float* __restrict__ bias, float* __restrict__ Cf,
       uint16_t* __restrict__ Co, int K, int Nvalid, int ldc)
{
    extern __shared__ char smem[];
    uint32_t sb = smem_u32(smem);
    int tid = threadIdx.x;
    int warp = tid >> 5, lane = tid & 31;
    int warp_m = warp >> 1, warp_n = warp & 1;
    int g = lane >> 2, tg = lane & 3;
    int m0 = blockIdx.y * 128, n0 = blockIdx.x * 128;

    uint32_t a_row = (uint32_t)(lane & 15) * (SAST * 2) + ((lane & 16) ? 16u : 0u);
    uint32_t b_row = ((uint32_t)(lane & 7) + ((lane & 16) ? 8u : 0u)) * (SAST * 2)
                   + ((lane & 8) ? 16u : 0u);

    // chunk = 64 K-values. 2 planes x 128 rows x 8 segs of 16B = 2048 cp.async / 256 thr = 8 each
    auto load_chunk = [&](int buf, int k0) {
        uint32_t base = sb + (uint32_t)buf * HBUF_BYTES;
#pragma unroll
        for (int p = 0; p < 8; p++) {
            int idx = tid + p * 256;
            int pl = idx >> 10;
            int rem = idx & 1023;
            int row = rem >> 3, seg = rem & 7;
            uint32_t doff = (uint32_t)pl * PLANE_BYTES + (uint32_t)(row * SAST + seg * 8) * 2;
            const uint16_t* src = (pl == 0) ? (A + (long)(m0 + row) * K + k0 + seg * 8)
                                            : (B + (long)(n0 + row) * K + k0 + seg * 8);
            CP16(base + doff, src);
        }
    };

    float acc[2][8][4];
#pragma unroll
    for (int mt = 0; mt < 2; mt++)
#pragma unroll
        for (int nt = 0; nt < 8; nt++)
#pragma unroll
            for (int q = 0; q < 4; q++) acc[mt][nt][q] = 0.0f;

    int nch = K >> 6;
    load_chunk(0, 0);
    CPCOMMIT();
    for (int c = 0; c < nch; c++) {
        if (c + 1 < nch) { load_chunk((c + 1) & 1, (c + 1) << 6); CPCOMMIT(); CPWAIT1(); }
        else CPWAIT0();
        __syncthreads();
        uint32_t bufb = sb + (uint32_t)(c & 1) * HBUF_BYTES;
        uint32_t pA = bufb, pB = bufb + PLANE_BYTES;
#pragma unroll
        for (int ks = 0; ks < 4; ks++) {
            uint32_t kboff = (uint32_t)(ks * 16) * 2;
            uint32_t ah[2][4];
#pragma unroll
            for (int mt = 0; mt < 2; mt++) {
                uint32_t ro = (uint32_t)(warp_m * 32 + mt * 16) * (SAST * 2) + a_row + kboff;
                ldsm_x4(ah[mt], pA + ro);
            }
            uint32_t bA[4], bBuf[4];
            uint32_t nbase = (uint32_t)(warp_n * 64) * (SAST * 2) + b_row + kboff;
            ldsm_x4(bA, pB + nbase);
            // ntp 0 (prefetch 1)
            ldsm_x4(bBuf, pB + nbase + 16 * (SAST * 2));
#pragma unroll
            for (int sub = 0; sub < 2; sub++)
#pragma unroll
                for (int mt = 0; mt < 2; mt++)
                    mma16816h(acc[mt][0 * 2 + sub], ah[mt], bA[sub * 2], bA[sub * 2 + 1]);
            // ntp 1 (prefetch 2)
            ldsm_x4(bA, pB + nbase + 32 * (SAST * 2));
#pragma unroll
            for (int sub = 0; sub < 2; sub++)
#pragma unroll
                for (int mt = 0; mt < 2; mt++)
                    mma16816h(acc[mt][1 * 2 + sub], ah[mt], bBuf[sub * 2], bBuf[sub * 2 + 1]);
            // ntp 2 (prefetch 3)
            ldsm_x4(bBuf, pB + nbase + 48 * (SAST * 2));
#pragma unroll
            for (int sub = 0; sub < 2; sub++)
#pragma unroll
                for (int mt = 0; mt < 2; mt++)
                    mma16816h(acc[mt][2 * 2 + sub], ah[mt], bA[sub * 2], bA[sub * 2 + 1]);
            // ntp 3
#pragma unroll
            for (int sub = 0; sub < 2; sub++)
#pragma unroll
                for (int mt = 0; mt < 2; mt++)
                    mma16816h(acc[mt][3 * 2 + sub], ah[mt], bBuf[sub * 2], bBuf[sub * 2 + 1]);
        }
        __syncthreads();
    }

    // -------- epilogue via smem stage --------
    float* stage = (float*)smem;
    for (int nh = 0; nh < 2; nh++) {
        if (warp_n == nh) {
#pragma unroll
            for (int mt = 0; mt < 2; mt++) {
#pragma unroll
                for (int nt = 0; nt < 8; nt++) {
                    int nl = nt * 8 + tg * 2;
                    int ng = n0 + nh * 64 + nl;
                    int r0 = warp_m * 32 + mt * 16 + g;
                    float b0v = (OM == 0) ? ((ng < Nvalid) ? bias[ng] : 0.0f) : bias[ng];
                    float b1v = (OM == 0) ? ((ng + 1 < Nvalid) ? bias[ng + 1] : 0.0f) : bias[ng + 1];
                    float v0 = acc[mt][nt][0] + b0v;
                    float v1 = acc[mt][nt][1] + b1v;
                    float v2 = acc[mt][nt][2] + b0v;
                    float v3 = acc[mt][nt][3] + b1v;
                    if (GELU) { v0 = gelu_f(v0); v1 = gelu_f(v1); v2 = gelu_f(v2); v3 = gelu_f(v3); }
                    if (OM == 2) {
                        stage[nl * 132 + r0] = v0;
                        stage[(nl + 1) * 132 + r0] = v1;
                        stage[nl * 132 + r0 + 8] = v2;
                        stage[(nl + 1) * 132 + r0 + 8] = v3;
                    } else {
                        stage[r0 * 68 + nl] = v0;
                        stage[r0 * 68 + nl + 1] = v1;
                        stage[(r0 + 8) * 68 + nl] = v2;
                        stage[(r0 + 8) * 68 + nl + 1] = v3;
                    }
                }
            }
        }
        __syncthreads();
        if (OM == 2) {
            int bidx = m0 >> 12;
            int l0 = m0 & 4095;
#pragma unroll
            for (int p = 0; p < 8; p++) {
                int nl = p * 8 + warp;
                int m4 = lane * 4;
                float4 v = *(float4*)&stage[nl * 132 + m4];
                int ng = n0 + nh * 64 + nl;
                long base = ((long)((bidx << 8) + ng)) * 4096 + l0 + m4;
                *(float4*)&Cf[base] = v;
            }
        } else if (OM == 1) {
#pragma unroll
            for (int p = 0; p < 8; p++) {
                int idx = tid + p * 256;
                int r = idx >> 4;
                int c4 = (idx & 15) * 4;
                int n = n0 + nh * 64 + c4;
                float4 v = *(float4*)&stage[r * 68 + c4];
                long base = (long)(m0 + r) * ldc + n;
                __half z0 = __float2half_rn(v.x), z1 = __float2half_rn(v.y);
                __half z2 = __float2half_rn(v.z), z3 = __float2half_rn(v.w);
                uint64_t pk = (uint64_t)*(uint16_t*)&z0 | ((uint64_t)*(uint16_t*)&z1 << 16)
                            | ((uint64_t)*(uint16_t*)&z2 << 32) | ((uint64_t)*(uint16_t*)&z3 << 48);
                *(uint64_t*)&Co[base] = pk;
            }
        } else {
#pragma unroll
            for (int p = 0; p < 8; p++) {
                int idx = tid + p * 256;
                int r = idx >> 4;
                int c4 = (idx & 15) * 4;
                int n = n0 + nh * 64 + c4;
                if (n < Nvalid) {
                    float4 v = *(float4*)&stage[r * 68 + c4];
                    *(float4*)&Cf[(long)(m0 + r) * ldc + n] = v;
                }
            }
        }
        __syncthreads();
    }
}

// ---------------- precompute per-head matrices (bf16 split output) ----------------
__global__ void precompute_kernel(const float* __restrict__ log_dt,
                                  const float* __restrict__ log_A_real,
                                  const float* __restrict__ A_imag,
                                  const float* __restrict__ B_re,
                                  const float* __restrict__ B_im,
                                  const float* __restrict__ C_re,
                                  const float* __restrict__ C_im)
{
    int h = blockIdx.x;
    int t = threadIdx.x;   // 0..63
    __shared__ float s_dtr[NST], s_dti[NST], s_c2r[NST], s_c2i[NST];
    __shared__ float s_k[CH];

    float dt = expf(log_dt[h]);
    if (t < NST) {
        int n = t;
        float Ar = -expf(log_A_real[h * NST + n]);
        float Ai = A_imag[h * NST + n];
        float dtr = dt * Ar, dti = dt * Ai;
        float er = expf(dtr);
        float Er = er * cosf(dti) - 1.0f;
        float Ei = er * sinf(dti);
        float br = B_re[h * NST + n], bi = B_im[h * NST + n];
        float cr = C_re[h * NST + n], ci = C_im[h * NST + n];
        float BCr = br * cr - bi * ci;
        float BCi = br * ci + bi * cr;
        float numr = BCr * Er - BCi * Ei;
        float numi = BCr * Ei + BCi * Er;
        float den = Ar * Ar + Ai * Ai;
        float cpr = (numr * Ar + numi * Ai) / den;
        float cpi = (numi * Ar - numr * Ai) / den;
        s_c2r[n] = 2.0f * cpr;
        s_c2i[n] = 2.0f * cpi;
        s_dtr[n] = dtr;
        s_dti[n] = dti;
        float e64 = expf(64.0f * dtr);
        g_wS[(h * NST + n) * 2 + 0] = e64 * cosf(64.0f * dti);
        g_wS[(h * NST + n) * 2 + 1] = e64 * sinf(64.0f * dti);
    }
    __syncthreads();

    float kt = 0.0f;
    for (int n = 0; n < NST; n++) {
        float dtr = s_dtr[n], dti = s_dti[n];
        float c2r = s_c2r[n], c2i = s_c2i[n];
        float p = (float)(63 - t);
        float ep = expf(p * dtr);
        float vr = ep * cosf(p * dti), vi = ep * sinf(p * dti);
        uint16_t hh, ll;
        splitf(vr, hh, ll);
        g_VSh[h * 4096 + (2 * n) * 64 + t] = hh; g_VSl[h * 4096 + (2 * n) * 64 + t] = ll;
        splitf(vi, hh, ll);
        g_VSh[h * 4096 + (2 * n + 1) * 64 + t] = hh; g_VSl[h * 4096 + (2 * n + 1) * 64 + t] = ll;
        float pt = (float)t;
        float et = expf(pt * dtr);
        float wr = et * cosf(pt * dti), wi = et * sinf(pt * dti);
        kt += c2r * wr - c2i * wi;
        float p1 = (float)(t + 1);
        float e1 = expf(p1 * dtr);
        float w1r = e1 * cosf(p1 * dti), w1i = e1 * sinf(p1 * dti);
        float gr = c2r * w1r - c2i * w1i;
        float gi = -(c2r * w1i + c2i * w1r);
        splitf(gr, hh, ll);
        g_CMSh[h * 8192 + t * 128 + 64 + 2 * n] = hh; g_CMSl[h * 8192 + t * 128 + 64 + 2 * n] = ll;
        splitf(gi, hh, ll);
        g_CMSh[h * 8192 + t * 128 + 64 + 2 * n + 1] = hh; g_CMSl[h * 8192 + t * 128 + 64 + 2 * n + 1] = ll;
    }
    s_k[t] = kt;
    __syncthreads();
    for (int j = 0; j < CH; j++) {
        float val = (j <= t) ? s_k[t - j] : 0.0f;
        uint16_t hh, ll; splitf(val, hh, ll);
        g_CMSh[h * 8192 + t * 128 + j] = hh;
        g_CMSl[h * 8192 + t * 128 + j] = ll;
    }
}

// ================= fused stageA + scan + stageC (bf16 3-term) =================
#define FU_UH 0
#define FU_UL 9216
#define FU_W  18432
#define FU_VH FU_W
#define FU_VL (FU_W + 9216)
#define FU_CH FU_W
#define FU_CL (FU_W + 17408)
#define FU_E  53248
#define FU_PH 70144
#define FU_PL 79360
#define FU_SMEM 88576

__global__ void __launch_bounds__(256, 2) stageAC(const float* __restrict__ Dskip)
{
    extern __shared__ char sm[];
    uint16_t* sUh = (uint16_t*)(sm + FU_UH);
    uint16_t* sUl = (uint16_t*)(sm + FU_UL);
    uint16_t* sVh = (uint16_t*)(sm + FU_VH);
    uint16_t* sVl = (uint16_t*)(sm + FU_VL);
    uint16_t* sCh = (uint16_t*)(sm + FU_CH);
    uint16_t* sCl = (uint16_t*)(sm + FU_CL);
    float*    sE  = (float*)(sm + FU_E);
    uint16_t* sPh = (uint16_t*)(sm + FU_PH);
    uint16_t* sPl = (uint16_t*)(sm + FU_PL);
    float*    sTf   = (float*)(sm + FU_PH);
    float*    sPref = (float*)(sm + FU_PL);

    uint32_t pUh = smem_u32(sUh), pUl = smem_u32(sUl);
    uint32_t pVh = smem_u32(sVh), pVl = smem_u32(sVl);
    uint32_t pCh = smem_u32(sCh), pCl = smem_u32(sCl);
    uint32_t pPh = smem_u32(sPh), pPl = smem_u32(sPl);

    int bh = blockIdx.x, h = bh & (HH - 1);
    int tid = threadIdx.x, warp = tid >> 5, lane = tid & 31;
    int warp_m = warp >> 1, warp_n = warp & 1;
    int g = lane >> 2, tg = lane & 3;
    const float* up = g_u + (long)bh * LL;

    uint32_t a_row72 = (uint32_t)(lane & 15) * 144 + ((lane & 16) ? 16u : 0u);
    uint32_t b_row72 = ((uint32_t)(lane & 7) + ((lane & 16) ? 8u : 0u)) * 144 + ((lane & 8) ? 16u : 0u);
    uint32_t b_row136 = ((uint32_t)(lane & 7) + ((lane & 16) ? 8u : 0u)) * 272 + ((lane & 8) ? 16u : 0u);

    {
        const uint16_t* vh = g_VSh + h * 4096;
        const uint16_t* vl = g_VSl + h * 4096;
#pragma unroll
        for (int p = 0; p < 4; p++) {
            int i = tid + p * 256;
            int e = i * 4, row = e >> 6, col = e & 63;
            float4 v = *(const float4*)(up + e);
            uint16_t h0, l0, h1, l1, h2, l2, h3, l3;
            splitf(v.x, h0, l0); splitf(v.y, h1, l1);
            splitf(v.z, h2, l2); splitf(v.w, h3, l3);
            *(uint2*)&sUh[row * 72 + col] = make_uint2((uint32_t)h0 | ((uint32_t)h1 << 16),
                                                       (uint32_t)h2 | ((uint32_t)h3 << 16));
            *(uint2*)&sUl[row * 72 + col] = make_uint2((uint32_t)l0 | ((uint32_t)l1 << 16),
                                                       (uint32_t)l2 | ((uint32_t)l3 << 16));
        }
#pragma unroll
        for (int p = 0; p < 2; p++) {
            int i = tid + p * 256;
            int row = i >> 3, seg = i & 7;
            *(uint4*)&sVh[row * 72 + seg * 8] = *(const uint4*)&vh[row * 64 + seg * 8];
            *(uint4*)&sVl[row * 72 + seg * 8] = *(const uint4*)&vl[row * 64 + seg * 8];
        }
    }
    __syncthreads();

    {
        float acc[4][4];
#pragma unroll
        for (int nt = 0; nt < 4; nt++)
#pragma unroll
            for (int q = 0; q < 4; q++) acc[nt][q] = 0.0f;
        int ra = warp_m * 16;
#pragma unroll
        for (int ks = 0; ks < 4; ks++) {
            uint32_t kboff = (uint32_t)(ks * 16) * 2;
            uint32_t ah[4], al[4];
            uint32_t ro = (uint32_t)ra * 144 + a_row72 + kboff;
            ldsm_x4(ah, pUh + ro);
            ldsm_x4(al, pUl + ro);
            uint32_t bhp[2][4], blp[2][4];
#pragma unroll
            for (int ntp = 0; ntp < 2; ntp++) {
                uint32_t nb = (uint32_t)(warp_n * 32 + ntp * 16) * 144 + b_row72 + kboff;
                ldsm_x4(bhp[ntp], pVh + nb);
                ldsm_x4(blp[ntp], pVl + nb);
            }
#pragma unroll
            for (int ntp = 0; ntp < 2; ntp++)
#pragma unroll
                for (int sub = 0; sub < 2; sub++)
                    mma16816(acc[ntp * 2 + sub], ah, bhp[ntp][sub * 2], bhp[ntp][sub * 2 + 1]);
#pragma unroll
            for (int ntp = 0; ntp < 2; ntp++)
#pragma unroll
                for (int sub = 0; sub < 2; sub++)
                    mma16816(acc[ntp * 2 + sub], ah, blp[ntp][sub * 2], blp[ntp][sub * 2 + 1]);
#pragma unroll
            for (int ntp = 0; ntp < 2; ntp++)
#pragma unroll
                for (int sub = 0; sub < 2; sub++)
                    mma16816(acc[ntp * 2 + sub], al, bhp[ntp][sub * 2], bhp[ntp][sub * 2 + 1]);
        }
        int ra2 = warp_m * 16;
#pragma unroll
        for (int nt = 0; nt < 4; nt++) {
            int s = warp_n * 32 + nt * 8 + tg * 2;
            sE[(ra2 + g) * 66 + s] = acc[nt][0];
            sE[(ra2 + g) * 66 + s + 1] = acc[nt][1];
            sE[(ra2 + g + 8) * 66 + s] = acc[nt][2];
            sE[(ra2 + g + 8) * 66 + s + 1] = acc[nt][3];
        }
    }
    __syncthreads();

    {
        const uint16_t* ch = g_CMSh + h * 8192;
        const uint16_t* cl = g_CMSl + h * 8192;
#pragma unroll
        for (int p = 0; p < 4; p++) {
            int i = tid + p * 256;
            int row = i >> 4, seg = i & 15;
            *(uint4*)&sCh[row * 136 + seg * 8] = *(const uint4*)&ch[row * 128 + seg * 8];
            *(uint4*)&sCl[row * 136 + seg * 8] = *(const uint4*)&cl[row * 128 + seg * 8];
        }
    }

    int segi = tid >> 5;
    int n = tid & 31;
    float wr = g_wS[(h * NST + n) * 2 + 0];
    float wi = g_wS[(h * NST + n) * 2 + 1];
    {
        float sr = 0.0f, si = 0.0f;
#pragma unroll
        for (int j = 0; j < 8; j++) {
            int c = segi * 8 + j;
            float er = sE[c * 66 + 2 * n], ei = sE[c * 66 + 2 * n + 1];
            float nsr = wr * sr - wi * si + er;
            si = wr * si + wi * sr + ei;
            sr = nsr;
        }
        sTf[segi * 64 + 2 * n] = sr;
        sTf[segi * 64 + 2 * n + 1] = si;
    }
    __syncthreads();
    if (tid < 32) {
        float w2r = wr * wr - wi * wi, w2i = 2.0f * wr * wi;
        float w4r = w2r * w2r - w2i * w2i, w4i = 2.0f * w2r * w2i;
        float w8r = w4r * w4r - w4i * w4i, w8i = 2.0f * w4r * w4i;
        float pr = 0.0f, pi = 0.0f;
#pragma unroll
        for (int s = 0; s < 8; s++) {
            sPref[s * 64 + 2 * n] = pr;
            sPref[s * 64 + 2 * n + 1] = pi;
            float tr = sTf[s * 64 + 2 * n], ti = sTf[s * 64 + 2 * n + 1];
            float npr = w8r * pr - w8i * pi + tr;
            pi = w8r * pi + w8i * pr + ti;
            pr = npr;
        }
    }
    __syncthreads();
    {
        float pr = sPref[segi * 64 + 2 * n];
        float pi = sPref[segi * 64 + 2 * n + 1];
        __syncthreads();
#pragma unroll
        for (int j = 0; j < 8; j++) {
            int c = segi * 8 + j;
            uint16_t hr, lr, hi2, li2;
            splitf(pr, hr, lr);
            splitf(pi, hi2, li2);
            sPh[c * 72 + 2 * n] = hr;  sPh[c * 72 + 2 * n + 1] = hi2;
            sPl[c * 72 + 2 * n] = lr;  sPl[c * 72 + 2 * n + 1] = li2;
            float er = sE[c * 66 + 2 * n], ei = sE[c * 66 + 2 * n + 1];
            float npr = wr * pr - wi * pi + er;
            pi = wr * pi + wi * pr + ei;
            pr = npr;
        }
    }
    __syncthreads();

    {
        float acc[4][4];
#pragma unroll
        for (int nt = 0; nt < 4; nt++)
#pragma unroll
            for (int q = 0; q < 4; q++) acc[nt][q] = 0.0f;
        int ra = warp_m * 16;
#pragma unroll
        for (int ks = 0; ks < 8; ks++) {
            uint32_t aH = (ks < 4) ? pUh : pPh;
            uint32_t aL = (ks < 4) ? pUl : pPl;
            uint32_t kloc = (uint32_t)((ks & 3) * 16) * 2;
            uint32_t ah[4], al[4];
            uint32_t ro = (uint32_t)ra * 144 + a_row72 + kloc;
            ldsm_x4(ah, aH + ro);
            ldsm_x4(al, aL + ro);
            uint32_t kb136 = (uint32_t)(ks * 16) * 2;
            uint32_t bhp[2][4], blp[2][4];
#pragma unroll
            for (int ntp = 0; ntp < 2; ntp++) {
                uint32_t nb = (uint32_t)(warp_n * 32 + ntp * 16) * 272 + b_row136 + kb136;
                ldsm_x4(bhp[ntp], pCh + nb);
                ldsm_x4(blp[ntp], pCl + nb);
            }
#pragma unroll
            for (int ntp = 0; ntp < 2; ntp++)
#pragma unroll
                for (int sub = 0; sub < 2; sub++)
                    mma16816(acc[ntp * 2 + sub], ah, bhp[ntp][sub * 2], bhp[ntp][sub * 2 + 1]);
#pragma unroll
            for (int ntp = 0; ntp < 2; ntp++)
#pragma unroll
                for (int sub = 0; sub < 2; sub++)
                    mma16816(acc[ntp * 2 + sub], ah, blp[ntp][sub * 2], blp[ntp][sub * 2 + 1]);
#pragma unroll
            for (int ntp = 0; ntp < 2; ntp++)
#pragma unroll
                for (int sub = 0; sub < 2; sub++)
                    mma16816(acc[ntp * 2 + sub], al, bhp[ntp][sub * 2], bhp[ntp][sub * 2 + 1]);
        }

        float dsk = Dskip[h];
        float* hp = g_hres + (long)bh * LL;
        int ra2 = warp_m * 16;
#pragma unroll
        for (int nt = 0; nt < 4; nt++) {
            int t = warp_n * 32 + nt * 8 + tg * 2;
            float u00 = __bfloat162float(*(__nv_bfloat16*)&sUh[(ra2 + g) * 72 + t])
                      + __bfloat162float(*(__nv_bfloat16*)&sUl[(ra2 + g) * 72 + t]);
            float u01 = __bfloat162float(*(__nv_bfloat16*)&sUh[(ra2 + g) * 72 + t + 1])
                      + __bfloat162float(*(__nv_bfloat16*)&sUl[(ra2 + g) * 72 + t + 1]);
            float u10 = __bfloat162float(*(__nv_bfloat16*)&sUh[(ra2 + g + 8) * 72 + t])
                      + __bfloat162float(*(__nv_bfloat16*)&sUl[(ra2 + g + 8) * 72 + t]);
            float u11 = __bfloat162float(*(__nv_bfloat16*)&sUh[(ra2 + g + 8) * 72 + t + 1])
                      + __bfloat162float(*(__nv_bfloat16*)&sUl[(ra2 + g + 8) * 72 + t + 1]);
            float y0 = gelu_f(acc[nt][0] + dsk * u00) + u00;
            float y1 = gelu_f(acc[nt][1] + dsk * u01) + u01;
            float y2 = gelu_f(acc[nt][2] + dsk * u10) + u10;
            float y3 = gelu_f(acc[nt][3] + dsk * u11) + u11;
            *(float2*)&hp[(ra2 + g) * 64 + t] = make_float2(y0, y1);
            *(float2*)&hp[(ra2 + g + 8) * 64 + t] = make_float2(y2, y3);
        }
    }
}

// ---------------- layernorm + transpose (B,H,L) -> (B,L,H), fp16 output ----------------
__global__ void __launch_bounds__(256, 1) layernorm_kernel(const float* __restrict__ ln_g,
                                                           const float* __restrict__ ln_b)
{
    int b = blockIdx.y;
    int l0 = blockIdx.x * 32;
    __shared__ float tile[256][33];
    int tid = threadIdx.x;
    int w = tid >> 5, lane = tid & 31;
    const float* hp = g_hres + (long)b * HH * LL;
    for (int hh = w; hh < 256; hh += 8) {
        tile[hh][lane] = hp[(long)hh * LL + l0 + lane];
    }
    __syncthreads();
    uint16_t* op = g_tlnH + ((long)b * LL + l0) * HH;
#pragma unroll
    for (int q = 0; q < 4; q++) {
        int tok = w * 4 + q;
        float s = 0.0f, sq = 0.0f;
#pragma unroll
        for (int j = 0; j < 8; j++) {
            float v = tile[lane + 32 * j][tok];
            s += v;
            sq += v * v;
        }
#pragma unroll
        for (int o = 16; o > 0; o >>= 1) {
            s += __shfl_xor_sync(0xffffffffu, s, o);
            sq += __shfl_xor_sync(0xffffffffu, sq, o);
        }
        float mean = s * (1.0f / 256.0f);
        float var = sq * (1.0f / 256.0f) - mean * mean;
        float rstd = rsqrtf(var + 1e-5f);
#pragma unroll
        for (int j = 0; j < 8; j++) {
            int hh = lane + 32 * j;
            float v = (tile[hh][tok] - mean) * rstd * ln_g[hh] + ln_b[hh];
            __half hv = __float2half_rn(v);
            op[(long)tok * HH + hh] = *(uint16_t*)&hv;
        }
    }
}

// ---------------- launcher ----------------
extern "C" void kernel_launch(void* const* d_in, const int* in_sizes, int n_in,
                              void* d_out, int out_size)
{
    const float* x          = (const float*)d_in[0];
    const float* enc_w      = (const float*)d_in[1];
    const float* enc_b      = (const float*)d_in[2];
    const float* log_dt     = (const float*)d_in[3];
    const float* log_A_real = (const float*)d_in[4];
    const float* A_imag     = (const float*)d_in[5];
    const float* B_re       = (const float*)d_in[6];
    const float* B_im       = (const float*)d_in[7];
    const float* C_re       = (const float*)d_in[8];
    const float* C_im       = (const float*)d_in[9];
    const float* Dskip      = (const float*)d_in[10];
    const float* ln_g       = (const float*)d_in[11];
    const float* ln_b       = (const float*)d_in[12];
    const float* dec1_w     = (const float*)d_in[13];
    const float* dec1_b     = (const float*)d_in[14];
    const float* dec2_w     = (const float*)d_in[15];
    const float* dec2_b     = (const float*)d_in[16];
    float* out = (float*)d_out;

    void *pu = 0;
    void *pxh = 0, *pwe = 0, *pw1 = 0, *pw2 = 0, *ptl = 0, *pz = 0;
    cudaGetSymbolAddress(&pu, g_u);
    cudaGetSymbolAddress(&pxh, g_xH);
    cudaGetSymbolAddress(&pwe, g_wencH);
    cudaGetSymbolAddress(&pw1, g_w1H);
    cudaGetSymbolAddress(&pw2, g_w2H);
    cudaGetSymbolAddress(&ptl, g_tlnH);
    cudaGetSymbolAddress(&pz, g_zH);

    cudaFuncSetAttribute(gemm_h<false, 2>, cudaFuncAttributeMaxDynamicSharedMemorySize, GH_SMEM);
    cudaFuncSetAttribute(gemm_h<true, 1>,  cudaFuncAttributeMaxDynamicSharedMemorySize, GH_SMEM);
    cudaFuncSetAttribute(gemm_h<false, 0>, cudaFuncAttributeMaxDynamicSharedMemorySize, GH_SMEM);
    cudaFuncSetAttribute(stageAC, cudaFuncAttributeMaxDynamicSharedMemorySize, FU_SMEM);

    // #1..#3 (keeps enc at launch #4 for ncu capture)
    conv_pad_h<<<(MTOK * 128 + 255) / 256, 256>>>(x, (uint16_t*)pxh, MTOK, DIN, 128, MTOK * 128);
    conv_pad_h<<<(HH * 128 + 255) / 256, 256>>>(enc_w, (uint16_t*)pwe, HH, DIN, 128, HH * 128);
    conv_pad_h<<<(DMID * HH + 255) / 256, 256>>>(dec1_w, (uint16_t*)pw1, DMID, HH, HH, DMID * HH);

    // #4: encoder GEMM -> g_u fp32 (B,H,L)   [ncu capture target]
    gemm_h<false, 2><<<dim3(2, 512), 256, GH_SMEM>>>(
        (const uint16_t*)pxh, (const uint16_t*)pwe,
        enc_b, (float*)pu, nullptr, 128, HH, 0);

    // #5, #6
    precompute_kernel<<<HH, 64>>>(log_dt, log_A_real, A_imag, B_re, B_im, C_re, C_im);
    conv_pad_h<<<(128 * DMID + 255) / 256, 256>>>(dec2_w, (uint16_t*)pw2, DOUTP, DMID, DMID, 128 * DMID);

    // #7: fused chunk-states + scan + output stage (bf16 precision path)
    stageAC<<<BB * HH, 256, FU_SMEM>>>(Dskip);

    // #8: layernorm + transpose -> fp16 plane
    layernorm_kernel<<<dim3(LL / 32, BB), 256>>>(ln_g, ln_b);

    // #9, #10: decoder MLP (pure fp16)
    gemm_h<true, 1><<<dim3(4, 512), 256, GH_SMEM>>>(
        (const uint16_t*)ptl, (const uint16_t*)pw1,
        dec1_b, nullptr, (uint16_t*)pz, HH, DMID, DMID);

    gemm_h<false, 0><<<dim3(1, 512), 256, GH_SMEM>>>(
        (const uint16_t*)pz, (const uint16_t*)pw2,
        dec2_b, out, nullptr, DMID, DOUTP, DOUTP);
}

// round 16
// speedup vs baseline: 1.9253x; 1.0377x over previous
#include <cuda_runtime.h>
#include <cuda_bf16.h>
#include <cuda_fp16.h>
#include <math.h>
#include <stdint.h>

#define BB   16
#define HH   256
#define LL   4096
#define DIN  100
#define DMID 512
#define DOUTP 100
#define NST  32
#define CH   64
#define NC   64
#define MTOK (BB * LL)

// ---------------- fp32 intermediates ----------------
__device__ float g_u[BB * HH * LL];       // encoder output, (B,H,L)
__device__ float g_hres[BB * HH * LL];    // post-gelu residual, (B,H,L)
__device__ float g_wS[HH * NST * 2];      // w^64 per (h,n)

// ---------------- fp16 planes (GEMM path) ----------------
__device__ uint16_t g_xH[MTOK * 128];                         // x fp16, padded 100->128
__device__ uint16_t g_wencH[HH * 128];                        // enc_w fp16
__device__ uint16_t g_w1H[DMID * HH];
__device__ uint16_t g_w2H[128 * DMID];                        // dec2_w padded rows
__device__ uint16_t g_tlnH[BB * LL * HH];                     // LN out fp16
__device__ uint16_t g_zH[MTOK * DMID];                        // MLP hidden fp16

// ---------------- fp16 hi/lo split planes (S4 matrices) ----------------
__device__ uint16_t g_VSh[HH * 64 * 64], g_VSl[HH * 64 * 64];     // [h][s][t]
__device__ uint16_t g_CMSh[HH * 64 * 128], g_CMSl[HH * 64 * 128]; // [h][t][k]

__device__ __forceinline__ float gelu_f(float x) {
    return 0.5f * x * (1.0f + erff(x * 0.70710678118654752f));
}
__device__ __forceinline__ void splith(float v, uint16_t& h, uint16_t& l) {
    __half hh = __float2half_rn(v);
    __half ll = __float2half_rn(v - __half2float(hh));
    h = *(uint16_t*)&hh; l = *(uint16_t*)&ll;
}
__device__ __forceinline__ void mma16816h(float* c, const uint32_t* a, uint32_t b0, uint32_t b1) {
    asm volatile(
        "mma.sync.aligned.m16n8k16.row.col.f32.f16.f16.f32 "
        "{%0,%1,%2,%3}, {%4,%5,%6,%7}, {%8,%9}, {%0,%1,%2,%3};"
        : "+f"(c[0]), "+f"(c[1]), "+f"(c[2]), "+f"(c[3])
        : "r"(a[0]), "r"(a[1]), "r"(a[2]), "r"(a[3]), "r"(b0), "r"(b1));
}
__device__ __forceinline__ void ldsm_x4(uint32_t* r, uint32_t addr) {
    asm volatile("ldmatrix.sync.aligned.m8n8.x4.shared.b16 {%0,%1,%2,%3}, [%4];"
        : "=r"(r[0]), "=r"(r[1]), "=r"(r[2]), "=r"(r[3]) : "r"(addr));
}
__device__ __forceinline__ uint32_t smem_u32(const void* p) {
    uint32_t a;
    asm("{ .reg .u64 t; cvta.to.shared.u64 t, %1; cvt.u32.u64 %0, t; }" : "=r"(a) : "l"(p));
    return a;
}
#define CP16(dst, src) asm volatile("cp.async.cg.shared.global [%0], [%1], 16;" :: "r"(dst), "l"(src))
#define CPCOMMIT() asm volatile("cp.async.commit_group;" ::: "memory")
#define CPWAIT1() asm volatile("cp.async.wait_group 1;" ::: "memory")
#define CPWAIT0() asm volatile("cp.async.wait_group 0;" ::: "memory")

// ---------------- fp16 convert/pad kernel ----------------
__global__ void conv_pad_h(const float* __restrict__ src, uint16_t* __restrict__ d,
                           int M, int K, int Kp, int total)
{
    int i = blockIdx.x * 256 + threadIdx.x;
    if (i >= total) return;
    int r = i / Kp, c = i - r * Kp;
    float v = (r < M && c < K) ? src[(long)r * K + c] : 0.0f;
    __half hv = __float2half_rn(v);
    d[i] = *(uint16_t*)&hv;
}

// ============ pure fp16 tensor-core GEMM: C[M,N] = A[M,K]*B[N,K]^T + bias ============
#define SAST 72
#define PLANE_BYTES (128 * SAST * 2)    // 18432
#define HBUF_BYTES (2 * PLANE_BYTES)    // 36864
#define GH_SMEM (2 * HBUF_BYTES)        // 73728

template <bool GELU, int OM>
__global__ void __launch_bounds__(256, 2)
gemm_h(const uint16_t* __restrict__ A, const uint16_t* __restrict__ B,
       const float* __restrict__ bias, float* __restrict__ Cf,
       uint16_t* __restrict__ Co, int K, int Nvalid, int ldc)
{
    extern __shared__ char smem[];
    uint32_t sb = smem_u32(smem);
    int tid = threadIdx.x;
    int warp = tid >> 5, lane = tid & 31;
    int warp_m = warp >> 1, warp_n = warp & 1;
    int g = lane >> 2, tg = lane & 3;
    int m0 = blockIdx.y * 128, n0 = blockIdx.x * 128;

    uint32_t a_row = (uint32_t)(lane & 15) * (SAST * 2) + ((lane & 16) ? 16u : 0u);
    uint32_t b_row = ((uint32_t)(lane & 7) + ((lane & 16) ? 8u : 0u)) * (SAST * 2)
                   + ((lane & 8) ? 16u : 0u);

    auto load_chunk = [&](int buf, int k0) {
        uint32_t base = sb + (uint32_t)buf * HBUF_BYTES;
#pragma unroll
        for (int p = 0; p < 8; p++) {
            int idx = tid + p * 256;
            int pl = idx >> 10;
            int rem = idx & 1023;
            int row = rem >> 3, seg = rem & 7;
            uint32_t doff = (uint32_t)pl * PLANE_BYTES + (uint32_t)(row * SAST + seg * 8) * 2;
            const uint16_t* src = (pl == 0) ? (A + (long)(m0 + row) * K + k0 + seg * 8)
                                            : (B + (long)(n0 + row) * K + k0 + seg * 8);
            CP16(base + doff, src);
        }
    };

    float acc[2][8][4];
#pragma unroll
    for (int mt = 0; mt < 2; mt++)
#pragma unroll
        for (int nt = 0; nt < 8; nt++)
#pragma unroll
            for (int q = 0; q < 4; q++) acc[mt][nt][q] = 0.0f;

    int nch = K >> 6;
    load_chunk(0, 0);
    CPCOMMIT();
    for (int c = 0; c < nch; c++) {
        if (c + 1 < nch) { load_chunk((c + 1) & 1, (c + 1) << 6); CPCOMMIT(); CPWAIT1(); }
        else CPWAIT0();
        __syncthreads();
        uint32_t bufb = sb + (uint32_t)(c & 1) * HBUF_BYTES;
        uint32_t pA = bufb, pB = bufb + PLANE_BYTES;
#pragma unroll
        for (int ks = 0; ks < 4; ks++) {
            uint32_t kboff = (uint32_t)(ks * 16) * 2;
            uint32_t ah[2][4];
#pragma unroll
            for (int mt = 0; mt < 2; mt++) {
                uint32_t ro = (uint32_t)(warp_m * 32 + mt * 16) * (SAST * 2) + a_row + kboff;
                ldsm_x4(ah[mt], pA + ro);
            }
            uint32_t bA[4], bBuf[4];
            uint32_t nbase = (uint32_t)(warp_n * 64) * (SAST * 2) + b_row + kboff;
            ldsm_x4(bA, pB + nbase);
            ldsm_x4(bBuf, pB + nbase + 16 * (SAST * 2));
#pragma unroll
            for (int sub = 0; sub < 2; sub++)
#pragma unroll
                for (int mt = 0; mt < 2; mt++)
                    mma16816h(acc[mt][0 * 2 + sub], ah[mt], bA[sub * 2], bA[sub * 2 + 1]);
            ldsm_x4(bA, pB + nbase + 32 * (SAST * 2));
#pragma unroll
            for (int sub = 0; sub < 2; sub++)
#pragma unroll
                for (int mt = 0; mt < 2; mt++)
                    mma16816h(acc[mt][1 * 2 + sub], ah[mt], bBuf[sub * 2], bBuf[sub * 2 + 1]);
            ldsm_x4(bBuf, pB + nbase + 48 * (SAST * 2));
#pragma unroll
            for (int sub = 0; sub < 2; sub++)
#pragma unroll
                for (int mt = 0; mt < 2; mt++)
                    mma16816h(acc[mt][2 * 2 + sub], ah[mt], bA[sub * 2], bA[sub * 2 + 1]);
#pragma unroll
            for (int sub = 0; sub < 2; sub++)
#pragma unroll
                for (int mt = 0; mt < 2; mt++)
                    mma16816h(acc[mt][3 * 2 + sub], ah[mt], bBuf[sub * 2], bBuf[sub * 2 + 1]);
        }
        __syncthreads();
    }

    // -------- epilogue via smem stage --------
    float* stage = (float*)smem;
    for (int nh = 0; nh < 2; nh++) {
        if (warp_n == nh) {
#pragma unroll
            for (int mt = 0; mt < 2; mt++) {
#pragma unroll
                for (int nt = 0; nt < 8; nt++) {
                    int nl = nt * 8 + tg * 2;
                    int ng = n0 + nh * 64 + nl;
                    int r0 = warp_m * 32 + mt * 16 + g;
                    float b0v = (OM == 0) ? ((ng < Nvalid) ? bias[ng] : 0.0f) : bias[ng];
                    float b1v = (OM == 0) ? ((ng + 1 < Nvalid) ? bias[ng + 1] : 0.0f) : bias[ng + 1];
                    float v0 = acc[mt][nt][0] + b0v;
                    float v1 = acc[mt][nt][1] + b1v;
                    float v2 = acc[mt][nt][2] + b0v;
                    float v3 = acc[mt][nt][3] + b1v;
                    if (GELU) { v0 = gelu_f(v0); v1 = gelu_f(v1); v2 = gelu_f(v2); v3 = gelu_f(v3); }
                    if (OM == 2) {
                        stage[nl * 132 + r0] = v0;
                        stage[(nl + 1) * 132 + r0] = v1;
                        stage[nl * 132 + r0 + 8] = v2;
                        stage[(nl + 1) * 132 + r0 + 8] = v3;
                    } else {
                        stage[r0 * 68 + nl] = v0;
                        stage[r0 * 68 + nl + 1] = v1;
                        stage[(r0 + 8) * 68 + nl] = v2;
                        stage[(r0 + 8) * 68 + nl + 1] = v3;
                    }
                }
            }
        }
        __syncthreads();
        if (OM == 2) {
            int bidx = m0 >> 12;
            int l0 = m0 & 4095;
#pragma unroll
            for (int p = 0; p < 8; p++) {
                int nl = p * 8 + warp;
                int m4 = lane * 4;
                float4 v = *(float4*)&stage[nl * 132 + m4];
                int ng = n0 + nh * 64 + nl;
                long base = ((long)((bidx << 8) + ng)) * 4096 + l0 + m4;
                *(float4*)&Cf[base] = v;
            }
        } else if (OM == 1) {
#pragma unroll
            for (int p = 0; p < 8; p++) {
                int idx = tid + p * 256;
                int r = idx >> 4;
                int c4 = (idx & 15) * 4;
                int n = n0 + nh * 64 + c4;
                float4 v = *(float4*)&stage[r * 68 + c4];
                long base = (long)(m0 + r) * ldc + n;
                __half z0 = __float2half_rn(v.x), z1 = __float2half_rn(v.y);
                __half z2 = __float2half_rn(v.z), z3 = __float2half_rn(v.w);
                uint64_t pk = (uint64_t)*(uint16_t*)&z0 | ((uint64_t)*(uint16_t*)&z1 << 16)
                            | ((uint64_t)*(uint16_t*)&z2 << 32) | ((uint64_t)*(uint16_t*)&z3 << 48);
                *(uint64_t*)&Co[base] = pk;
            }
        } else {
#pragma unroll
            for (int p = 0; p < 8; p++) {
                int idx = tid + p * 256;
                int r = idx >> 4;
                int c4 = (idx & 15) * 4;
                int n = n0 + nh * 64 + c4;
                if (n < Nvalid) {
                    float4 v = *(float4*)&stage[r * 68 + c4];
                    *(float4*)&Cf[(long)(m0 + r) * ldc + n] = v;
                }
            }
        }
        __syncthreads();
    }
}

// ---------------- precompute per-head matrices (fp16 hi/lo output) ----------------
__global__ void precompute_kernel(const float* __restrict__ log_dt,
                                  const float* __restrict__ log_A_real,
                                  const float* __restrict__ A_imag,
                                  const float* __restrict__ B_re,
                                  const float* __restrict__ B_im,
                                  const float* __restrict__ C_re,
                                  const float* __restrict__ C_im)
{
    int h = blockIdx.x;
    int t = threadIdx.x;   // 0..63
    __shared__ float s_dtr[NST], s_dti[NST], s_c2r[NST], s_c2i[NST];
    __shared__ float s_k[CH];

    float dt = expf(log_dt[h]);
    if (t < NST) {
        int n = t;
        float Ar = -expf(log_A_real[h * NST + n]);
        float Ai = A_imag[h * NST + n];
        float dtr = dt * Ar, dti = dt * Ai;
        float er = expf(dtr);
        float Er = er * cosf(dti) - 1.0f;
        float Ei = er * sinf(dti);
        float br = B_re[h * NST + n], bi = B_im[h * NST + n];
        float cr = C_re[h * NST + n], ci = C_im[h * NST + n];
        float BCr = br * cr - bi * ci;
        float BCi = br * ci + bi * cr;
        float numr = BCr * Er - BCi * Ei;
        float numi = BCr * Ei + BCi * Er;
        float den = Ar * Ar + Ai * Ai;
        float cpr = (numr * Ar + numi * Ai) / den;
        float cpi = (numi * Ar - numr * Ai) / den;
        s_c2r[n] = 2.0f * cpr;
        s_c2i[n] = 2.0f * cpi;
        s_dtr[n] = dtr;
        s_dti[n] = dti;
        float e64 = expf(64.0f * dtr);
        g_wS[(h * NST + n) * 2 + 0] = e64 * cosf(64.0f * dti);
        g_wS[(h * NST + n) * 2 + 1] = e64 * sinf(64.0f * dti);
    }
    __syncthreads();

    float kt = 0.0f;
    for (int n = 0; n < NST; n++) {
        float dtr = s_dtr[n], dti = s_dti[n];
        float c2r = s_c2r[n], c2i = s_c2i[n];
        float p = (float)(63 - t);
        float ep = expf(p * dtr);
        float vr = ep * cosf(p * dti), vi = ep * sinf(p * dti);
        uint16_t hh, ll;
        splith(vr, hh, ll);
        g_VSh[h * 4096 + (2 * n) * 64 + t] = hh; g_VSl[h * 4096 + (2 * n) * 64 + t] = ll;
        splith(vi, hh, ll);
        g_VSh[h * 4096 + (2 * n + 1) * 64 + t] = hh; g_VSl[h * 4096 + (2 * n + 1) * 64 + t] = ll;
        float pt = (float)t;
        float et = expf(pt * dtr);
        float wr = et * cosf(pt * dti), wi = et * sinf(pt * dti);
        kt += c2r * wr - c2i * wi;
        float p1 = (float)(t + 1);
        float e1 = expf(p1 * dtr);
        float w1r = e1 * cosf(p1 * dti), w1i = e1 * sinf(p1 * dti);
        float gr = c2r * w1r - c2i * w1i;
        float gi = -(c2r * w1i + c2i * w1r);
        splith(gr, hh, ll);
        g_CMSh[h * 8192 + t * 128 + 64 + 2 * n] = hh; g_CMSl[h * 8192 + t * 128 + 64 + 2 * n] = ll;
        splith(gi, hh, ll);
        g_CMSh[h * 8192 + t * 128 + 64 + 2 * n + 1] = hh; g_CMSl[h * 8192 + t * 128 + 64 + 2 * n + 1] = ll;
    }
    s_k[t] = kt;
    __syncthreads();
    for (int j = 0; j < CH; j++) {
        float val = (j <= t) ? s_k[t - j] : 0.0f;
        uint16_t hh, ll; splith(val, hh, ll);
        g_CMSh[h * 8192 + t * 128 + j] = hh;
        g_CMSl[h * 8192 + t * 128 + j] = ll;
    }
}

// ================= fused stageA + scan + stageC (fp16 2-term) =================
// smem layout (bytes):
#define FU_U  0                  // u fp16 single plane, 64x72 (9216)
#define FU_W  9216               // V hi/lo (phase1) or CM hi/lo (phase3)
#define FU_VH FU_W
#define FU_VL (FU_W + 9216)
#define FU_CH FU_W
#define FU_CL (FU_W + 17408)
#define FU_E  44032              // fp32 E, stride 66 (16896)
#define FU_P  60928              // P fp16 single plane, 64x72 (9216); temps overlap
#define FU_SMEM 70144

__global__ void __launch_bounds__(256, 2) stageAC(const float* __restrict__ Dskip)
{
    extern __shared__ char sm[];
    uint16_t* sU  = (uint16_t*)(sm + FU_U);
    uint16_t* sVh = (uint16_t*)(sm + FU_VH);
    uint16_t* sVl = (uint16_t*)(sm + FU_VL);
    uint16_t* sCh = (uint16_t*)(sm + FU_CH);
    uint16_t* sCl = (uint16_t*)(sm + FU_CL);
    float*    sE  = (float*)(sm + FU_E);
    uint16_t* sP  = (uint16_t*)(sm + FU_P);
    float*    sTf   = (float*)(sm + FU_P);          // 2048 B temp
    float*    sPref = (float*)(sm + FU_P + 2048);   // 2048 B temp

    uint32_t pU = smem_u32(sU);
    uint32_t pVh = smem_u32(sVh), pVl = smem_u32(sVl);
    uint32_t pCh = smem_u32(sCh), pCl = smem_u32(sCl);
    uint32_t pP = smem_u32(sP);

    int bh = blockIdx.x, h = bh & (HH - 1);
    int tid = threadIdx.x, warp = tid >> 5, lane = tid & 31;
    int warp_m = warp >> 1, warp_n = warp & 1;
    int g = lane >> 2, tg = lane & 3;
    const float* up = g_u + (long)bh * LL;

    uint32_t a_row72 = (uint32_t)(lane & 15) * 144 + ((lane & 16) ? 16u : 0u);
    uint32_t b_row72 = ((uint32_t)(lane & 7) + ((lane & 16) ? 8u : 0u)) * 144 + ((lane & 8) ? 16u : 0u);
    uint32_t b_row136 = ((uint32_t)(lane & 7) + ((lane & 16) ? 8u : 0u)) * 272 + ((lane & 8) ? 16u : 0u);

    // ---- load u -> single fp16 plane; load V hi/lo ----
    {
        const uint16_t* vh = g_VSh + h * 4096;
        const uint16_t* vl = g_VSl + h * 4096;
#pragma unroll
        for (int p = 0; p < 4; p++) {
            int i = tid + p * 256;
            int e = i * 4, row = e >> 6, col = e & 63;
            float4 v = *(const float4*)(up + e);
            __half h0 = __float2half_rn(v.x), h1 = __float2half_rn(v.y);
            __half h2 = __float2half_rn(v.z), h3 = __float2half_rn(v.w);
            *(uint2*)&sU[row * 72 + col] = make_uint2(
                (uint32_t)*(uint16_t*)&h0 | ((uint32_t)*(uint16_t*)&h1 << 16),
                (uint32_t)*(uint16_t*)&h2 | ((uint32_t)*(uint16_t*)&h3 << 16));
        }
#pragma unroll
        for (int p = 0; p < 2; p++) {
            int i = tid + p * 256;
            int row = i >> 3, seg = i & 7;
            *(uint4*)&sVh[row * 72 + seg * 8] = *(const uint4*)&vh[row * 64 + seg * 8];
            *(uint4*)&sVl[row * 72 + seg * 8] = *(const uint4*)&vl[row * 64 + seg * 8];
        }
    }
    __syncthreads();

    // ---- phase 1: E = U V^T  (2 MMA terms) ----
    {
        float acc[4][4];
#pragma unroll
        for (int nt = 0; nt < 4; nt++)
#pragma unroll
            for (int q = 0; q < 4; q++) acc[nt][q] = 0.0f;
        int ra = warp_m * 16;
#pragma unroll
        for (int ks = 0; ks < 4; ks++) {
            uint32_t kboff = (uint32_t)(ks * 16) * 2;
            uint32_t ah[4];
            ldsm_x4(ah, pU + (uint32_t)ra * 144 + a_row72 + kboff);
            uint32_t bhp[2][4], blp[2][4];
#pragma unroll
            for (int ntp = 0; ntp < 2; ntp++) {
                uint32_t nb = (uint32_t)(warp_n * 32 + ntp * 16) * 144 + b_row72 + kboff;
                ldsm_x4(bhp[ntp], pVh + nb);
                ldsm_x4(blp[ntp], pVl + nb);
            }
#pragma unroll
            for (int ntp = 0; ntp < 2; ntp++)
#pragma unroll
                for (int sub = 0; sub < 2; sub++)
                    mma16816h(acc[ntp * 2 + sub], ah, bhp[ntp][sub * 2], bhp[ntp][sub * 2 + 1]);
#pragma unroll
            for (int ntp = 0; ntp < 2; ntp++)
#pragma unroll
                for (int sub = 0; sub < 2; sub++)
                    mma16816h(acc[ntp * 2 + sub], ah, blp[ntp][sub * 2], blp[ntp][sub * 2 + 1]);
        }
        int ra2 = warp_m * 16;
#pragma unroll
        for (int nt = 0; nt < 4; nt++) {
            int s = warp_n * 32 + nt * 8 + tg * 2;
            sE[(ra2 + g) * 66 + s] = acc[nt][0];
            sE[(ra2 + g) * 66 + s + 1] = acc[nt][1];
            sE[(ra2 + g + 8) * 66 + s] = acc[nt][2];
            sE[(ra2 + g + 8) * 66 + s + 1] = acc[nt][3];
        }
    }
    __syncthreads();

    // ---- load CM hi/lo (overwrites V region) ----
    {
        const uint16_t* ch = g_CMSh + h * 8192;
        const uint16_t* cl = g_CMSl + h * 8192;
#pragma unroll
        for (int p = 0; p < 4; p++) {
            int i = tid + p * 256;
            int row = i >> 4, seg = i & 15;
            *(uint4*)&sCh[row * 136 + seg * 8] = *(const uint4*)&ch[row * 128 + seg * 8];
            *(uint4*)&sCl[row * 136 + seg * 8] = *(const uint4*)&cl[row * 128 + seg * 8];
        }
    }

    // ---- phase 2: hierarchical scan -> P fp16 plane ----
    int segi = tid >> 5;
    int n = tid & 31;
    float wr = g_wS[(h * NST + n) * 2 + 0];
    float wi = g_wS[(h * NST + n) * 2 + 1];
    {
        float sr = 0.0f, si = 0.0f;
#pragma unroll
        for (int j = 0; j < 8; j++) {
            int c = segi * 8 + j;
            float er = sE[c * 66 + 2 * n], ei = sE[c * 66 + 2 * n + 1];
            float nsr = wr * sr - wi * si + er;
            si = wr * si + wi * sr + ei;
            sr = nsr;
        }
        sTf[segi * 64 + 2 * n] = sr;
        sTf[segi * 64 + 2 * n + 1] = si;
    }
    __syncthreads();
    if (tid < 32) {
        float w2r = wr * wr - wi * wi, w2i = 2.0f * wr * wi;
        float w4r = w2r * w2r - w2i * w2i, w4i = 2.0f * w2r * w2i;
        float w8r = w4r * w4r - w4i * w4i, w8i = 2.0f * w4r * w4i;
        float pr = 0.0f, pi = 0.0f;
#pragma unroll
        for (int s = 0; s < 8; s++) {
            sPref[s * 64 + 2 * n] = pr;
            sPref[s * 64 + 2 * n + 1] = pi;
            float tr = sTf[s * 64 + 2 * n], ti = sTf[s * 64 + 2 * n + 1];
            float npr = w8r * pr - w8i * pi + tr;
            pi = w8r * pi + w8i * pr + ti;
            pr = npr;
        }
    }
    __syncthreads();
    {
        float pr = sPref[segi * 64 + 2 * n];
        float pi = sPref[segi * 64 + 2 * n + 1];
        // keep E values in regs for this seg before sP overwrites temps? sE untouched; only temps overlap sP.
        __syncthreads();   // all prefix reads done before P writes
#pragma unroll
        for (int j = 0; j < 8; j++) {
            int c = segi * 8 + j;
            __half hr = __float2half_rn(pr);
            __half hi = __float2half_rn(pi);
            sP[c * 72 + 2 * n] = *(uint16_t*)&hr;
            sP[c * 72 + 2 * n + 1] = *(uint16_t*)&hi;
            float er = sE[c * 66 + 2 * n], ei = sE[c * 66 + 2 * n + 1];
            float npr = wr * pr - wi * pi + er;
            pi = wr * pi + wi * pr + ei;
            pr = npr;
        }
    }
    __syncthreads();

    // ---- phase 3: Y = [u|P] * CM^T + Dskip*u, gelu, +u  (2 MMA terms) ----
    {
        float acc[4][4];
#pragma unroll
        for (int nt = 0; nt < 4; nt++)
#pragma unroll
            for (int q = 0; q < 4; q++) acc[nt][q] = 0.0f;
        int ra = warp_m * 16;
#pragma unroll
        for (int ks = 0; ks < 8; ks++) {
            uint32_t aBase = (ks < 4) ? pU : pP;
            uint32_t kloc = (uint32_t)((ks & 3) * 16) * 2;
            uint32_t ah[4];
            ldsm_x4(ah, aBase + (uint32_t)ra * 144 + a_row72 + kloc);
            uint32_t kb136 = (uint32_t)(ks * 16) * 2;
            uint32_t bhp[2][4], blp[2][4];
#pragma unroll
            for (int ntp = 0; ntp < 2; ntp++) {
                uint32_t nb = (uint32_t)(warp_n * 32 + ntp * 16) * 272 + b_row136 + kb136;
                ldsm_x4(bhp[ntp], pCh + nb);
                ldsm_x4(blp[ntp], pCl + nb);
            }
#pragma unroll
            for (int ntp = 0; ntp < 2; ntp++)
#pragma unroll
                for (int sub = 0; sub < 2; sub++)
                    mma16816h(acc[ntp * 2 + sub], ah, bhp[ntp][sub * 2], bhp[ntp][sub * 2 + 1]);
#pragma unroll
            for (int ntp = 0; ntp < 2; ntp++)
#pragma unroll
                for (int sub = 0; sub < 2; sub++)
                    mma16816h(acc[ntp * 2 + sub], ah, blp[ntp][sub * 2], blp[ntp][sub * 2 + 1]);
        }

        float dsk = Dskip[h];
        float* hp = g_hres + (long)bh * LL;
        int ra2 = warp_m * 16;
#pragma unroll
        for (int nt = 0; nt < 4; nt++) {
            int t = warp_n * 32 + nt * 8 + tg * 2;
            float u00 = __half2float(*(__half*)&sU[(ra2 + g) * 72 + t]);
            float u01 = __half2float(*(__half*)&sU[(ra2 + g) * 72 + t + 1]);
            float u10 = __half2float(*(__half*)&sU[(ra2 + g + 8) * 72 + t]);
            float u11 = __half2float(*(__half*)&sU[(ra2 + g + 8) * 72 + t + 1]);
            float y0 = gelu_f(acc[nt][0] + dsk * u00) + u00;
            float y1 = gelu_f(acc[nt][1] + dsk * u01) + u01;
            float y2 = gelu_f(acc[nt][2] + dsk * u10) + u10;
            float y3 = gelu_f(acc[nt][3] + dsk * u11) + u11;
            *(float2*)&hp[(ra2 + g) * 64 + t] = make_float2(y0, y1);
            *(float2*)&hp[(ra2 + g + 8) * 64 + t] = make_float2(y2, y3);
        }
    }
}

// ---------------- layernorm + transpose (B,H,L) -> (B,L,H), fp16 output ----------------
__global__ void __launch_bounds__(256, 1) layernorm_kernel(const float* __restrict__ ln_g,
                                                           const float* __restrict__ ln_b)
{
    int b = blockIdx.y;
    int l0 = blockIdx.x * 32;
    __shared__ float tile[256][33];
    int tid = threadIdx.x;
    int w = tid >> 5, lane = tid & 31;
    const float* hp = g_hres + (long)b * HH * LL;
    for (int hh = w; hh < 256; hh += 8) {
        tile[hh][lane] = hp[(long)hh * LL + l0 + lane];
    }
    __syncthreads();
    uint16_t* op = g_tlnH + ((long)b * LL + l0) * HH;
#pragma unroll
    for (int q = 0; q < 4; q++) {
        int tok = w * 4 + q;
        float s = 0.0f, sq = 0.0f;
#pragma unroll
        for (int j = 0; j < 8; j++) {
            float v = tile[lane + 32 * j][tok];
            s += v;
            sq += v * v;
        }
#pragma unroll
        for (int o = 16; o > 0; o >>= 1) {
            s += __shfl_xor_sync(0xffffffffu, s, o);
            sq += __shfl_xor_sync(0xffffffffu, sq, o);
        }
        float mean = s * (1.0f / 256.0f);
        float var = sq * (1.0f / 256.0f) - mean * mean;
        float rstd = rsqrtf(var + 1e-5f);
#pragma unroll
        for (int j = 0; j < 8; j++) {
            int hh = lane + 32 * j;
            float v = (tile[hh][tok] - mean) * rstd * ln_g[hh] + ln_b[hh];
            __half hv = __float2half_rn(v);
            op[(long)tok * HH + hh] = *(uint16_t*)&hv;
        }
    }
}

// ---------------- launcher ----------------
extern "C" void kernel_launch(void* const* d_in, const int* in_sizes, int n_in,
                              void* d_out, int out_size)
{
    const float* x          = (const float*)d_in[0];
    const float* enc_w      = (const float*)d_in[1];
    const float* enc_b      = (const float*)d_in[2];
    const float* log_dt     = (const float*)d_in[3];
    const float* log_A_real = (const float*)d_in[4];
    const float* A_imag     = (const float*)d_in[5];
    const float* B_re       = (const float*)d_in[6];
    const float* B_im       = (const float*)d_in[7];
    const float* C_re       = (const float*)d_in[8];
    const float* C_im       = (const float*)d_in[9];
    const float* Dskip      = (const float*)d_in[10];
    const float* ln_g       = (const float*)d_in[11];
    const float* ln_b       = (const float*)d_in[12];
    const float* dec1_w     = (const float*)d_in[13];
    const float* dec1_b     = (const float*)d_in[14];
    const float* dec2_w     = (const float*)d_in[15];
    const float* dec2_b     = (const float*)d_in[16];
    float* out = (float*)d_out;

    void *pu = 0;
    void *pxh = 0, *pwe = 0, *pw1 = 0, *pw2 = 0, *ptl = 0, *pz = 0;
    cudaGetSymbolAddress(&pu, g_u);
    cudaGetSymbolAddress(&pxh, g_xH);
    cudaGetSymbolAddress(&pwe, g_wencH);
    cudaGetSymbolAddress(&pw1, g_w1H);
    cudaGetSymbolAddress(&pw2, g_w2H);
    cudaGetSymbolAddress(&ptl, g_tlnH);
    cudaGetSymbolAddress(&pz, g_zH);

    cudaFuncSetAttribute(gemm_h<false, 2>, cudaFuncAttributeMaxDynamicSharedMemorySize, GH_SMEM);
    cudaFuncSetAttribute(gemm_h<true, 1>,  cudaFuncAttributeMaxDynamicSharedMemorySize, GH_SMEM);
    cudaFuncSetAttribute(gemm_h<false, 0>, cudaFuncAttributeMaxDynamicSharedMemorySize, GH_SMEM);
    cudaFuncSetAttribute(stageAC, cudaFuncAttributeMaxDynamicSharedMemorySize, FU_SMEM);

    // #1..#3 (keeps enc at launch #4 for ncu capture)
    conv_pad_h<<<(MTOK * 128 + 255) / 256, 256>>>(x, (uint16_t*)pxh, MTOK, DIN, 128, MTOK * 128);
    conv_pad_h<<<(HH * 128 + 255) / 256, 256>>>(enc_w, (uint16_t*)pwe, HH, DIN, 128, HH * 128);
    conv_pad_h<<<(DMID * HH + 255) / 256, 256>>>(dec1_w, (uint16_t*)pw1, DMID, HH, HH, DMID * HH);

    // #4: encoder GEMM -> g_u fp32 (B,H,L)   [ncu capture target]
    gemm_h<false, 2><<<dim3(2, 512), 256, GH_SMEM>>>(
        (const uint16_t*)pxh, (const uint16_t*)pwe,
        enc_b, (float*)pu, nullptr, 128, HH, 0);

    // #5, #6
    precompute_kernel<<<HH, 64>>>(log_dt, log_A_real, A_imag, B_re, B_im, C_re, C_im);
    conv_pad_h<<<(128 * DMID + 255) / 256, 256>>>(dec2_w, (uint16_t*)pw2, DOUTP, DMID, DMID, 128 * DMID);

    // #7: fused chunk-states + scan + output stage (fp16 2-term)
    stageAC<<<BB * HH, 256, FU_SMEM>>>(Dskip);

    // #8: layernorm + transpose -> fp16 plane
    layernorm_kernel<<<dim3(LL / 32, BB), 256>>>(ln_g, ln_b);

    // #9, #10: decoder MLP (pure fp16)
    gemm_h<true, 1><<<dim3(4, 512), 256, GH_SMEM>>>(
        (const uint16_t*)ptl, (const uint16_t*)pw1,
        dec1_b, nullptr, (uint16_t*)pz, HH, DMID, DMID);

    gemm_h<false, 0><<<dim3(1, 512), 256, GH_SMEM>>>(
        (const uint16_t*)pz, (const uint16_t*)pw2,
        dec2_b, out, nullptr, DMID, DOUTP, DOUTP);
}